// round 1
// baseline (speedup 1.0000x reference)
#include <cuda_runtime.h>
#include <math.h>

#define BB   8
#define CC   256
#define ICn  128
#define NPIX 4096
#define NPm  1024

typedef unsigned long long u64;

// ---------- packed f32x2 helpers (B200 has 2x fp32 rate via fma.rn.f32x2) ----------
__device__ __forceinline__ u64 pack2(float x, float y) {
    u64 r; asm("mov.b64 %0, {%1,%2};" : "=l"(r) : "f"(x), "f"(y)); return r;
}
__device__ __forceinline__ float2 unpack2(u64 v) {
    float2 r; asm("mov.b64 {%0,%1}, %2;" : "=f"(r.x), "=f"(r.y) : "l"(v)); return r;
}
__device__ __forceinline__ void fma2(u64 &d, u64 a, u64 b) {
    asm("fma.rn.f32x2 %0, %1, %2, %0;" : "+l"(d) : "l"(a), "l"(b));
}
__device__ __forceinline__ void mul2(u64 &d, u64 s) {
    asm("mul.rn.f32x2 %0, %0, %1;" : "+l"(d) : "l"(s));
}
__device__ __forceinline__ float f4get(const float4 &v, int q) {
    return q == 0 ? v.x : q == 1 ? v.y : q == 2 ? v.z : v.w;
}

// ---------- scratch (allocation-free rule: __device__ globals) ----------
__device__ float d_theta[BB * ICn * NPIX];  // [b][ic][n]
__device__ float d_phi  [BB * ICn * NPm];   // [b][ic][m]
__device__ float d_g    [BB * NPm * ICn];   // [b][m][ic]
__device__ float d_yT   [BB * ICn * NPIX];  // [b][ic][n]

// =====================================================================
// Kernel 1: joint projection GEMM (384 out channels) + fused 2x2 maxpool
// grid (32 pixel-tiles of 128 = 2 image rows, 6 j-tiles of 64, B)
// =====================================================================
__global__ __launch_bounds__(256) void proj_kernel(
    const float* __restrict__ x,
    const float* __restrict__ g_w,  const float* __restrict__ g_b,
    const float* __restrict__ th_w, const float* __restrict__ th_b,
    const float* __restrict__ ph_w, const float* __restrict__ ph_b)
{
    __shared__ union SU {
        struct { float As[16][128]; float Bs[16][64]; } mm;
        float tile[64][129];
    } sm;

    int pt = blockIdx.x, jt = blockIdx.y, b = blockIdx.z;
    const float *wsel, *bsel; int j0;
    if (jt < 2)      { wsel = th_w; bsel = th_b; j0 = jt * 64; }
    else if (jt < 4) { wsel = g_w;  bsel = g_b;  j0 = (jt - 2) * 64; }
    else             { wsel = ph_w; bsel = ph_b; j0 = (jt - 4) * 64; }

    int t = threadIdx.x;
    int a = t >> 4, bx = t & 15;

    u64 acc[4][4];
#pragma unroll
    for (int i = 0; i < 4; i++)
#pragma unroll
        for (int q = 0; q < 4; q++) acc[i][q] = 0ull;

    const float* xb = x + (size_t)b * CC * NPIX + pt * 128;

    for (int c0 = 0; c0 < CC; c0 += 16) {
#pragma unroll
        for (int k = 0; k < 2; k++) {
            int e = t + k * 256;
            int kc = e >> 5, po = (e & 31) * 4;
            *(float4*)&sm.mm.As[kc][po] =
                *(const float4*)&xb[(size_t)(c0 + kc) * NPIX + po];
        }
        {
            int j = t >> 2, cq = (t & 3) * 4;
            float4 wv = *(const float4*)&wsel[(j0 + j) * CC + c0 + cq];
            sm.mm.Bs[cq + 0][j] = wv.x; sm.mm.Bs[cq + 1][j] = wv.y;
            sm.mm.Bs[cq + 2][j] = wv.z; sm.mm.Bs[cq + 3][j] = wv.w;
        }
        __syncthreads();
#pragma unroll
        for (int kc = 0; kc < 16; kc++) {
            float4 wv = *(const float4*)&sm.mm.Bs[kc][a * 4];
            ulonglong2 p0 = *(const ulonglong2*)&sm.mm.As[kc][bx * 4];
            ulonglong2 p1 = *(const ulonglong2*)&sm.mm.As[kc][64 + bx * 4];
            u64 a0 = pack2(wv.x, wv.x), a1 = pack2(wv.y, wv.y);
            u64 a2 = pack2(wv.z, wv.z), a3 = pack2(wv.w, wv.w);
            fma2(acc[0][0], a0, p0.x); fma2(acc[0][1], a0, p0.y);
            fma2(acc[0][2], a0, p1.x); fma2(acc[0][3], a0, p1.y);
            fma2(acc[1][0], a1, p0.x); fma2(acc[1][1], a1, p0.y);
            fma2(acc[1][2], a1, p1.x); fma2(acc[1][3], a1, p1.y);
            fma2(acc[2][0], a2, p0.x); fma2(acc[2][1], a2, p0.y);
            fma2(acc[2][2], a2, p1.x); fma2(acc[2][3], a2, p1.y);
            fma2(acc[3][0], a3, p0.x); fma2(acc[3][1], a3, p0.y);
            fma2(acc[3][2], a3, p1.x); fma2(acc[3][3], a3, p1.y);
        }
        __syncthreads();
    }

    // unpack (+bias)
    float f[4][8];
#pragma unroll
    for (int i = 0; i < 4; i++) {
        float bias = bsel[j0 + a * 4 + i];
#pragma unroll
        for (int q = 0; q < 4; q++) {
            float2 v = unpack2(acc[i][q]);
            f[i][2 * q]     = v.x + bias;
            f[i][2 * q + 1] = v.y + bias;
        }
    }

    if (jt < 2) {
        // theta: direct store, layout [b][ic][n]
        float* out = d_theta + (size_t)b * ICn * NPIX;
#pragma unroll
        for (int i = 0; i < 4; i++) {
            int ic = j0 + a * 4 + i;
            float4 v0 = make_float4(f[i][0], f[i][1], f[i][2], f[i][3]);
            float4 v1 = make_float4(f[i][4], f[i][5], f[i][6], f[i][7]);
            *(float4*)&out[(size_t)ic * NPIX + pt * 128 + bx * 4]      = v0;
            *(float4*)&out[(size_t)ic * NPIX + pt * 128 + 64 + bx * 4] = v1;
        }
    } else {
        // stage tile, then fused 2x2 maxpool (tile = 2 image rows)
#pragma unroll
        for (int i = 0; i < 4; i++) {
            int jr = a * 4 + i;
#pragma unroll
            for (int q = 0; q < 4; q++) {
                sm.tile[jr][bx * 4 + q]      = f[i][q];
                sm.tile[jr][64 + bx * 4 + q] = f[i][4 + q];
            }
        }
        __syncthreads();
        if (jt < 4) {
            // g pooled: layout [b][m][ic]
            float* out = d_g + (size_t)b * NPm * ICn;
#pragma unroll
            for (int k = 0; k < 8; k++) {
                int e = t + k * 256;
                int m = e >> 6, j = e & 63;
                float v = fmaxf(fmaxf(sm.tile[j][2 * m],      sm.tile[j][2 * m + 1]),
                                fmaxf(sm.tile[j][64 + 2 * m], sm.tile[j][64 + 2 * m + 1]));
                out[(size_t)(pt * 32 + m) * ICn + j0 + j] = v;
            }
        } else {
            // phi pooled: layout [b][ic][m]
            float* out = d_phi + (size_t)b * ICn * NPm;
#pragma unroll
            for (int k = 0; k < 8; k++) {
                int e = t + k * 256;
                int j = e >> 5, m = e & 31;
                float v = fmaxf(fmaxf(sm.tile[j][2 * m],      sm.tile[j][2 * m + 1]),
                                fmaxf(sm.tile[j][64 + 2 * m], sm.tile[j][64 + 2 * m + 1]));
                out[(size_t)(j0 + j) * NPm + pt * 32 + m] = v;
            }
        }
    }
}

// =====================================================================
// Kernel 2: flash attention, 64 query rows per block, 64-key chunks
// grid (64 row-tiles, B), 256 threads (ty = t>>4 rows, tx = t&15 cols)
// =====================================================================
__global__ __launch_bounds__(256) void attn_kernel()
{
    extern __shared__ float smem[];
    float* s_th = smem;          // [128 ic][64 r]
    float* s_ph = smem + 8192;   // [128 ic][64 m]
    float* s_g  = smem + 16384;  // [64 m][128 ic]
    float* s_P  = smem + 24576;  // [64 r][64 m]

    int rt = blockIdx.x, b = blockIdx.y;
    int r0 = rt * 64;
    int t = threadIdx.x;
    int tx = t & 15, ty = t >> 4;

    const float* thb = d_theta + (size_t)b * ICn * NPIX + r0;
    const float* phb = d_phi   + (size_t)b * ICn * NPm;
    const float* gbp = d_g     + (size_t)b * NPm * ICn;

#pragma unroll
    for (int k = 0; k < 8; k++) {
        int e = t + k * 256;
        int ic = e >> 4, r4 = (e & 15) * 4;
        *(float4*)&s_th[ic * 64 + r4] = *(const float4*)&thb[(size_t)ic * NPIX + r4];
    }

    u64 accO[4][4];
#pragma unroll
    for (int i = 0; i < 4; i++)
#pragma unroll
        for (int q = 0; q < 4; q++) accO[i][q] = 0ull;
    float mrun[4], lrun[4];
#pragma unroll
    for (int i = 0; i < 4; i++) { mrun[i] = -1e30f; lrun[i] = 0.f; }

    __syncthreads();

    for (int m0 = 0; m0 < NPm; m0 += 64) {
#pragma unroll
        for (int k = 0; k < 8; k++) {
            int e = t + k * 256;
            int ic = e >> 4, m4 = (e & 15) * 4;
            *(float4*)&s_ph[ic * 64 + m4] = *(const float4*)&phb[(size_t)ic * NPm + m0 + m4];
        }
#pragma unroll
        for (int k = 0; k < 8; k++) {
            int e = t + k * 256;
            int m = e >> 5, ic4 = (e & 31) * 4;
            *(float4*)&s_g[m * 128 + ic4] = *(const float4*)&gbp[(size_t)(m0 + m) * ICn + ic4];
        }
        __syncthreads();

        // ---- S = theta^T chunk GEMM (64x64, K=128) ----
        u64 sa[4][2];
#pragma unroll
        for (int i = 0; i < 4; i++) { sa[i][0] = 0ull; sa[i][1] = 0ull; }
#pragma unroll 8
        for (int kc = 0; kc < 128; kc++) {
            float4 av = *(const float4*)&s_th[kc * 64 + ty * 4];
            ulonglong2 bv = *(const ulonglong2*)&s_ph[kc * 64 + tx * 4];
            u64 a0 = pack2(av.x, av.x), a1 = pack2(av.y, av.y);
            u64 a2 = pack2(av.z, av.z), a3 = pack2(av.w, av.w);
            fma2(sa[0][0], a0, bv.x); fma2(sa[0][1], a0, bv.y);
            fma2(sa[1][0], a1, bv.x); fma2(sa[1][1], a1, bv.y);
            fma2(sa[2][0], a2, bv.x); fma2(sa[2][1], a2, bv.y);
            fma2(sa[3][0], a3, bv.x); fma2(sa[3][1], a3, bv.y);
        }

        // ---- online softmax (rows split across 16 tx lanes) ----
        float sf[4][4];
#pragma unroll
        for (int i = 0; i < 4; i++) {
            float2 v0 = unpack2(sa[i][0]), v1 = unpack2(sa[i][1]);
            sf[i][0] = v0.x; sf[i][1] = v0.y; sf[i][2] = v1.x; sf[i][3] = v1.y;
        }
#pragma unroll
        for (int i = 0; i < 4; i++) {
            float mx = fmaxf(fmaxf(sf[i][0], sf[i][1]), fmaxf(sf[i][2], sf[i][3]));
#pragma unroll
            for (int off = 8; off > 0; off >>= 1)
                mx = fmaxf(mx, __shfl_xor_sync(0xffffffffu, mx, off, 16));
            float Mn = fmaxf(mrun[i], mx);
            float sc = __expf(mrun[i] - Mn);
            mrun[i] = Mn;
            float rs = 0.f;
#pragma unroll
            for (int j = 0; j < 4; j++) { sf[i][j] = __expf(sf[i][j] - Mn); rs += sf[i][j]; }
#pragma unroll
            for (int off = 8; off > 0; off >>= 1)
                rs += __shfl_xor_sync(0xffffffffu, rs, off, 16);
            lrun[i] = lrun[i] * sc + rs;
            u64 sc2 = pack2(sc, sc);
            mul2(accO[i][0], sc2); mul2(accO[i][1], sc2);
            mul2(accO[i][2], sc2); mul2(accO[i][3], sc2);
            *(float4*)&s_P[(ty * 4 + i) * 64 + tx * 4] =
                make_float4(sf[i][0], sf[i][1], sf[i][2], sf[i][3]);
        }
        __syncthreads();

        // ---- O += P @ g chunk (64x128, K=64) ----
#pragma unroll 4
        for (int mm = 0; mm < 64; mm += 4) {
            float4 pr0 = *(const float4*)&s_P[(ty * 4 + 0) * 64 + mm];
            float4 pr1 = *(const float4*)&s_P[(ty * 4 + 1) * 64 + mm];
            float4 pr2 = *(const float4*)&s_P[(ty * 4 + 2) * 64 + mm];
            float4 pr3 = *(const float4*)&s_P[(ty * 4 + 3) * 64 + mm];
#pragma unroll
            for (int q = 0; q < 4; q++) {
                ulonglong2 g0 = *(const ulonglong2*)&s_g[(mm + q) * 128 + tx * 4];
                ulonglong2 g1 = *(const ulonglong2*)&s_g[(mm + q) * 128 + 64 + tx * 4];
                u64 p0 = pack2(f4get(pr0, q), f4get(pr0, q));
                u64 p1 = pack2(f4get(pr1, q), f4get(pr1, q));
                u64 p2 = pack2(f4get(pr2, q), f4get(pr2, q));
                u64 p3 = pack2(f4get(pr3, q), f4get(pr3, q));
                fma2(accO[0][0], p0, g0.x); fma2(accO[0][1], p0, g0.y);
                fma2(accO[0][2], p0, g1.x); fma2(accO[0][3], p0, g1.y);
                fma2(accO[1][0], p1, g0.x); fma2(accO[1][1], p1, g0.y);
                fma2(accO[1][2], p1, g1.x); fma2(accO[1][3], p1, g1.y);
                fma2(accO[2][0], p2, g0.x); fma2(accO[2][1], p2, g0.y);
                fma2(accO[2][2], p2, g1.x); fma2(accO[2][3], p2, g1.y);
                fma2(accO[3][0], p3, g0.x); fma2(accO[3][1], p3, g0.y);
                fma2(accO[3][2], p3, g1.x); fma2(accO[3][3], p3, g1.y);
            }
        }
        __syncthreads();
    }

    // ---- normalize, stage, write y^T [b][ic][n] ----
    float* s_o = s_ph;  // [64][129] overlay (s_ph+s_g dead)
#pragma unroll
    for (int i = 0; i < 4; i++) {
        float inv = 1.f / lrun[i];
        int r = ty * 4 + i;
        float2 v;
        v = unpack2(accO[i][0]); s_o[r * 129 + tx * 4 + 0] = v.x * inv; s_o[r * 129 + tx * 4 + 1] = v.y * inv;
        v = unpack2(accO[i][1]); s_o[r * 129 + tx * 4 + 2] = v.x * inv; s_o[r * 129 + tx * 4 + 3] = v.y * inv;
        v = unpack2(accO[i][2]); s_o[r * 129 + 64 + tx * 4 + 0] = v.x * inv; s_o[r * 129 + 64 + tx * 4 + 1] = v.y * inv;
        v = unpack2(accO[i][3]); s_o[r * 129 + 64 + tx * 4 + 2] = v.x * inv; s_o[r * 129 + 64 + tx * 4 + 3] = v.y * inv;
    }
    __syncthreads();
    float* yo = d_yT + (size_t)b * ICn * NPIX + r0;
#pragma unroll
    for (int k = 0; k < 8; k++) {
        int e = t + k * 256;
        int ic = e >> 4, r4 = (e & 15) * 4;
        float4 v = make_float4(s_o[(r4 + 0) * 129 + ic], s_o[(r4 + 1) * 129 + ic],
                               s_o[(r4 + 2) * 129 + ic], s_o[(r4 + 3) * 129 + ic]);
        *(float4*)&yo[(size_t)ic * NPIX + r4] = v;
    }
}

// =====================================================================
// Kernel 3: output conv (K=128) + BatchNorm (eval) + residual
// =====================================================================
__global__ __launch_bounds__(256) void out_kernel(
    const float* __restrict__ x,
    const float* __restrict__ Ww,    const float* __restrict__ Wb,
    const float* __restrict__ gamma, const float* __restrict__ beta,
    const float* __restrict__ bmean, const float* __restrict__ bvar,
    float* __restrict__ out)
{
    __shared__ struct { float As[16][128]; float Bs[16][64]; } sm;
    int pt = blockIdx.x, jt = blockIdx.y, b = blockIdx.z;
    int j0 = jt * 64;
    int t = threadIdx.x, a = t >> 4, bx = t & 15;

    u64 acc[4][4];
#pragma unroll
    for (int i = 0; i < 4; i++)
#pragma unroll
        for (int q = 0; q < 4; q++) acc[i][q] = 0ull;

    const float* yb = d_yT + (size_t)b * ICn * NPIX + pt * 128;

    for (int c0 = 0; c0 < ICn; c0 += 16) {
#pragma unroll
        for (int k = 0; k < 2; k++) {
            int e = t + k * 256;
            int kc = e >> 5, po = (e & 31) * 4;
            *(float4*)&sm.As[kc][po] =
                *(const float4*)&yb[(size_t)(c0 + kc) * NPIX + po];
        }
        {
            int j = t >> 2, cq = (t & 3) * 4;
            float4 wv = *(const float4*)&Ww[(j0 + j) * ICn + c0 + cq];
            sm.Bs[cq + 0][j] = wv.x; sm.Bs[cq + 1][j] = wv.y;
            sm.Bs[cq + 2][j] = wv.z; sm.Bs[cq + 3][j] = wv.w;
        }
        __syncthreads();
#pragma unroll
        for (int kc = 0; kc < 16; kc++) {
            float4 wv = *(const float4*)&sm.Bs[kc][a * 4];
            ulonglong2 p0 = *(const ulonglong2*)&sm.As[kc][bx * 4];
            ulonglong2 p1 = *(const ulonglong2*)&sm.As[kc][64 + bx * 4];
            u64 a0 = pack2(wv.x, wv.x), a1 = pack2(wv.y, wv.y);
            u64 a2 = pack2(wv.z, wv.z), a3 = pack2(wv.w, wv.w);
            fma2(acc[0][0], a0, p0.x); fma2(acc[0][1], a0, p0.y);
            fma2(acc[0][2], a0, p1.x); fma2(acc[0][3], a0, p1.y);
            fma2(acc[1][0], a1, p0.x); fma2(acc[1][1], a1, p0.y);
            fma2(acc[1][2], a1, p1.x); fma2(acc[1][3], a1, p1.y);
            fma2(acc[2][0], a2, p0.x); fma2(acc[2][1], a2, p0.y);
            fma2(acc[2][2], a2, p1.x); fma2(acc[2][3], a2, p1.y);
            fma2(acc[3][0], a3, p0.x); fma2(acc[3][1], a3, p0.y);
            fma2(acc[3][2], a3, p1.x); fma2(acc[3][3], a3, p1.y);
        }
        __syncthreads();
    }

#pragma unroll
    for (int i = 0; i < 4; i++) {
        int oc = j0 + a * 4 + i;
        float inv = gamma[oc] * rsqrtf(bvar[oc] + 1e-5f);
        float addc = (Wb[oc] - bmean[oc]) * inv + beta[oc];
        size_t rowo = (size_t)b * CC * NPIX + (size_t)oc * NPIX + pt * 128;
        float f[8];
#pragma unroll
        for (int q = 0; q < 4; q++) {
            float2 v = unpack2(acc[i][q]);
            f[2 * q] = v.x; f[2 * q + 1] = v.y;
        }
        float4 xv0 = *(const float4*)&x[rowo + bx * 4];
        float4 xv1 = *(const float4*)&x[rowo + 64 + bx * 4];
        float4 o0 = make_float4(f[0] * inv + addc + xv0.x, f[1] * inv + addc + xv0.y,
                                f[2] * inv + addc + xv0.z, f[3] * inv + addc + xv0.w);
        float4 o1 = make_float4(f[4] * inv + addc + xv1.x, f[5] * inv + addc + xv1.y,
                                f[6] * inv + addc + xv1.z, f[7] * inv + addc + xv1.w);
        *(float4*)&out[rowo + bx * 4]      = o0;
        *(float4*)&out[rowo + 64 + bx * 4] = o1;
    }
}

// =====================================================================
extern "C" void kernel_launch(void* const* d_in, const int* in_sizes, int n_in,
                              void* d_out, int out_size)
{
    (void)in_sizes; (void)n_in; (void)out_size;
    const float* x    = (const float*)d_in[0];
    const float* g_w  = (const float*)d_in[1];
    const float* g_b  = (const float*)d_in[2];
    const float* th_w = (const float*)d_in[3];
    const float* th_b = (const float*)d_in[4];
    const float* ph_w = (const float*)d_in[5];
    const float* ph_b = (const float*)d_in[6];
    const float* W_w  = (const float*)d_in[7];
    const float* W_b  = (const float*)d_in[8];
    const float* bg   = (const float*)d_in[9];
    const float* bbta = (const float*)d_in[10];
    const float* bm   = (const float*)d_in[11];
    const float* bv   = (const float*)d_in[12];
    float* out = (float*)d_out;

    proj_kernel<<<dim3(32, 6, 8), 256>>>(x, g_w, g_b, th_w, th_b, ph_w, ph_b);

    const int smem2 = (8192 * 3 + 4096) * (int)sizeof(float);  // 114688 B
    cudaFuncSetAttribute(attn_kernel, cudaFuncAttributeMaxDynamicSharedMemorySize, smem2);
    attn_kernel<<<dim3(64, 8), 256, smem2>>>();

    out_kernel<<<dim3(32, 4, 8), 256>>>(x, W_w, W_b, bg, bbta, bm, bv, out);
}

// round 3
// speedup vs baseline: 1.0293x; 1.0293x over previous
#include <cuda_runtime.h>
#include <math.h>
#include <stdint.h>

#define BB   8
#define CC   256
#define ICn  128
#define NPIX 4096
#define NPm  1024

typedef unsigned long long u64;

// ---------- packed f32x2 helpers (scalar kernels) ----------
__device__ __forceinline__ u64 pack2(float x, float y) {
    u64 r; asm("mov.b64 %0, {%1,%2};" : "=l"(r) : "f"(x), "f"(y)); return r;
}
__device__ __forceinline__ float2 unpack2(u64 v) {
    float2 r; asm("mov.b64 {%0,%1}, %2;" : "=f"(r.x), "=f"(r.y) : "l"(v)); return r;
}
__device__ __forceinline__ void fma2(u64 &d, u64 a, u64 b) {
    asm("fma.rn.f32x2 %0, %1, %2, %0;" : "+l"(d) : "l"(a), "l"(b));
}

// ---------- tf32 helpers ----------
__device__ __forceinline__ uint32_t tf32r(float x) {
    uint32_t r; asm("cvt.rna.tf32.f32 %0, %1;" : "=r"(r) : "f"(x)); return r;
}
__device__ __forceinline__ float tf32f(float x) {
    return __uint_as_float(tf32r(x));
}

// mma.sync m16n8k8 tf32: C += A*B (A row-major 16x8, B col-major 8x8)
__device__ __forceinline__ void mma8(float* c, const uint32_t* a, const uint32_t* b) {
    asm volatile("mma.sync.aligned.m16n8k8.row.col.f32.tf32.tf32.f32 "
        "{%0,%1,%2,%3}, {%4,%5,%6,%7}, {%8,%9}, {%0,%1,%2,%3};"
        : "+f"(c[0]), "+f"(c[1]), "+f"(c[2]), "+f"(c[3])
        : "r"(a[0]), "r"(a[1]), "r"(a[2]), "r"(a[3]), "r"(b[0]), "r"(b[1]));
}

// ---------- scratch ----------
__device__ float d_theta[BB * NPIX * ICn];  // [b][n][ic]
__device__ float d_phi  [BB * NPm * ICn];   // [b][m][ic]
__device__ float d_g    [BB * ICn * NPm];   // [b][ic][m]
__device__ float d_y    [BB * ICn * NPIX];  // [b][ic][n]

// =====================================================================
// Kernel 1: joint projection GEMM (384 out channels) + fused 2x2 maxpool
// =====================================================================
__global__ __launch_bounds__(256) void proj_kernel(
    const float* __restrict__ x,
    const float* __restrict__ g_w,  const float* __restrict__ g_b,
    const float* __restrict__ th_w, const float* __restrict__ th_b,
    const float* __restrict__ ph_w, const float* __restrict__ ph_b)
{
    __shared__ union SU {
        struct { float As[16][128]; float Bs[16][64]; } mm;
        float tile[64][129];
    } sm;

    int pt = blockIdx.x, jt = blockIdx.y, b = blockIdx.z;
    const float *wsel, *bsel; int j0;
    if (jt < 2)      { wsel = th_w; bsel = th_b; j0 = jt * 64; }
    else if (jt < 4) { wsel = ph_w; bsel = ph_b; j0 = (jt - 2) * 64; }
    else             { wsel = g_w;  bsel = g_b;  j0 = (jt - 4) * 64; }

    int t = threadIdx.x;
    int a = t >> 4, bx = t & 15;

    u64 acc[4][4];
#pragma unroll
    for (int i = 0; i < 4; i++)
#pragma unroll
        for (int q = 0; q < 4; q++) acc[i][q] = 0ull;

    const float* xb = x + (size_t)b * CC * NPIX + pt * 128;

    for (int c0 = 0; c0 < CC; c0 += 16) {
#pragma unroll
        for (int k = 0; k < 2; k++) {
            int e = t + k * 256;
            int kc = e >> 5, po = (e & 31) * 4;
            *(float4*)&sm.mm.As[kc][po] =
                *(const float4*)&xb[(size_t)(c0 + kc) * NPIX + po];
        }
        {
            int j = t >> 2, cq = (t & 3) * 4;
            float4 wv = *(const float4*)&wsel[(j0 + j) * CC + c0 + cq];
            sm.mm.Bs[cq + 0][j] = wv.x; sm.mm.Bs[cq + 1][j] = wv.y;
            sm.mm.Bs[cq + 2][j] = wv.z; sm.mm.Bs[cq + 3][j] = wv.w;
        }
        __syncthreads();
#pragma unroll
        for (int kc = 0; kc < 16; kc++) {
            float4 wv = *(const float4*)&sm.mm.Bs[kc][a * 4];
            ulonglong2 p0 = *(const ulonglong2*)&sm.mm.As[kc][bx * 4];
            ulonglong2 p1 = *(const ulonglong2*)&sm.mm.As[kc][64 + bx * 4];
            u64 a0 = pack2(wv.x, wv.x), a1 = pack2(wv.y, wv.y);
            u64 a2 = pack2(wv.z, wv.z), a3 = pack2(wv.w, wv.w);
            fma2(acc[0][0], a0, p0.x); fma2(acc[0][1], a0, p0.y);
            fma2(acc[0][2], a0, p1.x); fma2(acc[0][3], a0, p1.y);
            fma2(acc[1][0], a1, p0.x); fma2(acc[1][1], a1, p0.y);
            fma2(acc[1][2], a1, p1.x); fma2(acc[1][3], a1, p1.y);
            fma2(acc[2][0], a2, p0.x); fma2(acc[2][1], a2, p0.y);
            fma2(acc[2][2], a2, p1.x); fma2(acc[2][3], a2, p1.y);
            fma2(acc[3][0], a3, p0.x); fma2(acc[3][1], a3, p0.y);
            fma2(acc[3][2], a3, p1.x); fma2(acc[3][3], a3, p1.y);
        }
        __syncthreads();
    }

    float f[4][8];
#pragma unroll
    for (int i = 0; i < 4; i++) {
        float bias = bsel[j0 + a * 4 + i];
#pragma unroll
        for (int q = 0; q < 4; q++) {
            float2 v = unpack2(acc[i][q]);
            f[i][2 * q]     = v.x + bias;
            f[i][2 * q + 1] = v.y + bias;
        }
    }

    // stage to smem tile [j(64)][n(128)]
#pragma unroll
    for (int i = 0; i < 4; i++) {
        int jr = a * 4 + i;
#pragma unroll
        for (int q = 0; q < 4; q++) {
            sm.tile[jr][bx * 4 + q]      = f[i][q];
            sm.tile[jr][64 + bx * 4 + q] = f[i][4 + q];
        }
    }
    __syncthreads();

    if (jt < 2) {
        // theta -> [b][n][ic]
        float* out = d_theta + ((size_t)b * NPIX + pt * 128) * ICn + j0;
#pragma unroll
        for (int k = 0; k < 8; k++) {
            int e = t + k * 256;
            int n = e >> 4, icq = (e & 15) * 4;
            float4 v = make_float4(sm.tile[icq][n], sm.tile[icq + 1][n],
                                   sm.tile[icq + 2][n], sm.tile[icq + 3][n]);
            *(float4*)&out[(size_t)n * ICn + icq] = v;
        }
    } else if (jt < 4) {
        // phi pooled -> [b][m][ic]
        float* out = d_phi + (size_t)b * NPm * ICn;
#pragma unroll
        for (int k = 0; k < 8; k++) {
            int e = t + k * 256;
            int m = e >> 6, j = e & 63;
            float v = fmaxf(fmaxf(sm.tile[j][2 * m],      sm.tile[j][2 * m + 1]),
                            fmaxf(sm.tile[j][64 + 2 * m], sm.tile[j][64 + 2 * m + 1]));
            out[(size_t)(pt * 32 + m) * ICn + j0 + j] = v;
        }
    } else {
        // g pooled -> [b][ic][m]
        float* out = d_g + (size_t)b * ICn * NPm;
#pragma unroll
        for (int k = 0; k < 8; k++) {
            int e = t + k * 256;
            int j = e >> 5, m = e & 31;
            float v = fmaxf(fmaxf(sm.tile[j][2 * m],      sm.tile[j][2 * m + 1]),
                            fmaxf(sm.tile[j][64 + 2 * m], sm.tile[j][64 + 2 * m + 1]));
            out[(size_t)(j0 + j) * NPm + pt * 32 + m] = v;
        }
    }
}

// =====================================================================
// Kernel 2: mma.sync tf32 attention. 128 query rows per CTA, 8 warps
// (16 rows each), 16 key-chunks of 64. Fragment-major smem layouts.
//   S = Ah*Bh + Al*Bh + Ah*Bl  (fp32-quality logits)
//   P = exp(S - 40)  (no online max; fixed shift)
//   Y += (Ph + Pl) * g_tf32
// smem (floats): TH_LO[0,16384) | PHI_HI/P_HI[16384,24576) |
//                PHI_LO/P_LO[24576,32768) | G[32768,40960)
// =====================================================================
#define O_THLO   0
#define O_PHI_HI 16384
#define O_PHI_LO 24576
#define O_G      32768
#define SMEM_FLOATS 40960

__global__ void __launch_bounds__(256, 1) attn_mma_kernel()
{
    extern __shared__ float sm[];
    int tid = threadIdx.x;
    int w = tid >> 5, lane = tid & 31;
    int g = lane >> 2, t4 = lane & 3;
    int rt = blockIdx.x, b = blockIdx.y;
    int r0 = rt * 128;

    // ---- prologue: stage theta fp32 at O_PHI_HI (128x128) ----
    {
        const float* th = d_theta + ((size_t)b * NPIX + r0) * ICn;
#pragma unroll
        for (int i = 0; i < 16; i++) {
            int e = tid + i * 256;
            int row = e >> 5, icq = (e & 31) * 4;
            *(float4*)&sm[O_PHI_HI + row * 128 + icq] =
                *(const float4*)&th[(size_t)row * ICn + icq];
        }
    }
    __syncthreads();

    // build persistent A_hi fragments + TH_LO fragment buffer
    uint32_t a_hi[16][4];
#pragma unroll
    for (int s = 0; s < 16; s++) {
        float v0 = sm[O_PHI_HI + (w * 16 + g)     * 128 + s * 8 + t4];
        float v1 = sm[O_PHI_HI + (w * 16 + g + 8) * 128 + s * 8 + t4];
        float v2 = sm[O_PHI_HI + (w * 16 + g)     * 128 + s * 8 + t4 + 4];
        float v3 = sm[O_PHI_HI + (w * 16 + g + 8) * 128 + s * 8 + t4 + 4];
        a_hi[s][0] = tf32r(v0); a_hi[s][1] = tf32r(v1);
        a_hi[s][2] = tf32r(v2); a_hi[s][3] = tf32r(v3);
    }
#pragma unroll
    for (int i = 0; i < 64; i++) {
        int e = tid + i * 256;          // 16384 elements
        int r = e >> 7, k = e & 127;
        float v = sm[O_PHI_HI + r * 128 + k];
        float lo = v - tf32f(v);
        int wv = r >> 4, rl = r & 15, s = k >> 3, k8 = k & 7;
        int idx = O_THLO + (wv * 16 + s) * 128
                + ((rl & 7) * 4 + (k8 & 3)) * 4 + (k8 >> 2) * 2 + (rl >> 3);
        sm[idx] = tf32f(lo);
    }

    float yacc[16][4];
#pragma unroll
    for (int nt = 0; nt < 16; nt++)
#pragma unroll
        for (int q = 0; q < 4; q++) yacc[nt][q] = 0.f;
    float ls0 = 0.f, ls1 = 0.f;

    __syncthreads();

    for (int ch = 0; ch < 16; ch++) {
        int m0 = ch * 64;

        // ---- load phi chunk (hi/lo) into B-frag layout ----
        {
            const float* ph = d_phi + ((size_t)b * NPm + m0) * ICn;
#pragma unroll
            for (int i = 0; i < 8; i++) {
                int e = tid + i * 256;            // 2048 float4
                int key = e >> 5, icq = (e & 31) * 4;
                float4 v = *(const float4*)&ph[(size_t)key * ICn + icq];
                int nt = key >> 3, n8 = key & 7;
#pragma unroll
                for (int j = 0; j < 4; j++) {
                    float vv = ((const float*)&v)[j];
                    float hv = tf32f(vv);
                    int k = icq + j, s = k >> 3, k8 = k & 7;
                    int idx = (s * 8 + nt) * 64 + (n8 * 4 + (k8 & 3)) * 2 + (k8 >> 2);
                    sm[O_PHI_HI + idx] = hv;
                    sm[O_PHI_LO + idx] = tf32f(vv - hv);
                }
            }
        }
        // ---- load g chunk into B-frag layout ----
        {
            const float* gp = d_g + (size_t)b * ICn * NPm + m0;
#pragma unroll
            for (int i = 0; i < 8; i++) {
                int e = tid + i * 256;            // 2048 float4
                int ic = e >> 4, mq = (e & 15) * 4;
                float4 v = *(const float4*)&gp[(size_t)ic * NPm + mq];
                int nt = ic >> 3, n8 = ic & 7;
#pragma unroll
                for (int j = 0; j < 4; j++) {
                    int mm = mq + j, kt = mm >> 3, m8 = mm & 7;
                    int idx = (kt * 16 + nt) * 64 + (n8 * 4 + (m8 & 3)) * 2 + (m8 >> 2);
                    sm[O_G + idx] = tf32f(((const float*)&v)[j]);
                }
            }
        }
        __syncthreads();

        // ---- S = theta . phi (3-way split) ----
        float sacc[8][4];
#pragma unroll
        for (int nt = 0; nt < 8; nt++)
#pragma unroll
            for (int q = 0; q < 4; q++) sacc[nt][q] = 0.f;

#pragma unroll
        for (int s = 0; s < 16; s++) {
            float4 alov = *(const float4*)&sm[O_THLO + (w * 16 + s) * 128 + lane * 4];
            const uint32_t* al = (const uint32_t*)&alov;
#pragma unroll
            for (int nt = 0; nt < 8; nt++) {
                float2 bhv = *(const float2*)&sm[O_PHI_HI + (s * 8 + nt) * 64 + lane * 2];
                float2 blv = *(const float2*)&sm[O_PHI_LO + (s * 8 + nt) * 64 + lane * 2];
                const uint32_t* bh = (const uint32_t*)&bhv;
                const uint32_t* bl = (const uint32_t*)&blv;
                mma8(sacc[nt], a_hi[s], bh);
                mma8(sacc[nt], al,      bh);
                mma8(sacc[nt], a_hi[s], bl);
            }
        }
        __syncthreads();   // all warps done reading phi; P may overwrite

        // ---- softmax: P = exp(S - 40); store P hi/lo in A-frag layout ----
#pragma unroll
        for (int nt = 0; nt < 8; nt++) {
            float p0 = __expf(sacc[nt][0] - 40.f);
            float p1 = __expf(sacc[nt][1] - 40.f);
            float p2 = __expf(sacc[nt][2] - 40.f);
            float p3 = __expf(sacc[nt][3] - 40.f);
            ls0 += p0 + p1;
            ls1 += p2 + p3;
            int base = (w * 8 + nt) * 128;
            int k0 = 2 * t4, k1 = 2 * t4 + 1;
            int i0 = base + (g * 4 + (k0 & 3)) * 4 + (k0 >> 2) * 2;  // row g
            int i1 = base + (g * 4 + (k1 & 3)) * 4 + (k1 >> 2) * 2;
            float h0 = tf32f(p0), h1 = tf32f(p1), h2 = tf32f(p2), h3 = tf32f(p3);
            sm[O_PHI_HI + i0]     = h0;
            sm[O_PHI_HI + i1]     = h1;
            sm[O_PHI_HI + i0 + 1] = h2;   // row g+8 -> slot+1
            sm[O_PHI_HI + i1 + 1] = h3;
            sm[O_PHI_LO + i0]     = tf32f(p0 - h0);
            sm[O_PHI_LO + i1]     = tf32f(p1 - h1);
            sm[O_PHI_LO + i0 + 1] = tf32f(p2 - h2);
            sm[O_PHI_LO + i1 + 1] = tf32f(p3 - h3);
        }
        __syncthreads();

        // ---- Y += (P_hi + P_lo) @ g ----
#pragma unroll
        for (int kt = 0; kt < 8; kt++) {
            float4 phv = *(const float4*)&sm[O_PHI_HI + (w * 8 + kt) * 128 + lane * 4];
            float4 plv = *(const float4*)&sm[O_PHI_LO + (w * 8 + kt) * 128 + lane * 4];
            const uint32_t* ah = (const uint32_t*)&phv;
            const uint32_t* alr = (const uint32_t*)&plv;
#pragma unroll
            for (int nt = 0; nt < 16; nt++) {
                float2 bgv = *(const float2*)&sm[O_G + (kt * 16 + nt) * 64 + lane * 2];
                const uint32_t* bg = (const uint32_t*)&bgv;
                mma8(yacc[nt], ah,  bg);
                mma8(yacc[nt], alr, bg);
            }
        }
        __syncthreads();   // free P/G for next chunk's loaders
    }

    // ---- epilogue: normalize, transpose via smem, write y [b][ic][n] ----
    ls0 += __shfl_xor_sync(0xffffffffu, ls0, 1);
    ls0 += __shfl_xor_sync(0xffffffffu, ls0, 2);
    ls1 += __shfl_xor_sync(0xffffffffu, ls1, 1);
    ls1 += __shfl_xor_sync(0xffffffffu, ls1, 2);
    float inv0 = 1.f / ls0, inv1 = 1.f / ls1;

    // stage [row 128][ic 128] pitch 129 at sm[0]
#pragma unroll
    for (int nt = 0; nt < 16; nt++) {
        int col = nt * 8 + 2 * t4;
        int ra = w * 16 + g, rb = ra + 8;
        sm[ra * 129 + col]     = yacc[nt][0] * inv0;
        sm[ra * 129 + col + 1] = yacc[nt][1] * inv0;
        sm[rb * 129 + col]     = yacc[nt][2] * inv1;
        sm[rb * 129 + col + 1] = yacc[nt][3] * inv1;
    }
    __syncthreads();
    {
        float* yo = d_y + (size_t)b * ICn * NPIX + r0;
#pragma unroll
        for (int i = 0; i < 16; i++) {
            int e = tid + i * 256;
            int ic = e >> 5, q = (e & 31) * 4;
            float4 v = make_float4(sm[(q + 0) * 129 + ic], sm[(q + 1) * 129 + ic],
                                   sm[(q + 2) * 129 + ic], sm[(q + 3) * 129 + ic]);
            *(float4*)&yo[(size_t)ic * NPIX + q] = v;
        }
    }
}

// =====================================================================
// Kernel 3: output conv (K=128) + BatchNorm (eval) + residual
// =====================================================================
__global__ __launch_bounds__(256) void out_kernel(
    const float* __restrict__ x,
    const float* __restrict__ Ww,    const float* __restrict__ Wb,
    const float* __restrict__ gamma, const float* __restrict__ beta,
    const float* __restrict__ bmean, const float* __restrict__ bvar,
    float* __restrict__ out)
{
    __shared__ struct { float As[16][128]; float Bs[16][64]; } sm;
    int pt = blockIdx.x, jt = blockIdx.y, b = blockIdx.z;
    int j0 = jt * 64;
    int t = threadIdx.x, a = t >> 4, bx = t & 15;

    u64 acc[4][4];
#pragma unroll
    for (int i = 0; i < 4; i++)
#pragma unroll
        for (int q = 0; q < 4; q++) acc[i][q] = 0ull;

    const float* yb = d_y + (size_t)b * ICn * NPIX + pt * 128;

    for (int c0 = 0; c0 < ICn; c0 += 16) {
#pragma unroll
        for (int k = 0; k < 2; k++) {
            int e = t + k * 256;
            int kc = e >> 5, po = (e & 31) * 4;
            *(float4*)&sm.As[kc][po] =
                *(const float4*)&yb[(size_t)(c0 + kc) * NPIX + po];
        }
        {
            int j = t >> 2, cq = (t & 3) * 4;
            float4 wv = *(const float4*)&Ww[(j0 + j) * ICn + c0 + cq];
            sm.Bs[cq + 0][j] = wv.x; sm.Bs[cq + 1][j] = wv.y;
            sm.Bs[cq + 2][j] = wv.z; sm.Bs[cq + 3][j] = wv.w;
        }
        __syncthreads();
#pragma unroll
        for (int kc = 0; kc < 16; kc++) {
            float4 wv = *(const float4*)&sm.Bs[kc][a * 4];
            ulonglong2 p0 = *(const ulonglong2*)&sm.As[kc][bx * 4];
            ulonglong2 p1 = *(const ulonglong2*)&sm.As[kc][64 + bx * 4];
            u64 a0 = pack2(wv.x, wv.x), a1 = pack2(wv.y, wv.y);
            u64 a2 = pack2(wv.z, wv.z), a3 = pack2(wv.w, wv.w);
            fma2(acc[0][0], a0, p0.x); fma2(acc[0][1], a0, p0.y);
            fma2(acc[0][2], a0, p1.x); fma2(acc[0][3], a0, p1.y);
            fma2(acc[1][0], a1, p0.x); fma2(acc[1][1], a1, p0.y);
            fma2(acc[1][2], a1, p1.x); fma2(acc[1][3], a1, p1.y);
            fma2(acc[2][0], a2, p0.x); fma2(acc[2][1], a2, p0.y);
            fma2(acc[2][2], a2, p1.x); fma2(acc[2][3], a2, p1.y);
            fma2(acc[3][0], a3, p0.x); fma2(acc[3][1], a3, p0.y);
            fma2(acc[3][2], a3, p1.x); fma2(acc[3][3], a3, p1.y);
        }
        __syncthreads();
    }

#pragma unroll
    for (int i = 0; i < 4; i++) {
        int oc = j0 + a * 4 + i;
        float inv = gamma[oc] * rsqrtf(bvar[oc] + 1e-5f);
        float addc = (Wb[oc] - bmean[oc]) * inv + beta[oc];
        size_t rowo = (size_t)b * CC * NPIX + (size_t)oc * NPIX + pt * 128;
        float f[8];
#pragma unroll
        for (int q = 0; q < 4; q++) {
            float2 v = unpack2(acc[i][q]);
            f[2 * q] = v.x; f[2 * q + 1] = v.y;
        }
        float4 xv0 = *(const float4*)&x[rowo + bx * 4];
        float4 xv1 = *(const float4*)&x[rowo + 64 + bx * 4];
        float4 o0 = make_float4(f[0] * inv + addc + xv0.x, f[1] * inv + addc + xv0.y,
                                f[2] * inv + addc + xv0.z, f[3] * inv + addc + xv0.w);
        float4 o1 = make_float4(f[4] * inv + addc + xv1.x, f[5] * inv + addc + xv1.y,
                                f[6] * inv + addc + xv1.z, f[7] * inv + addc + xv1.w);
        *(float4*)&out[rowo + bx * 4]      = o0;
        *(float4*)&out[rowo + 64 + bx * 4] = o1;
    }
}

// =====================================================================
extern "C" void kernel_launch(void* const* d_in, const int* in_sizes, int n_in,
                              void* d_out, int out_size)
{
    (void)in_sizes; (void)n_in; (void)out_size;
    const float* x    = (const float*)d_in[0];
    const float* g_w  = (const float*)d_in[1];
    const float* g_b  = (const float*)d_in[2];
    const float* th_w = (const float*)d_in[3];
    const float* th_b = (const float*)d_in[4];
    const float* ph_w = (const float*)d_in[5];
    const float* ph_b = (const float*)d_in[6];
    const float* W_w  = (const float*)d_in[7];
    const float* W_b  = (const float*)d_in[8];
    const float* bg   = (const float*)d_in[9];
    const float* bbta = (const float*)d_in[10];
    const float* bm   = (const float*)d_in[11];
    const float* bv   = (const float*)d_in[12];
    float* out = (float*)d_out;

    proj_kernel<<<dim3(32, 6, 8), 256>>>(x, g_w, g_b, th_w, th_b, ph_w, ph_b);

    const int smem2 = SMEM_FLOATS * (int)sizeof(float);  // 163840 B
    cudaFuncSetAttribute(attn_mma_kernel,
                         cudaFuncAttributeMaxDynamicSharedMemorySize, smem2);
    attn_mma_kernel<<<dim3(32, 8), 256, smem2>>>();

    out_kernel<<<dim3(32, 4, 8), 256>>>(x, W_w, W_b, bg, bbta, bm, bv, out);
}

// round 4
// speedup vs baseline: 1.5969x; 1.5514x over previous
#include <cuda_runtime.h>
#include <math.h>
#include <stdint.h>

#define BB   8
#define CC   256
#define ICn  128
#define NPIX 4096
#define NPm  1024

typedef unsigned long long u64;

// ---------- packed f32x2 helpers (scalar kernels) ----------
__device__ __forceinline__ u64 pack2(float x, float y) {
    u64 r; asm("mov.b64 %0, {%1,%2};" : "=l"(r) : "f"(x), "f"(y)); return r;
}
__device__ __forceinline__ float2 unpack2(u64 v) {
    float2 r; asm("mov.b64 {%0,%1}, %2;" : "=f"(r.x), "=f"(r.y) : "l"(v)); return r;
}
__device__ __forceinline__ void fma2(u64 &d, u64 a, u64 b) {
    asm("fma.rn.f32x2 %0, %1, %2, %0;" : "+l"(d) : "l"(a), "l"(b));
}

// ---------- bf16 helpers ----------
// pack (e0, e1) -> b32 with e0 in LOW half (element 0)
__device__ __forceinline__ uint32_t packbf(float e0, float e1) {
    uint32_t r; asm("cvt.rn.bf16x2.f32 %0, %1, %2;" : "=r"(r) : "f"(e1), "f"(e0)); return r;
}
// hi/lo split of a float pair into two bf16x2 regs
__device__ __forceinline__ void splitpair(float v0, float v1, uint32_t &hp, uint32_t &lp) {
    hp = packbf(v0, v1);
    float h0 = __uint_as_float(hp << 16);
    float h1 = __uint_as_float(hp & 0xffff0000u);
    lp = packbf(v0 - h0, v1 - h1);
}

// mma.sync m16n8k16 bf16: C += A*B
__device__ __forceinline__ void mma16(float* c, const uint32_t* a, const uint32_t* b) {
    asm volatile("mma.sync.aligned.m16n8k16.row.col.f32.bf16.bf16.f32 "
        "{%0,%1,%2,%3}, {%4,%5,%6,%7}, {%8,%9}, {%0,%1,%2,%3};"
        : "+f"(c[0]), "+f"(c[1]), "+f"(c[2]), "+f"(c[3])
        : "r"(a[0]), "r"(a[1]), "r"(a[2]), "r"(a[3]), "r"(b[0]), "r"(b[1]));
}

// ---------- scratch ----------
__device__ float d_theta[BB * NPIX * ICn];  // [b][n][ic]
__device__ float d_phi  [BB * NPm * ICn];   // [b][m][ic]
__device__ float d_g    [BB * ICn * NPm];   // [b][ic][m]
__device__ float d_y    [BB * ICn * NPIX];  // [b][ic][n]

// =====================================================================
// Kernel 1: joint projection GEMM (384 out channels) + fused 2x2 maxpool
// (unchanged scalar f32x2 version — known correct)
// =====================================================================
__global__ __launch_bounds__(256) void proj_kernel(
    const float* __restrict__ x,
    const float* __restrict__ g_w,  const float* __restrict__ g_b,
    const float* __restrict__ th_w, const float* __restrict__ th_b,
    const float* __restrict__ ph_w, const float* __restrict__ ph_b)
{
    __shared__ union SU {
        struct { float As[16][128]; float Bs[16][64]; } mm;
        float tile[64][129];
    } sm;

    int pt = blockIdx.x, jt = blockIdx.y, b = blockIdx.z;
    const float *wsel, *bsel; int j0;
    if (jt < 2)      { wsel = th_w; bsel = th_b; j0 = jt * 64; }
    else if (jt < 4) { wsel = ph_w; bsel = ph_b; j0 = (jt - 2) * 64; }
    else             { wsel = g_w;  bsel = g_b;  j0 = (jt - 4) * 64; }

    int t = threadIdx.x;
    int a = t >> 4, bx = t & 15;

    u64 acc[4][4];
#pragma unroll
    for (int i = 0; i < 4; i++)
#pragma unroll
        for (int q = 0; q < 4; q++) acc[i][q] = 0ull;

    const float* xb = x + (size_t)b * CC * NPIX + pt * 128;

    for (int c0 = 0; c0 < CC; c0 += 16) {
#pragma unroll
        for (int k = 0; k < 2; k++) {
            int e = t + k * 256;
            int kc = e >> 5, po = (e & 31) * 4;
            *(float4*)&sm.mm.As[kc][po] =
                *(const float4*)&xb[(size_t)(c0 + kc) * NPIX + po];
        }
        {
            int j = t >> 2, cq = (t & 3) * 4;
            float4 wv = *(const float4*)&wsel[(j0 + j) * CC + c0 + cq];
            sm.mm.Bs[cq + 0][j] = wv.x; sm.mm.Bs[cq + 1][j] = wv.y;
            sm.mm.Bs[cq + 2][j] = wv.z; sm.mm.Bs[cq + 3][j] = wv.w;
        }
        __syncthreads();
#pragma unroll
        for (int kc = 0; kc < 16; kc++) {
            float4 wv = *(const float4*)&sm.mm.Bs[kc][a * 4];
            ulonglong2 p0 = *(const ulonglong2*)&sm.mm.As[kc][bx * 4];
            ulonglong2 p1 = *(const ulonglong2*)&sm.mm.As[kc][64 + bx * 4];
            u64 a0 = pack2(wv.x, wv.x), a1 = pack2(wv.y, wv.y);
            u64 a2 = pack2(wv.z, wv.z), a3 = pack2(wv.w, wv.w);
            fma2(acc[0][0], a0, p0.x); fma2(acc[0][1], a0, p0.y);
            fma2(acc[0][2], a0, p1.x); fma2(acc[0][3], a0, p1.y);
            fma2(acc[1][0], a1, p0.x); fma2(acc[1][1], a1, p0.y);
            fma2(acc[1][2], a1, p1.x); fma2(acc[1][3], a1, p1.y);
            fma2(acc[2][0], a2, p0.x); fma2(acc[2][1], a2, p0.y);
            fma2(acc[2][2], a2, p1.x); fma2(acc[2][3], a2, p1.y);
            fma2(acc[3][0], a3, p0.x); fma2(acc[3][1], a3, p0.y);
            fma2(acc[3][2], a3, p1.x); fma2(acc[3][3], a3, p1.y);
        }
        __syncthreads();
    }

    float f[4][8];
#pragma unroll
    for (int i = 0; i < 4; i++) {
        float bias = bsel[j0 + a * 4 + i];
#pragma unroll
        for (int q = 0; q < 4; q++) {
            float2 v = unpack2(acc[i][q]);
            f[i][2 * q]     = v.x + bias;
            f[i][2 * q + 1] = v.y + bias;
        }
    }

    // stage to smem tile [j(64)][n(128)]
#pragma unroll
    for (int i = 0; i < 4; i++) {
        int jr = a * 4 + i;
#pragma unroll
        for (int q = 0; q < 4; q++) {
            sm.tile[jr][bx * 4 + q]      = f[i][q];
            sm.tile[jr][64 + bx * 4 + q] = f[i][4 + q];
        }
    }
    __syncthreads();

    if (jt < 2) {
        // theta -> [b][n][ic]
        float* out = d_theta + ((size_t)b * NPIX + pt * 128) * ICn + j0;
#pragma unroll
        for (int k = 0; k < 8; k++) {
            int e = t + k * 256;
            int n = e >> 4, icq = (e & 15) * 4;
            float4 v = make_float4(sm.tile[icq][n], sm.tile[icq + 1][n],
                                   sm.tile[icq + 2][n], sm.tile[icq + 3][n]);
            *(float4*)&out[(size_t)n * ICn + icq] = v;
        }
    } else if (jt < 4) {
        // phi pooled -> [b][m][ic]
        float* out = d_phi + (size_t)b * NPm * ICn;
#pragma unroll
        for (int k = 0; k < 8; k++) {
            int e = t + k * 256;
            int m = e >> 6, j = e & 63;
            float v = fmaxf(fmaxf(sm.tile[j][2 * m],      sm.tile[j][2 * m + 1]),
                            fmaxf(sm.tile[j][64 + 2 * m], sm.tile[j][64 + 2 * m + 1]));
            out[(size_t)(pt * 32 + m) * ICn + j0 + j] = v;
        }
    } else {
        // g pooled -> [b][ic][m]
        float* out = d_g + (size_t)b * ICn * NPm;
#pragma unroll
        for (int k = 0; k < 8; k++) {
            int e = t + k * 256;
            int j = e >> 5, m = e & 31;
            float v = fmaxf(fmaxf(sm.tile[j][2 * m],      sm.tile[j][2 * m + 1]),
                            fmaxf(sm.tile[j][64 + 2 * m], sm.tile[j][64 + 2 * m + 1]));
            out[(size_t)(j0 + j) * NPm + pt * 32 + m] = v;
        }
    }
}

// =====================================================================
// Kernel 2: bf16 m16n8k16 attention with hi/lo splits.
// 128 q-rows/CTA, 8 warps x 16 rows, 16 key-chunks of 64.
//   S = Ah*Bh + Al*Bh + Ah*Bl ; P = exp(S-40) split hi/lo ;
//   Y += Ph*Gh + Pl*Gh + Ph*Gl
// All operands in fragment-major smem (u32 units):
//   AH[0,8192) AL[8192,16384): theta A-frags, (w*8+s) blocks of 128
//   BH[16384,..) BL: phi B-frags, (s*8+nt) blocks of 66 (padded)
//                  -- reused as PH/PL ((w*4+kt) blocks of 128) for Y
//   GH, GL: g B-frags, (kt*16+nt) blocks of 66
// =====================================================================
#define O_AH 0
#define O_AL 8192
#define O_BH 16384
#define O_BL 20608
#define O_GH 24832
#define O_GL 29056
#define SMEM_U32 33280

__global__ void __launch_bounds__(256, 1) attn_bf16_kernel()
{
    extern __shared__ uint32_t su[];
    int tid = threadIdx.x;
    int w = tid >> 5, lane = tid & 31;
    int g = lane >> 2, t4 = lane & 3;
    int rt = blockIdx.x, b = blockIdx.y;
    int r0 = rt * 128;

    // ---- prologue: theta -> A-frags (hi/lo) ----
    {
        int row = tid >> 1, hf = tid & 1;
        int ww = row >> 4, gg = row & 7, hi8 = (row >> 3) & 1;
        const float* th = d_theta + ((size_t)b * NPIX + r0 + row) * ICn + hf * 64;
#pragma unroll
        for (int i = 0; i < 16; i++) {
            int k0 = hf * 64 + i * 4;
            float4 v = *(const float4*)&th[i * 4];
            uint32_t h0, l0, h1, l1;
            splitpair(v.x, v.y, h0, l0);
            splitpair(v.z, v.w, h1, l1);
            int s = k0 >> 4;
            int ta = (k0 >> 1) & 3, ra = 2 * ((k0 >> 3) & 1) + hi8;
            int tb = ((k0 + 2) >> 1) & 3, rb = 2 * (((k0 + 2) >> 3) & 1) + hi8;
            int blk = (ww * 8 + s) * 128;
            su[O_AH + blk + (gg * 4 + ta) * 4 + ra] = h0;
            su[O_AL + blk + (gg * 4 + ta) * 4 + ra] = l0;
            su[O_AH + blk + (gg * 4 + tb) * 4 + rb] = h1;
            su[O_AL + blk + (gg * 4 + tb) * 4 + rb] = l1;
        }
    }
    __syncthreads();

    float yacc[16][4];
#pragma unroll
    for (int nt = 0; nt < 16; nt++)
#pragma unroll
        for (int q = 0; q < 4; q++) yacc[nt][q] = 0.f;
    float ls0 = 0.f, ls1 = 0.f;

    for (int ch = 0; ch < 16; ch++) {
        int m0 = ch * 64;

        // ---- phi chunk -> B-frags (hi/lo) ----
        {
            const float* ph = d_phi + ((size_t)b * NPm + m0) * ICn;
#pragma unroll
            for (int i = 0; i < 8; i++) {
                int e = tid + i * 256;
                int key = e >> 5, icq = (e & 31) * 4;
                float4 v = *(const float4*)&ph[(size_t)key * ICn + icq];
                uint32_t h0, l0, h1, l1;
                splitpair(v.x, v.y, h0, l0);
                splitpair(v.z, v.w, h1, l1);
                int blk = ((icq >> 4) * 8 + (key >> 3)) * 66;
                int lb = (key & 7) * 4;
                int oa = blk + (lb + ((icq >> 1) & 3)) * 2 + ((icq >> 3) & 1);
                int ob = blk + (lb + (((icq + 2) >> 1) & 3)) * 2 + (((icq + 2) >> 3) & 1);
                su[O_BH + oa] = h0; su[O_BL + oa] = l0;
                su[O_BH + ob] = h1; su[O_BL + ob] = l1;
            }
        }
        // ---- g chunk -> B-frags (hi/lo) ----
        {
            const float* gp = d_g + (size_t)b * ICn * NPm + m0;
#pragma unroll
            for (int i = 0; i < 8; i++) {
                int e = tid + i * 256;
                int ic = e >> 4, mq = (e & 15) * 4;
                float4 v = *(const float4*)&gp[(size_t)ic * NPm + mq];
                uint32_t h0, l0, h1, l1;
                splitpair(v.x, v.y, h0, l0);
                splitpair(v.z, v.w, h1, l1);
                int lb = (ic & 7) * 4, nti = ic >> 3;
                int blkA = ((mq >> 4) * 16 + nti) * 66;
                int oa = blkA + (lb + ((mq >> 1) & 3)) * 2 + ((mq >> 3) & 1);
                int blkB = (((mq + 2) >> 4) * 16 + nti) * 66;
                int ob = blkB + (lb + (((mq + 2) >> 1) & 3)) * 2 + (((mq + 2) >> 3) & 1);
                su[O_GH + oa] = h0; su[O_GL + oa] = l0;
                su[O_GH + ob] = h1; su[O_GL + ob] = l1;
            }
        }
        __syncthreads();

        // ---- S = theta . phi (3-term bf16 split) ----
        float sacc[8][4];
#pragma unroll
        for (int nt = 0; nt < 8; nt++)
#pragma unroll
            for (int q = 0; q < 4; q++) sacc[nt][q] = 0.f;

#pragma unroll
        for (int s = 0; s < 8; s++) {
            uint4 ahv = *(const uint4*)&su[O_AH + (w * 8 + s) * 128 + lane * 4];
            uint4 alv = *(const uint4*)&su[O_AL + (w * 8 + s) * 128 + lane * 4];
            const uint32_t* ah = (const uint32_t*)&ahv;
            const uint32_t* al = (const uint32_t*)&alv;
#pragma unroll
            for (int nt = 0; nt < 8; nt++) {
                uint2 bhv = *(const uint2*)&su[O_BH + (s * 8 + nt) * 66 + lane * 2];
                uint2 blv = *(const uint2*)&su[O_BL + (s * 8 + nt) * 66 + lane * 2];
                mma16(sacc[nt], ah, (const uint32_t*)&bhv);
                mma16(sacc[nt], al, (const uint32_t*)&bhv);
                mma16(sacc[nt], ah, (const uint32_t*)&blv);
            }
        }
        __syncthreads();   // B reads done; P may overwrite

        // ---- P = exp(S - 40), split hi/lo, store as A-frags ----
#pragma unroll
        for (int nt = 0; nt < 8; nt++) {
            float p0 = __expf(sacc[nt][0] - 40.f);
            float p1 = __expf(sacc[nt][1] - 40.f);
            float p2 = __expf(sacc[nt][2] - 40.f);
            float p3 = __expf(sacc[nt][3] - 40.f);
            ls0 += p0 + p1;
            ls1 += p2 + p3;
            uint32_t hA, lA, hB, lB;
            splitpair(p0, p1, hA, lA);   // row g
            splitpair(p2, p3, hB, lB);   // row g+8
            int pidx = (w * 4 + (nt >> 1)) * 128 + lane * 4 + (nt & 1) * 2;
            uint2 hv = make_uint2(hA, hB);
            uint2 lv = make_uint2(lA, lB);
            *(uint2*)&su[O_BH + pidx] = hv;
            *(uint2*)&su[O_BL + pidx] = lv;
        }
        __syncthreads();

        // ---- Y += P @ g (3-term bf16 split) ----
#pragma unroll
        for (int kt = 0; kt < 4; kt++) {
            uint4 phv = *(const uint4*)&su[O_BH + (w * 4 + kt) * 128 + lane * 4];
            uint4 plv = *(const uint4*)&su[O_BL + (w * 4 + kt) * 128 + lane * 4];
            const uint32_t* phr = (const uint32_t*)&phv;
            const uint32_t* plr = (const uint32_t*)&plv;
#pragma unroll
            for (int nt = 0; nt < 16; nt++) {
                uint2 ghv = *(const uint2*)&su[O_GH + (kt * 16 + nt) * 66 + lane * 2];
                uint2 glv = *(const uint2*)&su[O_GL + (kt * 16 + nt) * 66 + lane * 2];
                mma16(yacc[nt], phr, (const uint32_t*)&ghv);
                mma16(yacc[nt], plr, (const uint32_t*)&ghv);
                mma16(yacc[nt], phr, (const uint32_t*)&glv);
            }
        }
        __syncthreads();   // P/G regions free for next chunk
    }

    // ---- epilogue: normalize, stage transpose, write y [b][ic][n] ----
    ls0 += __shfl_xor_sync(0xffffffffu, ls0, 1);
    ls0 += __shfl_xor_sync(0xffffffffu, ls0, 2);
    ls1 += __shfl_xor_sync(0xffffffffu, ls1, 1);
    ls1 += __shfl_xor_sync(0xffffffffu, ls1, 2);
    float inv0 = 1.f / ls0, inv1 = 1.f / ls1;

    float* sf = (float*)su;   // [row 128][ic 128] pitch 132
#pragma unroll
    for (int nt = 0; nt < 16; nt++) {
        int col = nt * 8 + 2 * t4;
        int ra = w * 16 + g, rb = ra + 8;
        sf[ra * 132 + col]     = yacc[nt][0] * inv0;
        sf[ra * 132 + col + 1] = yacc[nt][1] * inv0;
        sf[rb * 132 + col]     = yacc[nt][2] * inv1;
        sf[rb * 132 + col + 1] = yacc[nt][3] * inv1;
    }
    __syncthreads();
    {
        float* yo = d_y + (size_t)b * ICn * NPIX + r0;
#pragma unroll
        for (int i = 0; i < 16; i++) {
            int e = tid + i * 256;
            int ic = e >> 5, q = (e & 31) * 4;
            float4 v = make_float4(sf[(q + 0) * 132 + ic], sf[(q + 1) * 132 + ic],
                                   sf[(q + 2) * 132 + ic], sf[(q + 3) * 132 + ic]);
            *(float4*)&yo[(size_t)ic * NPIX + q] = v;
        }
    }
}

// =====================================================================
// Kernel 3: output conv (K=128) + BatchNorm (eval) + residual
// (unchanged scalar f32x2 version — known correct)
// =====================================================================
__global__ __launch_bounds__(256) void out_kernel(
    const float* __restrict__ x,
    const float* __restrict__ Ww,    const float* __restrict__ Wb,
    const float* __restrict__ gamma, const float* __restrict__ beta,
    const float* __restrict__ bmean, const float* __restrict__ bvar,
    float* __restrict__ out)
{
    __shared__ struct { float As[16][128]; float Bs[16][64]; } sm;
    int pt = blockIdx.x, jt = blockIdx.y, b = blockIdx.z;
    int j0 = jt * 64;
    int t = threadIdx.x, a = t >> 4, bx = t & 15;

    u64 acc[4][4];
#pragma unroll
    for (int i = 0; i < 4; i++)
#pragma unroll
        for (int q = 0; q < 4; q++) acc[i][q] = 0ull;

    const float* yb = d_y + (size_t)b * ICn * NPIX + pt * 128;

    for (int c0 = 0; c0 < ICn; c0 += 16) {
#pragma unroll
        for (int k = 0; k < 2; k++) {
            int e = t + k * 256;
            int kc = e >> 5, po = (e & 31) * 4;
            *(float4*)&sm.As[kc][po] =
                *(const float4*)&yb[(size_t)(c0 + kc) * NPIX + po];
        }
        {
            int j = t >> 2, cq = (t & 3) * 4;
            float4 wv = *(const float4*)&Ww[(j0 + j) * ICn + c0 + cq];
            sm.Bs[cq + 0][j] = wv.x; sm.Bs[cq + 1][j] = wv.y;
            sm.Bs[cq + 2][j] = wv.z; sm.Bs[cq + 3][j] = wv.w;
        }
        __syncthreads();
#pragma unroll
        for (int kc = 0; kc < 16; kc++) {
            float4 wv = *(const float4*)&sm.Bs[kc][a * 4];
            ulonglong2 p0 = *(const ulonglong2*)&sm.As[kc][bx * 4];
            ulonglong2 p1 = *(const ulonglong2*)&sm.As[kc][64 + bx * 4];
            u64 a0 = pack2(wv.x, wv.x), a1 = pack2(wv.y, wv.y);
            u64 a2 = pack2(wv.z, wv.z), a3 = pack2(wv.w, wv.w);
            fma2(acc[0][0], a0, p0.x); fma2(acc[0][1], a0, p0.y);
            fma2(acc[0][2], a0, p1.x); fma2(acc[0][3], a0, p1.y);
            fma2(acc[1][0], a1, p0.x); fma2(acc[1][1], a1, p0.y);
            fma2(acc[1][2], a1, p1.x); fma2(acc[1][3], a1, p1.y);
            fma2(acc[2][0], a2, p0.x); fma2(acc[2][1], a2, p0.y);
            fma2(acc[2][2], a2, p1.x); fma2(acc[2][3], a2, p1.y);
            fma2(acc[3][0], a3, p0.x); fma2(acc[3][1], a3, p0.y);
            fma2(acc[3][2], a3, p1.x); fma2(acc[3][3], a3, p1.y);
        }
        __syncthreads();
    }

#pragma unroll
    for (int i = 0; i < 4; i++) {
        int oc = j0 + a * 4 + i;
        float inv = gamma[oc] * rsqrtf(bvar[oc] + 1e-5f);
        float addc = (Wb[oc] - bmean[oc]) * inv + beta[oc];
        size_t rowo = (size_t)b * CC * NPIX + (size_t)oc * NPIX + pt * 128;
        float f[8];
#pragma unroll
        for (int q = 0; q < 4; q++) {
            float2 v = unpack2(acc[i][q]);
            f[2 * q] = v.x; f[2 * q + 1] = v.y;
        }
        float4 xv0 = *(const float4*)&x[rowo + bx * 4];
        float4 xv1 = *(const float4*)&x[rowo + 64 + bx * 4];
        float4 o0 = make_float4(f[0] * inv + addc + xv0.x, f[1] * inv + addc + xv0.y,
                                f[2] * inv + addc + xv0.z, f[3] * inv + addc + xv0.w);
        float4 o1 = make_float4(f[4] * inv + addc + xv1.x, f[5] * inv + addc + xv1.y,
                                f[6] * inv + addc + xv1.z, f[7] * inv + addc + xv1.w);
        *(float4*)&out[rowo + bx * 4]      = o0;
        *(float4*)&out[rowo + 64 + bx * 4] = o1;
    }
}

// =====================================================================
extern "C" void kernel_launch(void* const* d_in, const int* in_sizes, int n_in,
                              void* d_out, int out_size)
{
    (void)in_sizes; (void)n_in; (void)out_size;
    const float* x    = (const float*)d_in[0];
    const float* g_w  = (const float*)d_in[1];
    const float* g_b  = (const float*)d_in[2];
    const float* th_w = (const float*)d_in[3];
    const float* th_b = (const float*)d_in[4];
    const float* ph_w = (const float*)d_in[5];
    const float* ph_b = (const float*)d_in[6];
    const float* W_w  = (const float*)d_in[7];
    const float* W_b  = (const float*)d_in[8];
    const float* bg   = (const float*)d_in[9];
    const float* bbta = (const float*)d_in[10];
    const float* bm   = (const float*)d_in[11];
    const float* bv   = (const float*)d_in[12];
    float* out = (float*)d_out;

    proj_kernel<<<dim3(32, 6, 8), 256>>>(x, g_w, g_b, th_w, th_b, ph_w, ph_b);

    const int smem2 = SMEM_U32 * (int)sizeof(uint32_t);  // 133120 B
    cudaFuncSetAttribute(attn_bf16_kernel,
                         cudaFuncAttributeMaxDynamicSharedMemorySize, smem2);
    attn_bf16_kernel<<<dim3(32, 8), 256, smem2>>>();

    out_kernel<<<dim3(32, 4, 8), 256>>>(x, W_w, W_b, bg, bbta, bm, bv, out);
}

// round 6
// speedup vs baseline: 1.8700x; 1.1710x over previous
#include <cuda_runtime.h>
#include <math.h>
#include <stdint.h>

#define BB   8
#define CC   256
#define ICn  128
#define NPIX 4096
#define NPm  1024

typedef unsigned long long u64;

// ---------- bf16 helpers ----------
// pack (e0, e1) -> b32 with e0 in LOW half (element 0 = lower k)
__device__ __forceinline__ uint32_t packbf(float e0, float e1) {
    uint32_t r; asm("cvt.rn.bf16x2.f32 %0, %1, %2;" : "=r"(r) : "f"(e1), "f"(e0)); return r;
}
__device__ __forceinline__ void splitpair(float v0, float v1, uint32_t &hp, uint32_t &lp) {
    hp = packbf(v0, v1);
    float h0 = __uint_as_float(hp << 16);
    float h1 = __uint_as_float(hp & 0xffff0000u);
    lp = packbf(v0 - h0, v1 - h1);
}

// mma.sync m16n8k16 bf16: C += A*B
__device__ __forceinline__ void mma16(float* c, const uint32_t* a, const uint32_t* b) {
    asm volatile("mma.sync.aligned.m16n8k16.row.col.f32.bf16.bf16.f32 "
        "{%0,%1,%2,%3}, {%4,%5,%6,%7}, {%8,%9}, {%0,%1,%2,%3};"
        : "+f"(c[0]), "+f"(c[1]), "+f"(c[2]), "+f"(c[3])
        : "r"(a[0]), "r"(a[1]), "r"(a[2]), "r"(a[3]), "r"(b[0]), "r"(b[1]));
}

// ---------- scratch ----------
__device__ float d_theta[BB * NPIX * ICn];            // [b][n][ic]
__device__ float d_phi  [BB * NPm * ICn];             // [b][m][ic]
__device__ float d_g    [BB * ICn * NPm];             // [b][ic][m]
__device__ uint32_t d_yh[BB * 32 * 8 * 8 * 128];      // y bf16-hi A-frags
__device__ uint32_t d_yl[BB * 32 * 8 * 8 * 128];      // y bf16-lo A-frags

// =====================================================================
// Kernel 1: projection via bf16 mma (3-term split) + fused 2x2 maxpool.
// Per CTA: 128 pixels (M) x 128 outs (N), K=256 in 4 chunks of 64.
// grid (32 pixel-tiles, 3 proj-types {theta, phi, g}, B). 256 threads.
// smem u32: XH[0,4096) XL[4096,8192)  A-frags, blocks (w*4+s)*128
//           WH[8192,12416) WL[12416,16640)  B-frags, blocks (s*16+nt)*66
//           BIAS f32 [16896,17024)
// epilogue stage f32 [128][132] overlays [0,16896)
// =====================================================================
#define PJ_XH 0
#define PJ_XL 4096
#define PJ_WH 8192
#define PJ_WL 12416
#define PJ_BIAS 16896
#define PJ_U32 17024

__global__ void __launch_bounds__(256) proj_mma_kernel(
    const float* __restrict__ x,
    const float* __restrict__ g_w,  const float* __restrict__ g_b,
    const float* __restrict__ th_w, const float* __restrict__ th_b,
    const float* __restrict__ ph_w, const float* __restrict__ ph_b)
{
    extern __shared__ uint32_t su[];
    float* sf = (float*)su;

    int pt = blockIdx.x, jt = blockIdx.y, b = blockIdx.z;
    const float *wsel, *bsel;
    if (jt == 0)      { wsel = th_w; bsel = th_b; }
    else if (jt == 1) { wsel = ph_w; bsel = ph_b; }
    else              { wsel = g_w;  bsel = g_b;  }

    int tid = threadIdx.x;
    int w = tid >> 5, lane = tid & 31;
    int gr = lane >> 2, t4 = lane & 3;

    if (tid < 128) sf[PJ_BIAS + tid] = bsel[tid];

    float acc[16][4];
#pragma unroll
    for (int nt = 0; nt < 16; nt++)
#pragma unroll
        for (int q = 0; q < 4; q++) acc[nt][q] = 0.f;

    const float* xb = x + (size_t)b * CC * NPIX + pt * 128;

    for (int c0 = 0; c0 < CC; c0 += 64) {
        // ---- X chunk -> A-frags (hi/lo). Pairs of c rows per thread. ----
#pragma unroll
        for (int i = 0; i < 4; i++) {
            int e = tid + i * 256;
            int cp = e >> 5, pix4 = (e & 31) * 4;
            int c = c0 + 2 * cp;
            float4 v0 = *(const float4*)&xb[(size_t)c * NPIX + pix4];
            float4 v1 = *(const float4*)&xb[(size_t)(c + 1) * NPIX + pix4];
            int s = cp >> 3, t4v = cp & 3, rk = (cp >> 2) & 1;
#pragma unroll
            for (int j = 0; j < 4; j++) {
                float a0 = ((const float*)&v0)[j];
                float a1 = ((const float*)&v1)[j];
                uint32_t h, l;
                splitpair(a0, a1, h, l);
                int p = pix4 + j;
                int ww = p >> 4, gg = p & 7, hi8 = (p >> 3) & 1;
                int idx = (ww * 4 + s) * 128 + (gg * 4 + t4v) * 4 + rk * 2 + hi8;
                su[PJ_XH + idx] = h;
                su[PJ_XL + idx] = l;
            }
        }
        // ---- W chunk -> B-frags (hi/lo) ----
#pragma unroll
        for (int i = 0; i < 8; i++) {
            int e = tid + i * 256;
            int j = e >> 4, cq = (e & 15) * 4;
            float4 v = *(const float4*)&wsel[j * CC + c0 + cq];
            uint32_t h0, l0, h1, l1;
            splitpair(v.x, v.y, h0, l0);
            splitpair(v.z, v.w, h1, l1);
            int s = cq >> 4, t4a = (cq >> 1) & 3, rg = (cq >> 3) & 1;
            int nt = j >> 3, n8 = j & 7;
            int blk = (s * 16 + nt) * 66;
            int oa = blk + (n8 * 4 + t4a) * 2 + rg;
            int ob = blk + (n8 * 4 + t4a + 1) * 2 + rg;
            su[PJ_WH + oa] = h0; su[PJ_WL + oa] = l0;
            su[PJ_WH + ob] = h1; su[PJ_WL + ob] = l1;
        }
        __syncthreads();

        // ---- mma: 3-term split ----
#pragma unroll
        for (int s = 0; s < 4; s++) {
            uint4 ahv = *(const uint4*)&su[PJ_XH + (w * 4 + s) * 128 + lane * 4];
            uint4 alv = *(const uint4*)&su[PJ_XL + (w * 4 + s) * 128 + lane * 4];
            const uint32_t* ah = (const uint32_t*)&ahv;
            const uint32_t* al = (const uint32_t*)&alv;
#pragma unroll
            for (int nt = 0; nt < 16; nt++) {
                uint2 bhv = *(const uint2*)&su[PJ_WH + (s * 16 + nt) * 66 + lane * 2];
                uint2 blv = *(const uint2*)&su[PJ_WL + (s * 16 + nt) * 66 + lane * 2];
                mma16(acc[nt], ah, (const uint32_t*)&bhv);
                mma16(acc[nt], al, (const uint32_t*)&bhv);
                mma16(acc[nt], ah, (const uint32_t*)&blv);
            }
        }
        __syncthreads();
    }

    // ---- +bias, stage [pixel 128][out 128] pitch 132 ----
#pragma unroll
    for (int nt = 0; nt < 16; nt++) {
        int col = nt * 8 + 2 * t4;
        float b0 = sf[PJ_BIAS + col], b1 = sf[PJ_BIAS + col + 1];
        int ra = w * 16 + gr, rb = ra + 8;
        sf[ra * 132 + col]     = acc[nt][0] + b0;
        sf[ra * 132 + col + 1] = acc[nt][1] + b1;
        sf[rb * 132 + col]     = acc[nt][2] + b0;
        sf[rb * 132 + col + 1] = acc[nt][3] + b1;
    }
    __syncthreads();

    if (jt == 0) {
        // theta -> [b][n][ic]
        float* out = d_theta + ((size_t)b * NPIX + pt * 128) * ICn;
#pragma unroll
        for (int i = 0; i < 16; i++) {
            int e = tid + i * 256;
            int p = e >> 5, icq = (e & 31) * 4;
            *(float4*)&out[(size_t)p * ICn + icq] = *(const float4*)&sf[p * 132 + icq];
        }
    } else if (jt == 1) {
        // phi pooled -> [b][m][ic]
        float* out = d_phi + (size_t)b * NPm * ICn;
#pragma unroll
        for (int i = 0; i < 4; i++) {
            int e = tid + i * 256;
            int mc = e >> 5, icq = (e & 31) * 4;
            float4 r0 = *(const float4*)&sf[(2 * mc) * 132 + icq];
            float4 r1 = *(const float4*)&sf[(2 * mc + 1) * 132 + icq];
            float4 r2 = *(const float4*)&sf[(64 + 2 * mc) * 132 + icq];
            float4 r3 = *(const float4*)&sf[(65 + 2 * mc) * 132 + icq];
            float4 o;
            o.x = fmaxf(fmaxf(r0.x, r1.x), fmaxf(r2.x, r3.x));
            o.y = fmaxf(fmaxf(r0.y, r1.y), fmaxf(r2.y, r3.y));
            o.z = fmaxf(fmaxf(r0.z, r1.z), fmaxf(r2.z, r3.z));
            o.w = fmaxf(fmaxf(r0.w, r1.w), fmaxf(r2.w, r3.w));
            *(float4*)&out[(size_t)(pt * 32 + mc) * ICn + icq] = o;
        }
    } else {
        // g pooled -> [b][ic][m]
        float* out = d_g + (size_t)b * ICn * NPm;
#pragma unroll
        for (int i = 0; i < 4; i++) {
            int e = tid + i * 256;
            int ic = e >> 3, mc4 = (e & 7) * 4;
            float4 o;
#pragma unroll
            for (int j = 0; j < 4; j++) {
                int mc = mc4 + j;
                float v = fmaxf(fmaxf(sf[(2 * mc) * 132 + ic], sf[(2 * mc + 1) * 132 + ic]),
                                fmaxf(sf[(64 + 2 * mc) * 132 + ic], sf[(65 + 2 * mc) * 132 + ic]));
                ((float*)&o)[j] = v;
            }
            *(float4*)&out[(size_t)ic * NPm + pt * 32 + mc4] = o;
        }
    }
}

// =====================================================================
// Kernel 2: bf16 m16n8k16 attention (unchanged core). Epilogue stores
// y directly as bf16 hi/lo A-fragments to d_yh/d_yl.
// =====================================================================
#define O_AH 0
#define O_AL 8192
#define O_BH 16384
#define O_BL 20608
#define O_GH 24832
#define O_GL 29056
#define SMEM_U32 33280

__global__ void __launch_bounds__(256, 1) attn_bf16_kernel()
{
    extern __shared__ uint32_t su[];
    int tid = threadIdx.x;
    int w = tid >> 5, lane = tid & 31;
    int g = lane >> 2, t4 = lane & 3;
    int rt = blockIdx.x, b = blockIdx.y;
    int r0 = rt * 128;

    // ---- prologue: theta -> A-frags (hi/lo) ----
    {
        int row = tid >> 1, hf = tid & 1;
        int ww = row >> 4, gg = row & 7, hi8 = (row >> 3) & 1;
        const float* th = d_theta + ((size_t)b * NPIX + r0 + row) * ICn + hf * 64;
#pragma unroll
        for (int i = 0; i < 16; i++) {
            int k0 = hf * 64 + i * 4;
            float4 v = *(const float4*)&th[i * 4];
            uint32_t h0, l0, h1, l1;
            splitpair(v.x, v.y, h0, l0);
            splitpair(v.z, v.w, h1, l1);
            int s = k0 >> 4;
            int ta = (k0 >> 1) & 3, ra = 2 * ((k0 >> 3) & 1) + hi8;
            int tb = ((k0 + 2) >> 1) & 3, rb = 2 * (((k0 + 2) >> 3) & 1) + hi8;
            int blk = (ww * 8 + s) * 128;
            su[O_AH + blk + (gg * 4 + ta) * 4 + ra] = h0;
            su[O_AL + blk + (gg * 4 + ta) * 4 + ra] = l0;
            su[O_AH + blk + (gg * 4 + tb) * 4 + rb] = h1;
            su[O_AL + blk + (gg * 4 + tb) * 4 + rb] = l1;
        }
    }
    __syncthreads();

    float yacc[16][4];
#pragma unroll
    for (int nt = 0; nt < 16; nt++)
#pragma unroll
        for (int q = 0; q < 4; q++) yacc[nt][q] = 0.f;
    float ls0 = 0.f, ls1 = 0.f;

    for (int ch = 0; ch < 16; ch++) {
        int m0 = ch * 64;

        // ---- phi chunk -> B-frags (hi/lo) ----
        {
            const float* ph = d_phi + ((size_t)b * NPm + m0) * ICn;
#pragma unroll
            for (int i = 0; i < 8; i++) {
                int e = tid + i * 256;
                int key = e >> 5, icq = (e & 31) * 4;
                float4 v = *(const float4*)&ph[(size_t)key * ICn + icq];
                uint32_t h0, l0, h1, l1;
                splitpair(v.x, v.y, h0, l0);
                splitpair(v.z, v.w, h1, l1);
                int blk = ((icq >> 4) * 8 + (key >> 3)) * 66;
                int lb = (key & 7) * 4;
                int oa = blk + (lb + ((icq >> 1) & 3)) * 2 + ((icq >> 3) & 1);
                int ob = blk + (lb + (((icq + 2) >> 1) & 3)) * 2 + (((icq + 2) >> 3) & 1);
                su[O_BH + oa] = h0; su[O_BL + oa] = l0;
                su[O_BH + ob] = h1; su[O_BL + ob] = l1;
            }
        }
        // ---- g chunk -> B-frags (hi/lo) ----
        {
            const float* gp = d_g + (size_t)b * ICn * NPm + m0;
#pragma unroll
            for (int i = 0; i < 8; i++) {
                int e = tid + i * 256;
                int ic = e >> 4, mq = (e & 15) * 4;
                float4 v = *(const float4*)&gp[(size_t)ic * NPm + mq];
                uint32_t h0, l0, h1, l1;
                splitpair(v.x, v.y, h0, l0);
                splitpair(v.z, v.w, h1, l1);
                int lb = (ic & 7) * 4, nti = ic >> 3;
                int blkA = ((mq >> 4) * 16 + nti) * 66;
                int oa = blkA + (lb + ((mq >> 1) & 3)) * 2 + ((mq >> 3) & 1);
                int blkB = (((mq + 2) >> 4) * 16 + nti) * 66;
                int ob = blkB + (lb + (((mq + 2) >> 1) & 3)) * 2 + (((mq + 2) >> 3) & 1);
                su[O_GH + oa] = h0; su[O_GL + oa] = l0;
                su[O_GH + ob] = h1; su[O_GL + ob] = l1;
            }
        }
        __syncthreads();

        // ---- S = theta . phi (3-term bf16 split) ----
        float sacc[8][4];
#pragma unroll
        for (int nt = 0; nt < 8; nt++)
#pragma unroll
            for (int q = 0; q < 4; q++) sacc[nt][q] = 0.f;

#pragma unroll
        for (int s = 0; s < 8; s++) {
            uint4 ahv = *(const uint4*)&su[O_AH + (w * 8 + s) * 128 + lane * 4];
            uint4 alv = *(const uint4*)&su[O_AL + (w * 8 + s) * 128 + lane * 4];
            const uint32_t* ah = (const uint32_t*)&ahv;
            const uint32_t* al = (const uint32_t*)&alv;
#pragma unroll
            for (int nt = 0; nt < 8; nt++) {
                uint2 bhv = *(const uint2*)&su[O_BH + (s * 8 + nt) * 66 + lane * 2];
                uint2 blv = *(const uint2*)&su[O_BL + (s * 8 + nt) * 66 + lane * 2];
                mma16(sacc[nt], ah, (const uint32_t*)&bhv);
                mma16(sacc[nt], al, (const uint32_t*)&bhv);
                mma16(sacc[nt], ah, (const uint32_t*)&blv);
            }
        }
        __syncthreads();

        // ---- P = exp(S - 40), split hi/lo, store as A-frags ----
#pragma unroll
        for (int nt = 0; nt < 8; nt++) {
            float p0 = __expf(sacc[nt][0] - 40.f);
            float p1 = __expf(sacc[nt][1] - 40.f);
            float p2 = __expf(sacc[nt][2] - 40.f);
            float p3 = __expf(sacc[nt][3] - 40.f);
            ls0 += p0 + p1;
            ls1 += p2 + p3;
            uint32_t hA, lA, hB, lB;
            splitpair(p0, p1, hA, lA);
            splitpair(p2, p3, hB, lB);
            int pidx = (w * 4 + (nt >> 1)) * 128 + lane * 4 + (nt & 1) * 2;
            *(uint2*)&su[O_BH + pidx] = make_uint2(hA, hB);
            *(uint2*)&su[O_BL + pidx] = make_uint2(lA, lB);
        }
        __syncthreads();

        // ---- Y += P @ g (3-term bf16 split) ----
#pragma unroll
        for (int kt = 0; kt < 4; kt++) {
            uint4 phv = *(const uint4*)&su[O_BH + (w * 4 + kt) * 128 + lane * 4];
            uint4 plv = *(const uint4*)&su[O_BL + (w * 4 + kt) * 128 + lane * 4];
            const uint32_t* phr = (const uint32_t*)&phv;
            const uint32_t* plr = (const uint32_t*)&plv;
#pragma unroll
            for (int nt = 0; nt < 16; nt++) {
                uint2 ghv = *(const uint2*)&su[O_GH + (kt * 16 + nt) * 66 + lane * 2];
                uint2 glv = *(const uint2*)&su[O_GL + (kt * 16 + nt) * 66 + lane * 2];
                mma16(yacc[nt], phr, (const uint32_t*)&ghv);
                mma16(yacc[nt], plr, (const uint32_t*)&ghv);
                mma16(yacc[nt], phr, (const uint32_t*)&glv);
            }
        }
        __syncthreads();
    }

    // ---- epilogue: normalize, split hi/lo, store y as A-frags ----
    ls0 += __shfl_xor_sync(0xffffffffu, ls0, 1);
    ls0 += __shfl_xor_sync(0xffffffffu, ls0, 2);
    ls1 += __shfl_xor_sync(0xffffffffu, ls1, 1);
    ls1 += __shfl_xor_sync(0xffffffffu, ls1, 2);
    float inv0 = 1.f / ls0, inv1 = 1.f / ls1;

    size_t base = ((size_t)(b * 32 + rt) * 8 + w) * 1024;
#pragma unroll
    for (int kt = 0; kt < 8; kt++) {
        uint32_t h0, l0, h1, l1, h2, l2, h3, l3;
        splitpair(yacc[2 * kt][0] * inv0, yacc[2 * kt][1] * inv0, h0, l0);
        splitpair(yacc[2 * kt][2] * inv1, yacc[2 * kt][3] * inv1, h1, l1);
        splitpair(yacc[2 * kt + 1][0] * inv0, yacc[2 * kt + 1][1] * inv0, h2, l2);
        splitpair(yacc[2 * kt + 1][2] * inv1, yacc[2 * kt + 1][3] * inv1, h3, l3);
        *(uint4*)&d_yh[base + kt * 128 + lane * 4] = make_uint4(h0, h1, h2, h3);
        *(uint4*)&d_yl[base + kt * 128 + lane * 4] = make_uint4(l0, l1, l2, l3);
    }
}

// =====================================================================
// Kernel 3: output conv via bf16 mma (3-term) + BN + residual.
// Per CTA: 128 pixels x 128 out-channels, K=128. grid (32, 2, 8).
// A-frags loaded directly from d_yh/d_yl (same tile/warp mapping as attn).
// smem u32: BH[0,8448) BL[8448,16896) B-frags (kt*16+nt)*66
//           BN f32 [16896,17152)  (inv[128], addc[128])
// stage f32 [128][130] (scalar access only) overlays [0,16640)
// =====================================================================
#define OK_BH 0
#define OK_BL 8448
#define OK_BN 16896
#define OK_U32 17152

__global__ void __launch_bounds__(256) out_mma_kernel(
    const float* __restrict__ x,
    const float* __restrict__ Ww,    const float* __restrict__ Wb,
    const float* __restrict__ gamma, const float* __restrict__ beta,
    const float* __restrict__ bmean, const float* __restrict__ bvar,
    float* __restrict__ out)
{
    extern __shared__ uint32_t su[];
    float* sf = (float*)su;

    int pt = blockIdx.x, jt = blockIdx.y, b = blockIdx.z;
    int oc0 = jt * 128;
    int tid = threadIdx.x;
    int w = tid >> 5, lane = tid & 31;
    int gr = lane >> 2, t4 = lane & 3;

    if (tid < 128) {
        int oc = oc0 + tid;
        float inv = gamma[oc] * rsqrtf(bvar[oc] + 1e-5f);
        sf[OK_BN + tid] = inv;
        sf[OK_BN + 128 + tid] = (Wb[oc] - bmean[oc]) * inv + beta[oc];
    }

    // ---- W -> B-frags (hi/lo), K=128 ----
#pragma unroll
    for (int i = 0; i < 16; i++) {
        int e = tid + i * 256;
        int j = e >> 5, cq = (e & 31) * 4;
        float4 v = *(const float4*)&Ww[(oc0 + j) * ICn + cq];
        uint32_t h0, l0, h1, l1;
        splitpair(v.x, v.y, h0, l0);
        splitpair(v.z, v.w, h1, l1);
        int s = cq >> 4, t4a = (cq >> 1) & 3, rg = (cq >> 3) & 1;
        int nt = j >> 3, n8 = j & 7;
        int blk = (s * 16 + nt) * 66;
        int oa = blk + (n8 * 4 + t4a) * 2 + rg;
        int ob = blk + (n8 * 4 + t4a + 1) * 2 + rg;
        su[OK_BH + oa] = h0; su[OK_BL + oa] = l0;
        su[OK_BH + ob] = h1; su[OK_BL + ob] = l1;
    }
    __syncthreads();

    float acc[16][4];
#pragma unroll
    for (int nt = 0; nt < 16; nt++)
#pragma unroll
        for (int q = 0; q < 4; q++) acc[nt][q] = 0.f;

    size_t abase = ((size_t)(b * 32 + pt) * 8 + w) * 1024;
#pragma unroll
    for (int kt = 0; kt < 8; kt++) {
        uint4 ahv = *(const uint4*)&d_yh[abase + kt * 128 + lane * 4];
        uint4 alv = *(const uint4*)&d_yl[abase + kt * 128 + lane * 4];
        const uint32_t* ah = (const uint32_t*)&ahv;
        const uint32_t* al = (const uint32_t*)&alv;
#pragma unroll
        for (int nt = 0; nt < 16; nt++) {
            uint2 bhv = *(const uint2*)&su[OK_BH + (kt * 16 + nt) * 66 + lane * 2];
            uint2 blv = *(const uint2*)&su[OK_BL + (kt * 16 + nt) * 66 + lane * 2];
            mma16(acc[nt], ah, (const uint32_t*)&bhv);
            mma16(acc[nt], al, (const uint32_t*)&bhv);
            mma16(acc[nt], ah, (const uint32_t*)&blv);
        }
    }
    __syncthreads();

    // ---- BN, stage [pixel][oc] pitch 130 (scalar access only) ----
#pragma unroll
    for (int nt = 0; nt < 16; nt++) {
        int col = nt * 8 + 2 * t4;
        float i0 = sf[OK_BN + col],       i1 = sf[OK_BN + col + 1];
        float a0 = sf[OK_BN + 128 + col], a1 = sf[OK_BN + 128 + col + 1];
        int ra = w * 16 + gr, rb = ra + 8;
        sf[ra * 130 + col]     = acc[nt][0] * i0 + a0;
        sf[ra * 130 + col + 1] = acc[nt][1] * i1 + a1;
        sf[rb * 130 + col]     = acc[nt][2] * i0 + a0;
        sf[rb * 130 + col + 1] = acc[nt][3] * i1 + a1;
    }
    __syncthreads();

    // ---- transpose write + residual ----
    const float* xr = x + ((size_t)b * CC + oc0) * NPIX + pt * 128;
    float* outp = out + ((size_t)b * CC + oc0) * NPIX + pt * 128;
#pragma unroll
    for (int i = 0; i < 16; i++) {
        int e = tid + i * 256;
        int oc = e >> 5, pq = (e & 31) * 4;
        float4 xv = *(const float4*)&xr[(size_t)oc * NPIX + pq];
        float4 v = make_float4(sf[(pq + 0) * 130 + oc] + xv.x,
                               sf[(pq + 1) * 130 + oc] + xv.y,
                               sf[(pq + 2) * 130 + oc] + xv.z,
                               sf[(pq + 3) * 130 + oc] + xv.w);
        *(float4*)&outp[(size_t)oc * NPIX + pq] = v;
    }
}

// =====================================================================
extern "C" void kernel_launch(void* const* d_in, const int* in_sizes, int n_in,
                              void* d_out, int out_size)
{
    (void)in_sizes; (void)n_in; (void)out_size;
    const float* x    = (const float*)d_in[0];
    const float* g_w  = (const float*)d_in[1];
    const float* g_b  = (const float*)d_in[2];
    const float* th_w = (const float*)d_in[3];
    const float* th_b = (const float*)d_in[4];
    const float* ph_w = (const float*)d_in[5];
    const float* ph_b = (const float*)d_in[6];
    const float* W_w  = (const float*)d_in[7];
    const float* W_b  = (const float*)d_in[8];
    const float* bg   = (const float*)d_in[9];
    const float* bbta = (const float*)d_in[10];
    const float* bm   = (const float*)d_in[11];
    const float* bv   = (const float*)d_in[12];
    float* out = (float*)d_out;

    static int configured = 0;
    if (!configured) {
        cudaFuncSetAttribute(proj_mma_kernel,
            cudaFuncAttributeMaxDynamicSharedMemorySize, PJ_U32 * 4);
        cudaFuncSetAttribute(attn_bf16_kernel,
            cudaFuncAttributeMaxDynamicSharedMemorySize, SMEM_U32 * 4);
        cudaFuncSetAttribute(out_mma_kernel,
            cudaFuncAttributeMaxDynamicSharedMemorySize, OK_U32 * 4);
        configured = 1;
    }

    proj_mma_kernel<<<dim3(32, 3, 8), 256, PJ_U32 * 4>>>(
        x, g_w, g_b, th_w, th_b, ph_w, ph_b);

    attn_bf16_kernel<<<dim3(32, 8), 256, SMEM_U32 * 4>>>();

    out_mma_kernel<<<dim3(32, 2, 8), 256, OK_U32 * 4>>>(
        x, W_w, W_b, bg, bbta, bm, bv, out);
}

// round 8
// speedup vs baseline: 2.1307x; 1.1394x over previous
#include <cuda_runtime.h>
#include <math.h>
#include <stdint.h>

#define BB   8
#define CC   256
#define ICn  128
#define NPIX 4096
#define NPm  1024

// ---------- bf16 helpers ----------
// pack (e0, e1) -> b32 with e0 in LOW half (element 0 = lower index)
__device__ __forceinline__ uint32_t packbf(float e0, float e1) {
    uint32_t r; asm("cvt.rn.bf16x2.f32 %0, %1, %2;" : "=r"(r) : "f"(e1), "f"(e0)); return r;
}
__device__ __forceinline__ void splitpair(float v0, float v1, uint32_t &hp, uint32_t &lp) {
    hp = packbf(v0, v1);
    float h0 = __uint_as_float(hp << 16);
    float h1 = __uint_as_float(hp & 0xffff0000u);
    lp = packbf(v0 - h0, v1 - h1);
}

// mma.sync m16n8k16 bf16: C += A*B
__device__ __forceinline__ void mma16(float* c, const uint32_t* a, const uint32_t* b) {
    asm volatile("mma.sync.aligned.m16n8k16.row.col.f32.bf16.bf16.f32 "
        "{%0,%1,%2,%3}, {%4,%5,%6,%7}, {%8,%9}, {%0,%1,%2,%3};"
        : "+f"(c[0]), "+f"(c[1]), "+f"(c[2]), "+f"(c[3])
        : "r"(a[0]), "r"(a[1]), "r"(a[2]), "r"(a[3]), "r"(b[0]), "r"(b[1]));
}

// ---------- scratch: everything in frag format (hi/lo bf16x2) ----------
__device__ uint32_t d_thH[BB * 32 * 8192];       // theta A-frags [b][rt][ww][s][128]
__device__ uint32_t d_thL[BB * 32 * 8192];
__device__ uint32_t d_phH[BB * 16 * 4096];       // phi B-frags [b][ch][s 8][nt 8][64]
__device__ uint32_t d_phL[BB * 16 * 4096];
__device__ uint32_t d_gH [BB * 16 * 4096];       // g B-frags [b][ch][kt 4][nt 16][64]
__device__ uint32_t d_gL [BB * 16 * 4096];
__device__ uint32_t d_yh [BB * 32 * 8 * 8 * 128];  // y A-frags (attn -> out)
__device__ uint32_t d_yl [BB * 32 * 8 * 8 * 128];

// =====================================================================
// Kernel 1: projection via bf16 mma (3-term split) + fused 2x2 maxpool.
// Epilogues write frag-format gmem directly.
// grid (32 pixel-tiles, 3 proj-types, B). 256 threads.
// =====================================================================
#define PJ_XH 0
#define PJ_XL 4096
#define PJ_WH 8192
#define PJ_WL 12416
#define PJ_BIAS 16896
#define PJ_U32 17024

__global__ void __launch_bounds__(256) proj_mma_kernel(
    const float* __restrict__ x,
    const float* __restrict__ g_w,  const float* __restrict__ g_b,
    const float* __restrict__ th_w, const float* __restrict__ th_b,
    const float* __restrict__ ph_w, const float* __restrict__ ph_b)
{
    extern __shared__ uint32_t su[];
    float* sf = (float*)su;

    int pt = blockIdx.x, jt = blockIdx.y, b = blockIdx.z;
    const float *wsel, *bsel;
    if (jt == 0)      { wsel = th_w; bsel = th_b; }
    else if (jt == 1) { wsel = ph_w; bsel = ph_b; }
    else              { wsel = g_w;  bsel = g_b;  }

    int tid = threadIdx.x;
    int w = tid >> 5, lane = tid & 31;
    int gr = lane >> 2, t4 = lane & 3;

    if (tid < 128) sf[PJ_BIAS + tid] = bsel[tid];

    float acc[16][4];
#pragma unroll
    for (int nt = 0; nt < 16; nt++)
#pragma unroll
        for (int q = 0; q < 4; q++) acc[nt][q] = 0.f;

    const float* xb = x + (size_t)b * CC * NPIX + pt * 128;

    for (int c0 = 0; c0 < CC; c0 += 64) {
        // ---- X chunk -> A-frags (hi/lo) ----
#pragma unroll
        for (int i = 0; i < 4; i++) {
            int e = tid + i * 256;
            int cp = e >> 5, pix4 = (e & 31) * 4;
            int c = c0 + 2 * cp;
            float4 v0 = *(const float4*)&xb[(size_t)c * NPIX + pix4];
            float4 v1 = *(const float4*)&xb[(size_t)(c + 1) * NPIX + pix4];
            int s = cp >> 3, t4v = cp & 3, rk = (cp >> 2) & 1;
#pragma unroll
            for (int j = 0; j < 4; j++) {
                float a0 = ((const float*)&v0)[j];
                float a1 = ((const float*)&v1)[j];
                uint32_t h, l;
                splitpair(a0, a1, h, l);
                int p = pix4 + j;
                int ww = p >> 4, gg = p & 7, hi8 = (p >> 3) & 1;
                int idx = (ww * 4 + s) * 128 + (gg * 4 + t4v) * 4 + rk * 2 + hi8;
                su[PJ_XH + idx] = h;
                su[PJ_XL + idx] = l;
            }
        }
        // ---- W chunk -> B-frags (hi/lo) ----
#pragma unroll
        for (int i = 0; i < 8; i++) {
            int e = tid + i * 256;
            int j = e >> 4, cq = (e & 15) * 4;
            float4 v = *(const float4*)&wsel[j * CC + c0 + cq];
            uint32_t h0, l0, h1, l1;
            splitpair(v.x, v.y, h0, l0);
            splitpair(v.z, v.w, h1, l1);
            int s = cq >> 4, t4a = (cq >> 1) & 3, rg = (cq >> 3) & 1;
            int nt = j >> 3, n8 = j & 7;
            int blk = (s * 16 + nt) * 66;
            int oa = blk + (n8 * 4 + t4a) * 2 + rg;
            int ob = blk + (n8 * 4 + t4a + 1) * 2 + rg;
            su[PJ_WH + oa] = h0; su[PJ_WL + oa] = l0;
            su[PJ_WH + ob] = h1; su[PJ_WL + ob] = l1;
        }
        __syncthreads();

        // ---- mma: 3-term split ----
#pragma unroll
        for (int s = 0; s < 4; s++) {
            uint4 ahv = *(const uint4*)&su[PJ_XH + (w * 4 + s) * 128 + lane * 4];
            uint4 alv = *(const uint4*)&su[PJ_XL + (w * 4 + s) * 128 + lane * 4];
            const uint32_t* ah = (const uint32_t*)&ahv;
            const uint32_t* al = (const uint32_t*)&alv;
#pragma unroll
            for (int nt = 0; nt < 16; nt++) {
                uint2 bhv = *(const uint2*)&su[PJ_WH + (s * 16 + nt) * 66 + lane * 2];
                uint2 blv = *(const uint2*)&su[PJ_WL + (s * 16 + nt) * 66 + lane * 2];
                mma16(acc[nt], ah, (const uint32_t*)&bhv);
                mma16(acc[nt], al, (const uint32_t*)&bhv);
                mma16(acc[nt], ah, (const uint32_t*)&blv);
            }
        }
        __syncthreads();
    }

    // ---- +bias, stage [pixel 128][out 128] pitch 132 (scalar reads below) ----
#pragma unroll
    for (int nt = 0; nt < 16; nt++) {
        int col = nt * 8 + 2 * t4;
        float b0 = sf[PJ_BIAS + col], b1 = sf[PJ_BIAS + col + 1];
        int ra = w * 16 + gr, rb = ra + 8;
        sf[ra * 132 + col]     = acc[nt][0] + b0;
        sf[ra * 132 + col + 1] = acc[nt][1] + b1;
        sf[rb * 132 + col]     = acc[nt][2] + b0;
        sf[rb * 132 + col + 1] = acc[nt][3] + b1;
    }
    __syncthreads();

    if (jt == 0) {
        // theta -> A-frag gmem [b][rt=pt][ww 8][s 8][128]
        size_t base = (size_t)(b * 32 + pt) * 8192;
#pragma unroll
        for (int i = 0; i < 32; i++) {
            int e = tid + i * 256;
            int blk = e >> 7, off = e & 127;
            int ww = blk >> 3, s = blk & 7;
            int gg = off >> 4, ta = (off >> 2) & 3, rg = (off >> 1) & 1, hi8 = off & 1;
            int p = ww * 16 + hi8 * 8 + gg;
            int ic = s * 16 + rg * 8 + ta * 2;
            uint32_t h, l;
            splitpair(sf[p * 132 + ic], sf[p * 132 + ic + 1], h, l);
            d_thH[base + e] = h;
            d_thL[base + e] = l;
        }
    } else if (jt == 1) {
        // phi pooled -> B-frag gmem [b][ch][s 8][nt 8][64]
        int ch = pt >> 1, nthi = (pt & 1) * 4;
        size_t base = (size_t)(b * 16 + ch) * 4096;
#pragma unroll
        for (int i = 0; i < 8; i++) {
            int e = tid + i * 256;
            int s = e >> 8, r = e & 255;
            int ntl = r >> 6, woff = r & 63;
            int n8 = woff >> 3, ta = (woff >> 1) & 3, rg = woff & 1;
            int mc = ntl * 8 + n8;
            int ic = s * 16 + rg * 8 + ta * 2;
            int r0 = 2 * mc, r1 = 2 * mc + 1, r2 = 64 + 2 * mc, r3 = 65 + 2 * mc;
            float v0 = fmaxf(fmaxf(sf[r0 * 132 + ic],     sf[r1 * 132 + ic]),
                             fmaxf(sf[r2 * 132 + ic],     sf[r3 * 132 + ic]));
            float v1 = fmaxf(fmaxf(sf[r0 * 132 + ic + 1], sf[r1 * 132 + ic + 1]),
                             fmaxf(sf[r2 * 132 + ic + 1], sf[r3 * 132 + ic + 1]));
            uint32_t h, l;
            splitpair(v0, v1, h, l);
            size_t idx = base + ((size_t)s * 8 + nthi + ntl) * 64 + woff;
            d_phH[idx] = h;
            d_phL[idx] = l;
        }
    } else {
        // g pooled -> B-frag gmem [b][ch][kt 4][nt 16][64]
        int ch = pt >> 1, kthi = (pt & 1) * 2;
        size_t base = (size_t)(b * 16 + ch) * 4096;
#pragma unroll
        for (int i = 0; i < 8; i++) {
            int e = tid + i * 256;
            int ktl = e >> 10, r = e & 1023;
            int nt = r >> 6, woff = r & 63;
            int n8 = woff >> 3, ta = (woff >> 1) & 3, rg = woff & 1;
            int m16 = rg * 8 + ta * 2;
            int mc = ktl * 16 + m16;
            int ic = nt * 8 + n8;
            int ra = 2 * mc, rb = 2 * mc + 1, rc = 64 + 2 * mc, rd = 65 + 2 * mc;
            float v0 = fmaxf(fmaxf(sf[ra * 132 + ic], sf[rb * 132 + ic]),
                             fmaxf(sf[rc * 132 + ic], sf[rd * 132 + ic]));
            ra += 2; rb += 2; rc += 2; rd += 2;   // pooled key mc+1
            float v1 = fmaxf(fmaxf(sf[ra * 132 + ic], sf[rb * 132 + ic]),
                             fmaxf(sf[rc * 132 + ic], sf[rd * 132 + ic]));
            uint32_t h, l;
            splitpair(v0, v1, h, l);
            size_t idx = base + ((size_t)(kthi + ktl) * 16 + nt) * 64 + woff;
            d_gH[idx] = h;
            d_gL[idx] = l;
        }
    }
}

// =====================================================================
// Kernel 2: bf16 attention, all operands pre-fragged.
// Per chunk: uint4 copy phi/g frags -> smem; S-mma; in-register P; Y-mma.
// smem u32: TH_H[0,8192) TH_L[8192,16384) PB_H[16384,20480)
//           PB_L[20480,24576) GB_H[24576,28672) GB_L[28672,32768)
// =====================================================================
#define A_THH 0
#define A_THL 8192
#define A_PBH 16384
#define A_PBL 20480
#define A_GBH 24576
#define A_GBL 28672
#define AT_U32 32768

__global__ void __launch_bounds__(256, 1) attn_bf16_kernel()
{
    extern __shared__ uint32_t su[];
    int tid = threadIdx.x;
    int w = tid >> 5, lane = tid & 31;
    int rt = blockIdx.x, b = blockIdx.y;

    // ---- prologue: copy theta A-frags (linear) ----
    {
        size_t base = (size_t)(b * 32 + rt) * 8192;
#pragma unroll
        for (int i = 0; i < 8; i++) {
            int e4 = (tid + i * 256) * 4;
            *(uint4*)&su[A_THH + e4] = *(const uint4*)&d_thH[base + e4];
            *(uint4*)&su[A_THL + e4] = *(const uint4*)&d_thL[base + e4];
        }
    }
    __syncthreads();

    float yacc[16][4];
#pragma unroll
    for (int nt = 0; nt < 16; nt++)
#pragma unroll
        for (int q = 0; q < 4; q++) yacc[nt][q] = 0.f;
    float ls0 = 0.f, ls1 = 0.f;

    for (int ch = 0; ch < 16; ch++) {
        // ---- copy phi/g frag chunks (linear uint4) ----
        {
            size_t base = (size_t)(b * 16 + ch) * 4096;
#pragma unroll
            for (int i = 0; i < 4; i++) {
                int e4 = (tid + i * 256) * 4;
                *(uint4*)&su[A_PBH + e4] = *(const uint4*)&d_phH[base + e4];
                *(uint4*)&su[A_PBL + e4] = *(const uint4*)&d_phL[base + e4];
                *(uint4*)&su[A_GBH + e4] = *(const uint4*)&d_gH[base + e4];
                *(uint4*)&su[A_GBL + e4] = *(const uint4*)&d_gL[base + e4];
            }
        }
        __syncthreads();

        // ---- S = theta . phi (3-term bf16 split) ----
        float sacc[8][4];
#pragma unroll
        for (int nt = 0; nt < 8; nt++)
#pragma unroll
            for (int q = 0; q < 4; q++) sacc[nt][q] = 0.f;

#pragma unroll
        for (int s = 0; s < 8; s++) {
            uint4 ahv = *(const uint4*)&su[A_THH + (w * 8 + s) * 128 + lane * 4];
            uint4 alv = *(const uint4*)&su[A_THL + (w * 8 + s) * 128 + lane * 4];
            const uint32_t* ah = (const uint32_t*)&ahv;
            const uint32_t* al = (const uint32_t*)&alv;
#pragma unroll
            for (int nt = 0; nt < 8; nt++) {
                uint2 bhv = *(const uint2*)&su[A_PBH + (s * 8 + nt) * 64 + lane * 2];
                uint2 blv = *(const uint2*)&su[A_PBL + (s * 8 + nt) * 64 + lane * 2];
                mma16(sacc[nt], ah, (const uint32_t*)&bhv);
                mma16(sacc[nt], al, (const uint32_t*)&bhv);
                mma16(sacc[nt], ah, (const uint32_t*)&blv);
            }
        }

        // ---- P = exp(S - 40): in-register, pack straight to A-frags ----
        uint32_t pa[16], pl[16];   // [nt*2], [nt*2+1] = rows gr / gr+8
#pragma unroll
        for (int nt = 0; nt < 8; nt++) {
            float p0 = __expf(sacc[nt][0] - 40.f);
            float p1 = __expf(sacc[nt][1] - 40.f);
            float p2 = __expf(sacc[nt][2] - 40.f);
            float p3 = __expf(sacc[nt][3] - 40.f);
            ls0 += p0 + p1;
            ls1 += p2 + p3;
            splitpair(p0, p1, pa[nt * 2],     pl[nt * 2]);
            splitpair(p2, p3, pa[nt * 2 + 1], pl[nt * 2 + 1]);
        }

        // ---- Y += P @ g (3-term bf16 split), P from registers ----
#pragma unroll
        for (int kt = 0; kt < 4; kt++) {
            uint32_t ah[4] = { pa[4 * kt], pa[4 * kt + 1], pa[4 * kt + 2], pa[4 * kt + 3] };
            uint32_t al[4] = { pl[4 * kt], pl[4 * kt + 1], pl[4 * kt + 2], pl[4 * kt + 3] };
#pragma unroll
            for (int nt = 0; nt < 16; nt++) {
                uint2 ghv = *(const uint2*)&su[A_GBH + (kt * 16 + nt) * 64 + lane * 2];
                uint2 glv = *(const uint2*)&su[A_GBL + (kt * 16 + nt) * 64 + lane * 2];
                mma16(yacc[nt], ah, (const uint32_t*)&ghv);
                mma16(yacc[nt], al, (const uint32_t*)&ghv);
                mma16(yacc[nt], ah, (const uint32_t*)&glv);
            }
        }
        __syncthreads();   // phi/g buffers free for next chunk
    }

    // ---- epilogue: normalize, split hi/lo, store y as A-frags ----
    ls0 += __shfl_xor_sync(0xffffffffu, ls0, 1);
    ls0 += __shfl_xor_sync(0xffffffffu, ls0, 2);
    ls1 += __shfl_xor_sync(0xffffffffu, ls1, 1);
    ls1 += __shfl_xor_sync(0xffffffffu, ls1, 2);
    float inv0 = 1.f / ls0, inv1 = 1.f / ls1;

    size_t base = ((size_t)(b * 32 + rt) * 8 + w) * 1024;
#pragma unroll
    for (int kt = 0; kt < 8; kt++) {
        uint32_t h0, l0, h1, l1, h2, l2, h3, l3;
        splitpair(yacc[2 * kt][0] * inv0, yacc[2 * kt][1] * inv0, h0, l0);
        splitpair(yacc[2 * kt][2] * inv1, yacc[2 * kt][3] * inv1, h1, l1);
        splitpair(yacc[2 * kt + 1][0] * inv0, yacc[2 * kt + 1][1] * inv0, h2, l2);
        splitpair(yacc[2 * kt + 1][2] * inv1, yacc[2 * kt + 1][3] * inv1, h3, l3);
        *(uint4*)&d_yh[base + kt * 128 + lane * 4] = make_uint4(h0, h1, h2, h3);
        *(uint4*)&d_yl[base + kt * 128 + lane * 4] = make_uint4(l0, l1, l2, l3);
    }
}

// =====================================================================
// Kernel 3: output conv via bf16 mma (3-term) + BN + residual (unchanged)
// =====================================================================
#define OK_BH 0
#define OK_BL 8448
#define OK_BN 16896
#define OK_U32 17152

__global__ void __launch_bounds__(256) out_mma_kernel(
    const float* __restrict__ x,
    const float* __restrict__ Ww,    const float* __restrict__ Wb,
    const float* __restrict__ gamma, const float* __restrict__ beta,
    const float* __restrict__ bmean, const float* __restrict__ bvar,
    float* __restrict__ out)
{
    extern __shared__ uint32_t su[];
    float* sf = (float*)su;

    int pt = blockIdx.x, jt = blockIdx.y, b = blockIdx.z;
    int oc0 = jt * 128;
    int tid = threadIdx.x;
    int w = tid >> 5, lane = tid & 31;
    int gr = lane >> 2, t4 = lane & 3;

    if (tid < 128) {
        int oc = oc0 + tid;
        float inv = gamma[oc] * rsqrtf(bvar[oc] + 1e-5f);
        sf[OK_BN + tid] = inv;
        sf[OK_BN + 128 + tid] = (Wb[oc] - bmean[oc]) * inv + beta[oc];
    }

    // ---- W -> B-frags (hi/lo), K=128 ----
#pragma unroll
    for (int i = 0; i < 16; i++) {
        int e = tid + i * 256;
        int j = e >> 5, cq = (e & 31) * 4;
        float4 v = *(const float4*)&Ww[(oc0 + j) * ICn + cq];
        uint32_t h0, l0, h1, l1;
        splitpair(v.x, v.y, h0, l0);
        splitpair(v.z, v.w, h1, l1);
        int s = cq >> 4, t4a = (cq >> 1) & 3, rg = (cq >> 3) & 1;
        int nt = j >> 3, n8 = j & 7;
        int blk = (s * 16 + nt) * 66;
        int oa = blk + (n8 * 4 + t4a) * 2 + rg;
        int ob = blk + (n8 * 4 + t4a + 1) * 2 + rg;
        su[OK_BH + oa] = h0; su[OK_BL + oa] = l0;
        su[OK_BH + ob] = h1; su[OK_BL + ob] = l1;
    }
    __syncthreads();

    float acc[16][4];
#pragma unroll
    for (int nt = 0; nt < 16; nt++)
#pragma unroll
        for (int q = 0; q < 4; q++) acc[nt][q] = 0.f;

    size_t abase = ((size_t)(b * 32 + pt) * 8 + w) * 1024;
#pragma unroll
    for (int kt = 0; kt < 8; kt++) {
        uint4 ahv = *(const uint4*)&d_yh[abase + kt * 128 + lane * 4];
        uint4 alv = *(const uint4*)&d_yl[abase + kt * 128 + lane * 4];
        const uint32_t* ah = (const uint32_t*)&ahv;
        const uint32_t* al = (const uint32_t*)&alv;
#pragma unroll
        for (int nt = 0; nt < 16; nt++) {
            uint2 bhv = *(const uint2*)&su[OK_BH + (kt * 16 + nt) * 66 + lane * 2];
            uint2 blv = *(const uint2*)&su[OK_BL + (kt * 16 + nt) * 66 + lane * 2];
            mma16(acc[nt], ah, (const uint32_t*)&bhv);
            mma16(acc[nt], al, (const uint32_t*)&bhv);
            mma16(acc[nt], ah, (const uint32_t*)&blv);
        }
    }
    __syncthreads();

    // ---- BN, stage [pixel][oc] pitch 130 (scalar access only) ----
#pragma unroll
    for (int nt = 0; nt < 16; nt++) {
        int col = nt * 8 + 2 * t4;
        float i0 = sf[OK_BN + col],       i1 = sf[OK_BN + col + 1];
        float a0 = sf[OK_BN + 128 + col], a1 = sf[OK_BN + 128 + col + 1];
        int ra = w * 16 + gr, rb = ra + 8;
        sf[ra * 130 + col]     = acc[nt][0] * i0 + a0;
        sf[ra * 130 + col + 1] = acc[nt][1] * i1 + a1;
        sf[rb * 130 + col]     = acc[nt][2] * i0 + a0;
        sf[rb * 130 + col + 1] = acc[nt][3] * i1 + a1;
    }
    __syncthreads();

    // ---- transpose write + residual ----
    const float* xr = x + ((size_t)b * CC + oc0) * NPIX + pt * 128;
    float* outp = out + ((size_t)b * CC + oc0) * NPIX + pt * 128;
#pragma unroll
    for (int i = 0; i < 16; i++) {
        int e = tid + i * 256;
        int oc = e >> 5, pq = (e & 31) * 4;
        float4 xv = *(const float4*)&xr[(size_t)oc * NPIX + pq];
        float4 v = make_float4(sf[(pq + 0) * 130 + oc] + xv.x,
                               sf[(pq + 1) * 130 + oc] + xv.y,
                               sf[(pq + 2) * 130 + oc] + xv.z,
                               sf[(pq + 3) * 130 + oc] + xv.w);
        *(float4*)&outp[(size_t)oc * NPIX + pq] = v;
    }
}

// =====================================================================
extern "C" void kernel_launch(void* const* d_in, const int* in_sizes, int n_in,
                              void* d_out, int out_size)
{
    (void)in_sizes; (void)n_in; (void)out_size;
    const float* x    = (const float*)d_in[0];
    const float* g_w  = (const float*)d_in[1];
    const float* g_b  = (const float*)d_in[2];
    const float* th_w = (const float*)d_in[3];
    const float* th_b = (const float*)d_in[4];
    const float* ph_w = (const float*)d_in[5];
    const float* ph_b = (const float*)d_in[6];
    const float* W_w  = (const float*)d_in[7];
    const float* W_b  = (const float*)d_in[8];
    const float* bg   = (const float*)d_in[9];
    const float* bbta = (const float*)d_in[10];
    const float* bm   = (const float*)d_in[11];
    const float* bv   = (const float*)d_in[12];
    float* out = (float*)d_out;

    static int configured = 0;
    if (!configured) {
        cudaFuncSetAttribute(proj_mma_kernel,
            cudaFuncAttributeMaxDynamicSharedMemorySize, PJ_U32 * 4);
        cudaFuncSetAttribute(attn_bf16_kernel,
            cudaFuncAttributeMaxDynamicSharedMemorySize, AT_U32 * 4);
        cudaFuncSetAttribute(out_mma_kernel,
            cudaFuncAttributeMaxDynamicSharedMemorySize, OK_U32 * 4);
        configured = 1;
    }

    proj_mma_kernel<<<dim3(32, 3, 8), 256, PJ_U32 * 4>>>(
        x, g_w, g_b, th_w, th_b, ph_w, ph_b);

    attn_bf16_kernel<<<dim3(32, 8), 256, AT_U32 * 4>>>();

    out_mma_kernel<<<dim3(32, 2, 8), 256, OK_U32 * 4>>>(
        x, W_w, W_b, bg, bbta, bm, bv, out);
}

// round 10
// speedup vs baseline: 2.1712x; 1.0190x over previous
#include <cuda_runtime.h>
#include <math.h>
#include <stdint.h>

#define BB   8
#define CC   256
#define ICn  128
#define NPIX 4096
#define NPm  1024

// ---------- bf16 helpers ----------
__device__ __forceinline__ uint32_t packbf(float e0, float e1) {
    uint32_t r; asm("cvt.rn.bf16x2.f32 %0, %1, %2;" : "=r"(r) : "f"(e1), "f"(e0)); return r;
}
__device__ __forceinline__ void splitpair(float v0, float v1, uint32_t &hp, uint32_t &lp) {
    hp = packbf(v0, v1);
    float h0 = __uint_as_float(hp << 16);
    float h1 = __uint_as_float(hp & 0xffff0000u);
    lp = packbf(v0 - h0, v1 - h1);
}

// mma.sync m16n8k16 bf16: C += A*B
__device__ __forceinline__ void mma16(float* c, const uint32_t* a, const uint32_t* b) {
    asm volatile("mma.sync.aligned.m16n8k16.row.col.f32.bf16.bf16.f32 "
        "{%0,%1,%2,%3}, {%4,%5,%6,%7}, {%8,%9}, {%0,%1,%2,%3};"
        : "+f"(c[0]), "+f"(c[1]), "+f"(c[2]), "+f"(c[3])
        : "r"(a[0]), "r"(a[1]), "r"(a[2]), "r"(a[3]), "r"(b[0]), "r"(b[1]));
}

// ---------- scratch: everything in frag format (hi/lo bf16x2) ----------
__device__ uint32_t d_xH [BB * 32 * 16384];      // x A-frags [b][pt][ch4][ww8 s4][128]
__device__ uint32_t d_xL [BB * 32 * 16384];
__device__ uint32_t d_wpH[3 * 16384 + 2 * 8192]; // proj W B-frags [jt][ch][s][nt][64]; out W at 49152
__device__ uint32_t d_wpL[3 * 16384 + 2 * 8192];
__device__ uint32_t d_thH[BB * 32 * 8192];       // theta A-frags [b][rt][ww][s][128]
__device__ uint32_t d_thL[BB * 32 * 8192];
__device__ uint32_t d_phH[BB * 16 * 4096];       // phi B-frags [b][ch][s 8][nt 8][64]
__device__ uint32_t d_phL[BB * 16 * 4096];
__device__ uint32_t d_gH [BB * 16 * 4096];       // g B-frags [b][ch][kt 4][nt 16][64]
__device__ uint32_t d_gL [BB * 16 * 4096];
__device__ uint32_t d_yh [BB * 32 * 8192];       // y A-frags (attn -> out)
__device__ uint32_t d_yl [BB * 32 * 8192];

#define OW_BASE 49152

// =====================================================================
// Kernel 0a: weight prep — convert all weights to B-frags once.
// grid(5): jt 0=theta, 1=phi, 2=g (K=256); jt 3,4 = out W halves (K=128)
// =====================================================================
__global__ void __launch_bounds__(256) wprep_kernel(
    const float* __restrict__ g_w, const float* __restrict__ th_w,
    const float* __restrict__ ph_w, const float* __restrict__ W_w)
{
    int jt = blockIdx.x, tid = threadIdx.x;
    if (jt < 3) {
        const float* wsel = (jt == 0) ? th_w : (jt == 1) ? ph_w : g_w;
#pragma unroll
        for (int i = 0; i < 64; i++) {
            int e = tid + i * 256;           // 16384 pairs
            int j = e >> 7, kp = e & 127, k0 = 2 * kp;
            float2 v = *(const float2*)&wsel[j * CC + k0];
            uint32_t h, l;
            splitpair(v.x, v.y, h, l);
            int ch = k0 >> 6, kl = k0 & 63;
            int s = kl >> 4, rg = (kl >> 3) & 1, ta = (kl >> 1) & 3;
            int nt = j >> 3, n8 = j & 7;
            int idx = jt * 16384 + ch * 4096 + (s * 16 + nt) * 64 + (n8 * 4 + ta) * 2 + rg;
            d_wpH[idx] = h;
            d_wpL[idx] = l;
        }
    } else {
        int oc0 = (jt - 3) * 128;
#pragma unroll
        for (int i = 0; i < 32; i++) {
            int e = tid + i * 256;           // 8192 pairs
            int oc = e >> 6, kp = e & 63, k0 = 2 * kp;
            float2 v = *(const float2*)&W_w[(oc0 + oc) * ICn + k0];
            uint32_t h, l;
            splitpair(v.x, v.y, h, l);
            int kt = k0 >> 4, rg = (k0 >> 3) & 1, ta = (k0 >> 1) & 3;
            int nt = oc >> 3, n8 = oc & 7;
            int idx = OW_BASE + (jt - 3) * 8192 + (kt * 16 + nt) * 64 + (n8 * 4 + ta) * 2 + rg;
            d_wpH[idx] = h;
            d_wpL[idx] = l;
        }
    }
}

// =====================================================================
// Kernel 0b: x prep — convert each 128-pixel tile of x to A-frags once.
// grid (32, 8), 256 threads, smem 32KB staging.
// =====================================================================
__global__ void __launch_bounds__(256) xprep_kernel(const float* __restrict__ x)
{
    __shared__ float sx[64 * 128];
    int pt = blockIdx.x, b = blockIdx.y, tid = threadIdx.x;
    size_t base = (size_t)(b * 32 + pt) * 16384;

    for (int ch = 0; ch < 4; ch++) {
#pragma unroll
        for (int i = 0; i < 8; i++) {        // 2048 float4 = 64 rows x 128 cols
            int e = tid + i * 256;
            int kc = e >> 5, p4 = (e & 31) * 4;
            *(float4*)&sx[kc * 128 + p4] =
                *(const float4*)&x[((size_t)b * CC + ch * 64 + kc) * NPIX + pt * 128 + p4];
        }
        __syncthreads();
#pragma unroll
        for (int i = 0; i < 16; i++) {
            int e = tid + i * 256;           // 4096 frag u32
            int blk = e >> 7, off = e & 127;
            int ww = blk >> 2, s = blk & 3;
            int gg = off >> 4, ta = (off >> 2) & 3, rg = (off >> 1) & 1, hi8 = off & 1;
            int p = ww * 16 + hi8 * 8 + gg;
            int kl = s * 16 + rg * 8 + ta * 2;
            uint32_t h, l;
            splitpair(sx[kl * 128 + p], sx[(kl + 1) * 128 + p], h, l);
            d_xH[base + ch * 4096 + e] = h;
            d_xL[base + ch * 4096 + e] = l;
        }
        __syncthreads();
    }
}

// =====================================================================
// Kernel 1: projection mma + fused 2x2 maxpool. All operands pre-fragged.
// 4x2 warp tiling: wM = w>>1 (32 rows), wN = w&1 (64 cols).
// smem u32: XH[0,4096) XL[4096,8192) WH[8192,12288) WL[12288,16384)
//           BIAS f32 [16896,17024); stage f32 [128][132] overlays [0,16896)
// =====================================================================
#define PJ_XH 0
#define PJ_XL 4096
#define PJ_WH 8192
#define PJ_WL 12288
#define PJ_BIAS 16896
#define PJ_U32 17024

__global__ void __launch_bounds__(256) proj_mma_kernel(
    const float* __restrict__ g_b, const float* __restrict__ th_b,
    const float* __restrict__ ph_b)
{
    extern __shared__ uint32_t su[];
    float* sf = (float*)su;

    int pt = blockIdx.x, jt = blockIdx.y, b = blockIdx.z;
    const float* bsel = (jt == 0) ? th_b : (jt == 1) ? ph_b : g_b;

    int tid = threadIdx.x;
    int w = tid >> 5, lane = tid & 31;
    int gr = lane >> 2, t4 = lane & 3;
    int wM = w >> 1, wN = w & 1;

    if (tid < 128) sf[PJ_BIAS + tid] = bsel[tid];

    float acc[2][8][4];
#pragma unroll
    for (int mt = 0; mt < 2; mt++)
#pragma unroll
        for (int nt = 0; nt < 8; nt++)
#pragma unroll
            for (int q = 0; q < 4; q++) acc[mt][nt][q] = 0.f;

    size_t xbase = (size_t)(b * 32 + pt) * 16384;

    for (int ch = 0; ch < 4; ch++) {
        // ---- linear copies: X frag chunk + W frag chunk ----
        {
            size_t xo = xbase + ch * 4096;
            int wo = jt * 16384 + ch * 4096;
#pragma unroll
            for (int i = 0; i < 4; i++) {
                int e4 = (tid + i * 256) * 4;
                *(uint4*)&su[PJ_XH + e4] = *(const uint4*)&d_xH[xo + e4];
                *(uint4*)&su[PJ_XL + e4] = *(const uint4*)&d_xL[xo + e4];
                *(uint4*)&su[PJ_WH + e4] = *(const uint4*)&d_wpH[wo + e4];
                *(uint4*)&su[PJ_WL + e4] = *(const uint4*)&d_wpL[wo + e4];
            }
        }
        __syncthreads();

        // ---- mma: 3-term split, 4x2 warp tiling ----
#pragma unroll
        for (int s = 0; s < 4; s++) {
            uint4 ahv[2], alv[2];
#pragma unroll
            for (int mt = 0; mt < 2; mt++) {
                int ww = wM * 2 + mt;
                ahv[mt] = *(const uint4*)&su[PJ_XH + (ww * 4 + s) * 128 + lane * 4];
                alv[mt] = *(const uint4*)&su[PJ_XL + (ww * 4 + s) * 128 + lane * 4];
            }
#pragma unroll
            for (int nt = 0; nt < 8; nt++) {
                int ntg = wN * 8 + nt;
                uint2 bhv = *(const uint2*)&su[PJ_WH + (s * 16 + ntg) * 64 + lane * 2];
                uint2 blv = *(const uint2*)&su[PJ_WL + (s * 16 + ntg) * 64 + lane * 2];
#pragma unroll
                for (int mt = 0; mt < 2; mt++) {
                    mma16(acc[mt][nt], (const uint32_t*)&ahv[mt], (const uint32_t*)&bhv);
                    mma16(acc[mt][nt], (const uint32_t*)&alv[mt], (const uint32_t*)&bhv);
                    mma16(acc[mt][nt], (const uint32_t*)&ahv[mt], (const uint32_t*)&blv);
                }
            }
        }
        __syncthreads();
    }

    // ---- +bias, stage [pixel 128][out 128] pitch 132 ----
#pragma unroll
    for (int mt = 0; mt < 2; mt++)
#pragma unroll
    for (int nt = 0; nt < 8; nt++) {
        int col = wN * 64 + nt * 8 + 2 * t4;
        float b0 = sf[PJ_BIAS + col], b1 = sf[PJ_BIAS + col + 1];
        int ra = (wM * 2 + mt) * 16 + gr, rb = ra + 8;
        sf[ra * 132 + col]     = acc[mt][nt][0] + b0;
        sf[ra * 132 + col + 1] = acc[mt][nt][1] + b1;
        sf[rb * 132 + col]     = acc[mt][nt][2] + b0;
        sf[rb * 132 + col + 1] = acc[mt][nt][3] + b1;
    }
    __syncthreads();

    if (jt == 0) {
        // theta -> A-frag gmem [b][rt=pt][ww 8][s 8][128]
        size_t base = (size_t)(b * 32 + pt) * 8192;
#pragma unroll
        for (int i = 0; i < 32; i++) {
            int e = tid + i * 256;
            int blk = e >> 7, off = e & 127;
            int ww = blk >> 3, s = blk & 7;
            int gg = off >> 4, ta = (off >> 2) & 3, rg = (off >> 1) & 1, hi8 = off & 1;
            int p = ww * 16 + hi8 * 8 + gg;
            int ic = s * 16 + rg * 8 + ta * 2;
            uint32_t h, l;
            splitpair(sf[p * 132 + ic], sf[p * 132 + ic + 1], h, l);
            d_thH[base + e] = h;
            d_thL[base + e] = l;
        }
    } else if (jt == 1) {
        // phi pooled -> B-frag gmem [b][ch][s 8][nt 8][64]
        int ch = pt >> 1, nthi = (pt & 1) * 4;
        size_t base = (size_t)(b * 16 + ch) * 4096;
#pragma unroll
        for (int i = 0; i < 8; i++) {
            int e = tid + i * 256;
            int s = e >> 8, r = e & 255;
            int ntl = r >> 6, woff = r & 63;
            int n8 = woff >> 3, ta = (woff >> 1) & 3, rg = woff & 1;
            int mc = ntl * 8 + n8;
            int ic = s * 16 + rg * 8 + ta * 2;
            int r0 = 2 * mc, r1 = 2 * mc + 1, r2 = 64 + 2 * mc, r3 = 65 + 2 * mc;
            float v0 = fmaxf(fmaxf(sf[r0 * 132 + ic],     sf[r1 * 132 + ic]),
                             fmaxf(sf[r2 * 132 + ic],     sf[r3 * 132 + ic]));
            float v1 = fmaxf(fmaxf(sf[r0 * 132 + ic + 1], sf[r1 * 132 + ic + 1]),
                             fmaxf(sf[r2 * 132 + ic + 1], sf[r3 * 132 + ic + 1]));
            uint32_t h, l;
            splitpair(v0, v1, h, l);
            size_t idx = base + ((size_t)s * 8 + nthi + ntl) * 64 + woff;
            d_phH[idx] = h;
            d_phL[idx] = l;
        }
    } else {
        // g pooled -> B-frag gmem [b][ch][kt 4][nt 16][64]
        int ch = pt >> 1, kthi = (pt & 1) * 2;
        size_t base = (size_t)(b * 16 + ch) * 4096;
#pragma unroll
        for (int i = 0; i < 8; i++) {
            int e = tid + i * 256;
            int ktl = e >> 10, r = e & 1023;
            int nt = r >> 6, woff = r & 63;
            int n8 = woff >> 3, ta = (woff >> 1) & 3, rg = woff & 1;
            int m16 = rg * 8 + ta * 2;
            int mc = ktl * 16 + m16;
            int ic = nt * 8 + n8;
            int ra = 2 * mc, rb = 2 * mc + 1, rc = 64 + 2 * mc, rd = 65 + 2 * mc;
            float v0 = fmaxf(fmaxf(sf[ra * 132 + ic], sf[rb * 132 + ic]),
                             fmaxf(sf[rc * 132 + ic], sf[rd * 132 + ic]));
            ra += 2; rb += 2; rc += 2; rd += 2;
            float v1 = fmaxf(fmaxf(sf[ra * 132 + ic], sf[rb * 132 + ic]),
                             fmaxf(sf[rc * 132 + ic], sf[rd * 132 + ic]));
            uint32_t h, l;
            splitpair(v0, v1, h, l);
            size_t idx = base + ((size_t)(kthi + ktl) * 16 + nt) * 64 + woff;
            d_gH[idx] = h;
            d_gL[idx] = l;
        }
    }
}

// =====================================================================
// Kernel 2: bf16 attention (unchanged from round 8 passing version)
// =====================================================================
#define A_THH 0
#define A_THL 8192
#define A_PBH 16384
#define A_PBL 20480
#define A_GBH 24576
#define A_GBL 28672
#define AT_U32 32768

__global__ void __launch_bounds__(256, 1) attn_bf16_kernel()
{
    extern __shared__ uint32_t su[];
    int tid = threadIdx.x;
    int w = tid >> 5, lane = tid & 31;
    int rt = blockIdx.x, b = blockIdx.y;

    {
        size_t base = (size_t)(b * 32 + rt) * 8192;
#pragma unroll
        for (int i = 0; i < 8; i++) {
            int e4 = (tid + i * 256) * 4;
            *(uint4*)&su[A_THH + e4] = *(const uint4*)&d_thH[base + e4];
            *(uint4*)&su[A_THL + e4] = *(const uint4*)&d_thL[base + e4];
        }
    }
    __syncthreads();

    float yacc[16][4];
#pragma unroll
    for (int nt = 0; nt < 16; nt++)
#pragma unroll
        for (int q = 0; q < 4; q++) yacc[nt][q] = 0.f;
    float ls0 = 0.f, ls1 = 0.f;

    for (int ch = 0; ch < 16; ch++) {
        {
            size_t base = (size_t)(b * 16 + ch) * 4096;
#pragma unroll
            for (int i = 0; i < 4; i++) {
                int e4 = (tid + i * 256) * 4;
                *(uint4*)&su[A_PBH + e4] = *(const uint4*)&d_phH[base + e4];
                *(uint4*)&su[A_PBL + e4] = *(const uint4*)&d_phL[base + e4];
                *(uint4*)&su[A_GBH + e4] = *(const uint4*)&d_gH[base + e4];
                *(uint4*)&su[A_GBL + e4] = *(const uint4*)&d_gL[base + e4];
            }
        }
        __syncthreads();

        float sacc[8][4];
#pragma unroll
        for (int nt = 0; nt < 8; nt++)
#pragma unroll
            for (int q = 0; q < 4; q++) sacc[nt][q] = 0.f;

#pragma unroll
        for (int s = 0; s < 8; s++) {
            uint4 ahv = *(const uint4*)&su[A_THH + (w * 8 + s) * 128 + lane * 4];
            uint4 alv = *(const uint4*)&su[A_THL + (w * 8 + s) * 128 + lane * 4];
            const uint32_t* ah = (const uint32_t*)&ahv;
            const uint32_t* al = (const uint32_t*)&alv;
#pragma unroll
            for (int nt = 0; nt < 8; nt++) {
                uint2 bhv = *(const uint2*)&su[A_PBH + (s * 8 + nt) * 64 + lane * 2];
                uint2 blv = *(const uint2*)&su[A_PBL + (s * 8 + nt) * 64 + lane * 2];
                mma16(sacc[nt], ah, (const uint32_t*)&bhv);
                mma16(sacc[nt], al, (const uint32_t*)&bhv);
                mma16(sacc[nt], ah, (const uint32_t*)&blv);
            }
        }

        uint32_t pa[16], pl[16];
#pragma unroll
        for (int nt = 0; nt < 8; nt++) {
            float p0 = __expf(sacc[nt][0] - 40.f);
            float p1 = __expf(sacc[nt][1] - 40.f);
            float p2 = __expf(sacc[nt][2] - 40.f);
            float p3 = __expf(sacc[nt][3] - 40.f);
            ls0 += p0 + p1;
            ls1 += p2 + p3;
            splitpair(p0, p1, pa[nt * 2],     pl[nt * 2]);
            splitpair(p2, p3, pa[nt * 2 + 1], pl[nt * 2 + 1]);
        }

#pragma unroll
        for (int kt = 0; kt < 4; kt++) {
            uint32_t ah[4] = { pa[4 * kt], pa[4 * kt + 1], pa[4 * kt + 2], pa[4 * kt + 3] };
            uint32_t al[4] = { pl[4 * kt], pl[4 * kt + 1], pl[4 * kt + 2], pl[4 * kt + 3] };
#pragma unroll
            for (int nt = 0; nt < 16; nt++) {
                uint2 ghv = *(const uint2*)&su[A_GBH + (kt * 16 + nt) * 64 + lane * 2];
                uint2 glv = *(const uint2*)&su[A_GBL + (kt * 16 + nt) * 64 + lane * 2];
                mma16(yacc[nt], ah, (const uint32_t*)&ghv);
                mma16(yacc[nt], al, (const uint32_t*)&ghv);
                mma16(yacc[nt], ah, (const uint32_t*)&glv);
            }
        }
        __syncthreads();
    }

    ls0 += __shfl_xor_sync(0xffffffffu, ls0, 1);
    ls0 += __shfl_xor_sync(0xffffffffu, ls0, 2);
    ls1 += __shfl_xor_sync(0xffffffffu, ls1, 1);
    ls1 += __shfl_xor_sync(0xffffffffu, ls1, 2);
    float inv0 = 1.f / ls0, inv1 = 1.f / ls1;

    size_t base = ((size_t)(b * 32 + rt) * 8 + w) * 1024;
#pragma unroll
    for (int kt = 0; kt < 8; kt++) {
        uint32_t h0, l0, h1, l1, h2, l2, h3, l3;
        splitpair(yacc[2 * kt][0] * inv0, yacc[2 * kt][1] * inv0, h0, l0);
        splitpair(yacc[2 * kt][2] * inv1, yacc[2 * kt][3] * inv1, h1, l1);
        splitpair(yacc[2 * kt + 1][0] * inv0, yacc[2 * kt + 1][1] * inv0, h2, l2);
        splitpair(yacc[2 * kt + 1][2] * inv1, yacc[2 * kt + 1][3] * inv1, h3, l3);
        *(uint4*)&d_yh[base + kt * 128 + lane * 4] = make_uint4(h0, h1, h2, h3);
        *(uint4*)&d_yl[base + kt * 128 + lane * 4] = make_uint4(l0, l1, l2, l3);
    }
}

// =====================================================================
// Kernel 3: output conv mma + BN + residual. Pre-fragged W, 4x2 tiling.
// smem u32: BH[0,8192) BL[8192,16384) BN f32 [16640,16896)
// stage f32 [128][130] overlays [0,16640)
// =====================================================================
#define OK_BH 0
#define OK_BL 8192
#define OK_BN 16640
#define OK_U32 16896

__global__ void __launch_bounds__(256) out_mma_kernel(
    const float* __restrict__ x,
    const float* __restrict__ Wb,    const float* __restrict__ gamma,
    const float* __restrict__ beta,  const float* __restrict__ bmean,
    const float* __restrict__ bvar,  float* __restrict__ out)
{
    extern __shared__ uint32_t su[];
    float* sf = (float*)su;

    int pt = blockIdx.x, jt = blockIdx.y, b = blockIdx.z;
    int oc0 = jt * 128;
    int tid = threadIdx.x;
    int w = tid >> 5, lane = tid & 31;
    int gr = lane >> 2, t4 = lane & 3;
    int wM = w >> 1, wN = w & 1;

    if (tid < 128) {
        int oc = oc0 + tid;
        float inv = gamma[oc] * rsqrtf(bvar[oc] + 1e-5f);
        sf[OK_BN + tid] = inv;
        sf[OK_BN + 128 + tid] = (Wb[oc] - bmean[oc]) * inv + beta[oc];
    }

    // ---- copy W frags (linear) ----
    {
        int wo = OW_BASE + jt * 8192;
#pragma unroll
        for (int i = 0; i < 8; i++) {
            int e4 = (tid + i * 256) * 4;
            *(uint4*)&su[OK_BH + e4] = *(const uint4*)&d_wpH[wo + e4];
            *(uint4*)&su[OK_BL + e4] = *(const uint4*)&d_wpL[wo + e4];
        }
    }
    __syncthreads();

    float acc[2][8][4];
#pragma unroll
    for (int mt = 0; mt < 2; mt++)
#pragma unroll
        for (int nt = 0; nt < 8; nt++)
#pragma unroll
            for (int q = 0; q < 4; q++) acc[mt][nt][q] = 0.f;

    size_t abase = (size_t)(b * 32 + pt) * 8192;
#pragma unroll
    for (int kt = 0; kt < 8; kt++) {
        uint4 ahv[2], alv[2];
#pragma unroll
        for (int mt = 0; mt < 2; mt++) {
            int ww = wM * 2 + mt;
            ahv[mt] = *(const uint4*)&d_yh[abase + (ww * 8 + kt) * 128 + lane * 4];
            alv[mt] = *(const uint4*)&d_yl[abase + (ww * 8 + kt) * 128 + lane * 4];
        }
#pragma unroll
        for (int nt = 0; nt < 8; nt++) {
            int ntg = wN * 8 + nt;
            uint2 bhv = *(const uint2*)&su[OK_BH + (kt * 16 + ntg) * 64 + lane * 2];
            uint2 blv = *(const uint2*)&su[OK_BL + (kt * 16 + ntg) * 64 + lane * 2];
#pragma unroll
            for (int mt = 0; mt < 2; mt++) {
                mma16(acc[mt][nt], (const uint32_t*)&ahv[mt], (const uint32_t*)&bhv);
                mma16(acc[mt][nt], (const uint32_t*)&alv[mt], (const uint32_t*)&bhv);
                mma16(acc[mt][nt], (const uint32_t*)&ahv[mt], (const uint32_t*)&blv);
            }
        }
    }
    __syncthreads();

    // ---- BN, stage [pixel][oc] pitch 130 (scalar access only) ----
#pragma unroll
    for (int mt = 0; mt < 2; mt++)
#pragma unroll
    for (int nt = 0; nt < 8; nt++) {
        int col = wN * 64 + nt * 8 + 2 * t4;
        float i0 = sf[OK_BN + col],       i1 = sf[OK_BN + col + 1];
        float a0 = sf[OK_BN + 128 + col], a1 = sf[OK_BN + 128 + col + 1];
        int ra = (wM * 2 + mt) * 16 + gr, rb = ra + 8;
        sf[ra * 130 + col]     = acc[mt][nt][0] * i0 + a0;
        sf[ra * 130 + col + 1] = acc[mt][nt][1] * i1 + a1;
        sf[rb * 130 + col]     = acc[mt][nt][2] * i0 + a0;
        sf[rb * 130 + col + 1] = acc[mt][nt][3] * i1 + a1;
    }
    __syncthreads();

    // ---- transpose write + residual ----
    const float* xr = x + ((size_t)b * CC + oc0) * NPIX + pt * 128;
    float* outp = out + ((size_t)b * CC + oc0) * NPIX + pt * 128;
#pragma unroll
    for (int i = 0; i < 16; i++) {
        int e = tid + i * 256;
        int oc = e >> 5, pq = (e & 31) * 4;
        float4 xv = *(const float4*)&xr[(size_t)oc * NPIX + pq];
        float4 v = make_float4(sf[(pq + 0) * 130 + oc] + xv.x,
                               sf[(pq + 1) * 130 + oc] + xv.y,
                               sf[(pq + 2) * 130 + oc] + xv.z,
                               sf[(pq + 3) * 130 + oc] + xv.w);
        *(float4*)&outp[(size_t)oc * NPIX + pq] = v;
    }
}

// =====================================================================
extern "C" void kernel_launch(void* const* d_in, const int* in_sizes, int n_in,
                              void* d_out, int out_size)
{
    (void)in_sizes; (void)n_in; (void)out_size;
    const float* x    = (const float*)d_in[0];
    const float* g_w  = (const float*)d_in[1];
    const float* g_b  = (const float*)d_in[2];
    const float* th_w = (const float*)d_in[3];
    const float* th_b = (const float*)d_in[4];
    const float* ph_w = (const float*)d_in[5];
    const float* ph_b = (const float*)d_in[6];
    const float* W_w  = (const float*)d_in[7];
    const float* W_b  = (const float*)d_in[8];
    const float* bg   = (const float*)d_in[9];
    const float* bbta = (const float*)d_in[10];
    const float* bm   = (const float*)d_in[11];
    const float* bv   = (const float*)d_in[12];
    float* out = (float*)d_out;

    static int configured = 0;
    if (!configured) {
        cudaFuncSetAttribute(proj_mma_kernel,
            cudaFuncAttributeMaxDynamicSharedMemorySize, PJ_U32 * 4);
        cudaFuncSetAttribute(attn_bf16_kernel,
            cudaFuncAttributeMaxDynamicSharedMemorySize, AT_U32 * 4);
        cudaFuncSetAttribute(out_mma_kernel,
            cudaFuncAttributeMaxDynamicSharedMemorySize, OK_U32 * 4);
        configured = 1;
    }

    wprep_kernel<<<5, 256>>>(g_w, th_w, ph_w, W_w);
    xprep_kernel<<<dim3(32, 8), 256>>>(x);

    proj_mma_kernel<<<dim3(32, 3, 8), 256, PJ_U32 * 4>>>(g_b, th_b, ph_b);

    attn_bf16_kernel<<<dim3(32, 8), 256, AT_U32 * 4>>>();

    out_mma_kernel<<<dim3(32, 2, 8), 256, OK_U32 * 4>>>(
        x, W_b, bg, bbta, bm, bv, out);
}

// round 11
// speedup vs baseline: 2.2967x; 1.0578x over previous
#include <cuda_runtime.h>
#include <math.h>
#include <stdint.h>

#define BB   8
#define CC   256
#define ICn  128
#define NPIX 4096
#define NPm  1024

// ---------- bf16 helpers ----------
__device__ __forceinline__ uint32_t packbf(float e0, float e1) {
    uint32_t r; asm("cvt.rn.bf16x2.f32 %0, %1, %2;" : "=r"(r) : "f"(e1), "f"(e0)); return r;
}
__device__ __forceinline__ void splitpair(float v0, float v1, uint32_t &hp, uint32_t &lp) {
    hp = packbf(v0, v1);
    float h0 = __uint_as_float(hp << 16);
    float h1 = __uint_as_float(hp & 0xffff0000u);
    lp = packbf(v0 - h0, v1 - h1);
}

// mma.sync m16n8k16 bf16: C += A*B
__device__ __forceinline__ void mma16(float* c, const uint32_t* a, const uint32_t* b) {
    asm volatile("mma.sync.aligned.m16n8k16.row.col.f32.bf16.bf16.f32 "
        "{%0,%1,%2,%3}, {%4,%5,%6,%7}, {%8,%9}, {%0,%1,%2,%3};"
        : "+f"(c[0]), "+f"(c[1]), "+f"(c[2]), "+f"(c[3])
        : "r"(a[0]), "r"(a[1]), "r"(a[2]), "r"(a[3]), "r"(b[0]), "r"(b[1]));
}

// ---------- cp.async helpers ----------
__device__ __forceinline__ uint32_t smem_u32addr(const void* p) {
    uint32_t a;
    asm("{ .reg .u64 t; cvta.to.shared.u64 t, %1; cvt.u32.u64 %0, t; }" : "=r"(a) : "l"(p));
    return a;
}
__device__ __forceinline__ void cp_async16(uint32_t dst, const void* src) {
    asm volatile("cp.async.cg.shared.global [%0], [%1], 16;" :: "r"(dst), "l"(src));
}
#define CP_COMMIT() asm volatile("cp.async.commit_group;" ::: "memory")
#define CP_WAIT(n)  asm volatile("cp.async.wait_group %0;" :: "n"(n) : "memory")

// ---------- scratch: everything in frag format (hi/lo bf16x2) ----------
__device__ uint32_t d_xH [BB * 32 * 16384];      // x A-frags [b][pt][ch4][ww8 s4][128]
__device__ uint32_t d_xL [BB * 32 * 16384];
__device__ uint32_t d_wpH[3 * 16384 + 2 * 8192]; // proj W B-frags; out W at 49152
__device__ uint32_t d_wpL[3 * 16384 + 2 * 8192];
__device__ uint32_t d_thH[BB * 32 * 8192];       // theta A-frags [b][rt][ww][s][128]
__device__ uint32_t d_thL[BB * 32 * 8192];
__device__ uint32_t d_phH[BB * 16 * 4096];       // phi B-frags [b][ch][s 8][nt 8][64]
__device__ uint32_t d_phL[BB * 16 * 4096];
__device__ uint32_t d_gH [BB * 16 * 4096];       // g B-frags [b][ch][kt 4][nt 16][64]
__device__ uint32_t d_gL [BB * 16 * 4096];
__device__ uint32_t d_yh [BB * 32 * 8192];       // y A-frags (attn -> out)
__device__ uint32_t d_yl [BB * 32 * 8192];

#define OW_BASE 49152

// =====================================================================
// Kernel 0a: weight prep — convert all weights to B-frags once.
// =====================================================================
__global__ void __launch_bounds__(256) wprep_kernel(
    const float* __restrict__ g_w, const float* __restrict__ th_w,
    const float* __restrict__ ph_w, const float* __restrict__ W_w)
{
    int jt = blockIdx.x, tid = threadIdx.x;
    if (jt < 3) {
        const float* wsel = (jt == 0) ? th_w : (jt == 1) ? ph_w : g_w;
#pragma unroll
        for (int i = 0; i < 64; i++) {
            int e = tid + i * 256;
            int j = e >> 7, kp = e & 127, k0 = 2 * kp;
            float2 v = *(const float2*)&wsel[j * CC + k0];
            uint32_t h, l;
            splitpair(v.x, v.y, h, l);
            int ch = k0 >> 6, kl = k0 & 63;
            int s = kl >> 4, rg = (kl >> 3) & 1, ta = (kl >> 1) & 3;
            int nt = j >> 3, n8 = j & 7;
            int idx = jt * 16384 + ch * 4096 + (s * 16 + nt) * 64 + (n8 * 4 + ta) * 2 + rg;
            d_wpH[idx] = h;
            d_wpL[idx] = l;
        }
    } else {
        int oc0 = (jt - 3) * 128;
#pragma unroll
        for (int i = 0; i < 32; i++) {
            int e = tid + i * 256;
            int oc = e >> 6, kp = e & 63, k0 = 2 * kp;
            float2 v = *(const float2*)&W_w[(oc0 + oc) * ICn + k0];
            uint32_t h, l;
            splitpair(v.x, v.y, h, l);
            int kt = k0 >> 4, rg = (k0 >> 3) & 1, ta = (k0 >> 1) & 3;
            int nt = oc >> 3, n8 = oc & 7;
            int idx = OW_BASE + (jt - 3) * 8192 + (kt * 16 + nt) * 64 + (n8 * 4 + ta) * 2 + rg;
            d_wpH[idx] = h;
            d_wpL[idx] = l;
        }
    }
}

// =====================================================================
// Kernel 0b: x prep — convert each 128-pixel tile of x to A-frags once.
// =====================================================================
__global__ void __launch_bounds__(256) xprep_kernel(const float* __restrict__ x)
{
    __shared__ float sx[64 * 128];
    int pt = blockIdx.x, b = blockIdx.y, tid = threadIdx.x;
    size_t base = (size_t)(b * 32 + pt) * 16384;

    for (int ch = 0; ch < 4; ch++) {
#pragma unroll
        for (int i = 0; i < 8; i++) {
            int e = tid + i * 256;
            int kc = e >> 5, p4 = (e & 31) * 4;
            *(float4*)&sx[kc * 128 + p4] =
                *(const float4*)&x[((size_t)b * CC + ch * 64 + kc) * NPIX + pt * 128 + p4];
        }
        __syncthreads();
#pragma unroll
        for (int i = 0; i < 16; i++) {
            int e = tid + i * 256;
            int blk = e >> 7, off = e & 127;
            int ww = blk >> 2, s = blk & 3;
            int gg = off >> 4, ta = (off >> 2) & 3, rg = (off >> 1) & 1, hi8 = off & 1;
            int p = ww * 16 + hi8 * 8 + gg;
            int kl = s * 16 + rg * 8 + ta * 2;
            uint32_t h, l;
            splitpair(sx[kl * 128 + p], sx[(kl + 1) * 128 + p], h, l);
            d_xH[base + ch * 4096 + e] = h;
            d_xL[base + ch * 4096 + e] = l;
        }
        __syncthreads();
    }
}

// =====================================================================
// Kernel 1: projection mma + fused 2x2 maxpool (unchanged from round 10)
// =====================================================================
#define PJ_XH 0
#define PJ_XL 4096
#define PJ_WH 8192
#define PJ_WL 12288
#define PJ_BIAS 16896
#define PJ_U32 17024

__global__ void __launch_bounds__(256) proj_mma_kernel(
    const float* __restrict__ g_b, const float* __restrict__ th_b,
    const float* __restrict__ ph_b)
{
    extern __shared__ uint32_t su[];
    float* sf = (float*)su;

    int pt = blockIdx.x, jt = blockIdx.y, b = blockIdx.z;
    const float* bsel = (jt == 0) ? th_b : (jt == 1) ? ph_b : g_b;

    int tid = threadIdx.x;
    int w = tid >> 5, lane = tid & 31;
    int gr = lane >> 2, t4 = lane & 3;
    int wM = w >> 1, wN = w & 1;

    if (tid < 128) sf[PJ_BIAS + tid] = bsel[tid];

    float acc[2][8][4];
#pragma unroll
    for (int mt = 0; mt < 2; mt++)
#pragma unroll
        for (int nt = 0; nt < 8; nt++)
#pragma unroll
            for (int q = 0; q < 4; q++) acc[mt][nt][q] = 0.f;

    size_t xbase = (size_t)(b * 32 + pt) * 16384;

    for (int ch = 0; ch < 4; ch++) {
        {
            size_t xo = xbase + ch * 4096;
            int wo = jt * 16384 + ch * 4096;
#pragma unroll
            for (int i = 0; i < 4; i++) {
                int e4 = (tid + i * 256) * 4;
                *(uint4*)&su[PJ_XH + e4] = *(const uint4*)&d_xH[xo + e4];
                *(uint4*)&su[PJ_XL + e4] = *(const uint4*)&d_xL[xo + e4];
                *(uint4*)&su[PJ_WH + e4] = *(const uint4*)&d_wpH[wo + e4];
                *(uint4*)&su[PJ_WL + e4] = *(const uint4*)&d_wpL[wo + e4];
            }
        }
        __syncthreads();

#pragma unroll
        for (int s = 0; s < 4; s++) {
            uint4 ahv[2], alv[2];
#pragma unroll
            for (int mt = 0; mt < 2; mt++) {
                int ww = wM * 2 + mt;
                ahv[mt] = *(const uint4*)&su[PJ_XH + (ww * 4 + s) * 128 + lane * 4];
                alv[mt] = *(const uint4*)&su[PJ_XL + (ww * 4 + s) * 128 + lane * 4];
            }
#pragma unroll
            for (int nt = 0; nt < 8; nt++) {
                int ntg = wN * 8 + nt;
                uint2 bhv = *(const uint2*)&su[PJ_WH + (s * 16 + ntg) * 64 + lane * 2];
                uint2 blv = *(const uint2*)&su[PJ_WL + (s * 16 + ntg) * 64 + lane * 2];
#pragma unroll
                for (int mt = 0; mt < 2; mt++) {
                    mma16(acc[mt][nt], (const uint32_t*)&ahv[mt], (const uint32_t*)&bhv);
                    mma16(acc[mt][nt], (const uint32_t*)&alv[mt], (const uint32_t*)&bhv);
                    mma16(acc[mt][nt], (const uint32_t*)&ahv[mt], (const uint32_t*)&blv);
                }
            }
        }
        __syncthreads();
    }

#pragma unroll
    for (int mt = 0; mt < 2; mt++)
#pragma unroll
    for (int nt = 0; nt < 8; nt++) {
        int col = wN * 64 + nt * 8 + 2 * t4;
        float b0 = sf[PJ_BIAS + col], b1 = sf[PJ_BIAS + col + 1];
        int ra = (wM * 2 + mt) * 16 + gr, rb = ra + 8;
        sf[ra * 132 + col]     = acc[mt][nt][0] + b0;
        sf[ra * 132 + col + 1] = acc[mt][nt][1] + b1;
        sf[rb * 132 + col]     = acc[mt][nt][2] + b0;
        sf[rb * 132 + col + 1] = acc[mt][nt][3] + b1;
    }
    __syncthreads();

    if (jt == 0) {
        size_t base = (size_t)(b * 32 + pt) * 8192;
#pragma unroll
        for (int i = 0; i < 32; i++) {
            int e = tid + i * 256;
            int blk = e >> 7, off = e & 127;
            int ww = blk >> 3, s = blk & 7;
            int gg = off >> 4, ta = (off >> 2) & 3, rg = (off >> 1) & 1, hi8 = off & 1;
            int p = ww * 16 + hi8 * 8 + gg;
            int ic = s * 16 + rg * 8 + ta * 2;
            uint32_t h, l;
            splitpair(sf[p * 132 + ic], sf[p * 132 + ic + 1], h, l);
            d_thH[base + e] = h;
            d_thL[base + e] = l;
        }
    } else if (jt == 1) {
        int ch = pt >> 1, nthi = (pt & 1) * 4;
        size_t base = (size_t)(b * 16 + ch) * 4096;
#pragma unroll
        for (int i = 0; i < 8; i++) {
            int e = tid + i * 256;
            int s = e >> 8, r = e & 255;
            int ntl = r >> 6, woff = r & 63;
            int n8 = woff >> 3, ta = (woff >> 1) & 3, rg = woff & 1;
            int mc = ntl * 8 + n8;
            int ic = s * 16 + rg * 8 + ta * 2;
            int r0 = 2 * mc, r1 = 2 * mc + 1, r2 = 64 + 2 * mc, r3 = 65 + 2 * mc;
            float v0 = fmaxf(fmaxf(sf[r0 * 132 + ic],     sf[r1 * 132 + ic]),
                             fmaxf(sf[r2 * 132 + ic],     sf[r3 * 132 + ic]));
            float v1 = fmaxf(fmaxf(sf[r0 * 132 + ic + 1], sf[r1 * 132 + ic + 1]),
                             fmaxf(sf[r2 * 132 + ic + 1], sf[r3 * 132 + ic + 1]));
            uint32_t h, l;
            splitpair(v0, v1, h, l);
            size_t idx = base + ((size_t)s * 8 + nthi + ntl) * 64 + woff;
            d_phH[idx] = h;
            d_phL[idx] = l;
        }
    } else {
        int ch = pt >> 1, kthi = (pt & 1) * 2;
        size_t base = (size_t)(b * 16 + ch) * 4096;
#pragma unroll
        for (int i = 0; i < 8; i++) {
            int e = tid + i * 256;
            int ktl = e >> 10, r = e & 1023;
            int nt = r >> 6, woff = r & 63;
            int n8 = woff >> 3, ta = (woff >> 1) & 3, rg = woff & 1;
            int m16 = rg * 8 + ta * 2;
            int mc = ktl * 16 + m16;
            int ic = nt * 8 + n8;
            int ra = 2 * mc, rb = 2 * mc + 1, rc = 64 + 2 * mc, rd = 65 + 2 * mc;
            float v0 = fmaxf(fmaxf(sf[ra * 132 + ic], sf[rb * 132 + ic]),
                             fmaxf(sf[rc * 132 + ic], sf[rd * 132 + ic]));
            ra += 2; rb += 2; rc += 2; rd += 2;
            float v1 = fmaxf(fmaxf(sf[ra * 132 + ic], sf[rb * 132 + ic]),
                             fmaxf(sf[rc * 132 + ic], sf[rd * 132 + ic]));
            uint32_t h, l;
            splitpair(v0, v1, h, l);
            size_t idx = base + ((size_t)(kthi + ktl) * 16 + nt) * 64 + woff;
            d_gH[idx] = h;
            d_gL[idx] = l;
        }
    }
}

// =====================================================================
// Kernel 2: bf16 attention, cp.async double-buffered phi/g, theta in regs.
// smem u32: buf0 [0,16384): PBH[0,4096) PBL[4096) GBH[8192) GBL[12288)
//           buf1 [16384,32768)
// =====================================================================
#define AT_U32 32768

__global__ void __launch_bounds__(256, 1) attn_bf16_kernel()
{
    extern __shared__ uint32_t su[];
    uint32_t sb = smem_u32addr(su);
    int tid = threadIdx.x;
    int w = tid >> 5, lane = tid & 31;
    int rt = blockIdx.x, b = blockIdx.y;

    // ---- issue chunk 0 copy (cp.async) ----
    {
        size_t base = (size_t)(b * 16) * 4096;
#pragma unroll
        for (int i = 0; i < 4; i++) {
            int e4 = (tid + i * 256) * 4;
            cp_async16(sb + (e4) * 4,          &d_phH[base + e4]);
            cp_async16(sb + (4096 + e4) * 4,   &d_phL[base + e4]);
            cp_async16(sb + (8192 + e4) * 4,   &d_gH[base + e4]);
            cp_async16(sb + (12288 + e4) * 4,  &d_gL[base + e4]);
        }
        CP_COMMIT();
    }

    // ---- theta A-frags -> registers (coalesced gmem loads) ----
    uint4 thh[8], thl[8];
    {
        size_t tb = (size_t)(b * 32 + rt) * 8192;
#pragma unroll
        for (int s = 0; s < 8; s++) {
            thh[s] = *(const uint4*)&d_thH[tb + (w * 8 + s) * 128 + lane * 4];
            thl[s] = *(const uint4*)&d_thL[tb + (w * 8 + s) * 128 + lane * 4];
        }
    }

    float yacc[16][4];
#pragma unroll
    for (int nt = 0; nt < 16; nt++)
#pragma unroll
        for (int q = 0; q < 4; q++) yacc[nt][q] = 0.f;
    float ls0 = 0.f, ls1 = 0.f;

    for (int ch = 0; ch < 16; ch++) {
        int off = (ch & 1) * 16384;

        // prefetch next chunk into other buffer, then wait for current
        if (ch + 1 < 16) {
            int noff = ((ch + 1) & 1) * 16384;
            size_t base = (size_t)(b * 16 + ch + 1) * 4096;
#pragma unroll
            for (int i = 0; i < 4; i++) {
                int e4 = (tid + i * 256) * 4;
                cp_async16(sb + (noff + e4) * 4,         &d_phH[base + e4]);
                cp_async16(sb + (noff + 4096 + e4) * 4,  &d_phL[base + e4]);
                cp_async16(sb + (noff + 8192 + e4) * 4,  &d_gH[base + e4]);
                cp_async16(sb + (noff + 12288 + e4) * 4, &d_gL[base + e4]);
            }
            CP_COMMIT();
            CP_WAIT(1);
        } else {
            CP_WAIT(0);
        }
        __syncthreads();

        // ---- S = theta . phi (3-term bf16 split), theta from regs ----
        float sacc[8][4];
#pragma unroll
        for (int nt = 0; nt < 8; nt++)
#pragma unroll
            for (int q = 0; q < 4; q++) sacc[nt][q] = 0.f;

#pragma unroll
        for (int s = 0; s < 8; s++) {
#pragma unroll
            for (int nt = 0; nt < 8; nt++) {
                uint2 bhv = *(const uint2*)&su[off + (s * 8 + nt) * 64 + lane * 2];
                uint2 blv = *(const uint2*)&su[off + 4096 + (s * 8 + nt) * 64 + lane * 2];
                mma16(sacc[nt], (const uint32_t*)&thh[s], (const uint32_t*)&bhv);
                mma16(sacc[nt], (const uint32_t*)&thl[s], (const uint32_t*)&bhv);
                mma16(sacc[nt], (const uint32_t*)&thh[s], (const uint32_t*)&blv);
            }
        }

        // ---- P = exp(S - 40): in-register, pack straight to A-frags ----
        uint32_t pa[16], pl[16];
#pragma unroll
        for (int nt = 0; nt < 8; nt++) {
            float p0 = __expf(sacc[nt][0] - 40.f);
            float p1 = __expf(sacc[nt][1] - 40.f);
            float p2 = __expf(sacc[nt][2] - 40.f);
            float p3 = __expf(sacc[nt][3] - 40.f);
            ls0 += p0 + p1;
            ls1 += p2 + p3;
            splitpair(p0, p1, pa[nt * 2],     pl[nt * 2]);
            splitpair(p2, p3, pa[nt * 2 + 1], pl[nt * 2 + 1]);
        }

        // ---- Y += P @ g (3-term bf16 split), P from registers ----
#pragma unroll
        for (int kt = 0; kt < 4; kt++) {
            uint32_t ah[4] = { pa[4 * kt], pa[4 * kt + 1], pa[4 * kt + 2], pa[4 * kt + 3] };
            uint32_t al[4] = { pl[4 * kt], pl[4 * kt + 1], pl[4 * kt + 2], pl[4 * kt + 3] };
#pragma unroll
            for (int nt = 0; nt < 16; nt++) {
                uint2 ghv = *(const uint2*)&su[off + 8192 + (kt * 16 + nt) * 64 + lane * 2];
                uint2 glv = *(const uint2*)&su[off + 12288 + (kt * 16 + nt) * 64 + lane * 2];
                mma16(yacc[nt], ah, (const uint32_t*)&ghv);
                mma16(yacc[nt], al, (const uint32_t*)&ghv);
                mma16(yacc[nt], ah, (const uint32_t*)&glv);
            }
        }
        __syncthreads();   // all warps done with this buffer before ch+2 overwrites it
    }

    // ---- epilogue: normalize, split hi/lo, store y as A-frags ----
    ls0 += __shfl_xor_sync(0xffffffffu, ls0, 1);
    ls0 += __shfl_xor_sync(0xffffffffu, ls0, 2);
    ls1 += __shfl_xor_sync(0xffffffffu, ls1, 1);
    ls1 += __shfl_xor_sync(0xffffffffu, ls1, 2);
    float inv0 = 1.f / ls0, inv1 = 1.f / ls1;

    size_t base = ((size_t)(b * 32 + rt) * 8 + w) * 1024;
#pragma unroll
    for (int kt = 0; kt < 8; kt++) {
        uint32_t h0, l0, h1, l1, h2, l2, h3, l3;
        splitpair(yacc[2 * kt][0] * inv0, yacc[2 * kt][1] * inv0, h0, l0);
        splitpair(yacc[2 * kt][2] * inv1, yacc[2 * kt][3] * inv1, h1, l1);
        splitpair(yacc[2 * kt + 1][0] * inv0, yacc[2 * kt + 1][1] * inv0, h2, l2);
        splitpair(yacc[2 * kt + 1][2] * inv1, yacc[2 * kt + 1][3] * inv1, h3, l3);
        *(uint4*)&d_yh[base + kt * 128 + lane * 4] = make_uint4(h0, h1, h2, h3);
        *(uint4*)&d_yl[base + kt * 128 + lane * 4] = make_uint4(l0, l1, l2, l3);
    }
}

// =====================================================================
// Kernel 3: output conv mma + BN + residual (unchanged from round 10)
// =====================================================================
#define OK_BH 0
#define OK_BL 8192
#define OK_BN 16640
#define OK_U32 16896

__global__ void __launch_bounds__(256) out_mma_kernel(
    const float* __restrict__ x,
    const float* __restrict__ Wb,    const float* __restrict__ gamma,
    const float* __restrict__ beta,  const float* __restrict__ bmean,
    const float* __restrict__ bvar,  float* __restrict__ out)
{
    extern __shared__ uint32_t su[];
    float* sf = (float*)su;

    int pt = blockIdx.x, jt = blockIdx.y, b = blockIdx.z;
    int oc0 = jt * 128;
    int tid = threadIdx.x;
    int w = tid >> 5, lane = tid & 31;
    int gr = lane >> 2, t4 = lane & 3;
    int wM = w >> 1, wN = w & 1;

    if (tid < 128) {
        int oc = oc0 + tid;
        float inv = gamma[oc] * rsqrtf(bvar[oc] + 1e-5f);
        sf[OK_BN + tid] = inv;
        sf[OK_BN + 128 + tid] = (Wb[oc] - bmean[oc]) * inv + beta[oc];
    }

    {
        int wo = OW_BASE + jt * 8192;
#pragma unroll
        for (int i = 0; i < 8; i++) {
            int e4 = (tid + i * 256) * 4;
            *(uint4*)&su[OK_BH + e4] = *(const uint4*)&d_wpH[wo + e4];
            *(uint4*)&su[OK_BL + e4] = *(const uint4*)&d_wpL[wo + e4];
        }
    }
    __syncthreads();

    float acc[2][8][4];
#pragma unroll
    for (int mt = 0; mt < 2; mt++)
#pragma unroll
        for (int nt = 0; nt < 8; nt++)
#pragma unroll
            for (int q = 0; q < 4; q++) acc[mt][nt][q] = 0.f;

    size_t abase = (size_t)(b * 32 + pt) * 8192;
#pragma unroll
    for (int kt = 0; kt < 8; kt++) {
        uint4 ahv[2], alv[2];
#pragma unroll
        for (int mt = 0; mt < 2; mt++) {
            int ww = wM * 2 + mt;
            ahv[mt] = *(const uint4*)&d_yh[abase + (ww * 8 + kt) * 128 + lane * 4];
            alv[mt] = *(const uint4*)&d_yl[abase + (ww * 8 + kt) * 128 + lane * 4];
        }
#pragma unroll
        for (int nt = 0; nt < 8; nt++) {
            int ntg = wN * 8 + nt;
            uint2 bhv = *(const uint2*)&su[OK_BH + (kt * 16 + ntg) * 64 + lane * 2];
            uint2 blv = *(const uint2*)&su[OK_BL + (kt * 16 + ntg) * 64 + lane * 2];
#pragma unroll
            for (int mt = 0; mt < 2; mt++) {
                mma16(acc[mt][nt], (const uint32_t*)&ahv[mt], (const uint32_t*)&bhv);
                mma16(acc[mt][nt], (const uint32_t*)&alv[mt], (const uint32_t*)&bhv);
                mma16(acc[mt][nt], (const uint32_t*)&ahv[mt], (const uint32_t*)&blv);
            }
        }
    }
    __syncthreads();

#pragma unroll
    for (int mt = 0; mt < 2; mt++)
#pragma unroll
    for (int nt = 0; nt < 8; nt++) {
        int col = wN * 64 + nt * 8 + 2 * t4;
        float i0 = sf[OK_BN + col],       i1 = sf[OK_BN + col + 1];
        float a0 = sf[OK_BN + 128 + col], a1 = sf[OK_BN + 128 + col + 1];
        int ra = (wM * 2 + mt) * 16 + gr, rb = ra + 8;
        sf[ra * 130 + col]     = acc[mt][nt][0] * i0 + a0;
        sf[ra * 130 + col + 1] = acc[mt][nt][1] * i1 + a1;
        sf[rb * 130 + col]     = acc[mt][nt][2] * i0 + a0;
        sf[rb * 130 + col + 1] = acc[mt][nt][3] * i1 + a1;
    }
    __syncthreads();

    const float* xr = x + ((size_t)b * CC + oc0) * NPIX + pt * 128;
    float* outp = out + ((size_t)b * CC + oc0) * NPIX + pt * 128;
#pragma unroll
    for (int i = 0; i < 16; i++) {
        int e = tid + i * 256;
        int oc = e >> 5, pq = (e & 31) * 4;
        float4 xv = *(const float4*)&xr[(size_t)oc * NPIX + pq];
        float4 v = make_float4(sf[(pq + 0) * 130 + oc] + xv.x,
                               sf[(pq + 1) * 130 + oc] + xv.y,
                               sf[(pq + 2) * 130 + oc] + xv.z,
                               sf[(pq + 3) * 130 + oc] + xv.w);
        *(float4*)&outp[(size_t)oc * NPIX + pq] = v;
    }
}

// =====================================================================
extern "C" void kernel_launch(void* const* d_in, const int* in_sizes, int n_in,
                              void* d_out, int out_size)
{
    (void)in_sizes; (void)n_in; (void)out_size;
    const float* x    = (const float*)d_in[0];
    const float* g_w  = (const float*)d_in[1];
    const float* g_b  = (const float*)d_in[2];
    const float* th_w = (const float*)d_in[3];
    const float* th_b = (const float*)d_in[4];
    const float* ph_w = (const float*)d_in[5];
    const float* ph_b = (const float*)d_in[6];
    const float* W_w  = (const float*)d_in[7];
    const float* W_b  = (const float*)d_in[8];
    const float* bg   = (const float*)d_in[9];
    const float* bbta = (const float*)d_in[10];
    const float* bm   = (const float*)d_in[11];
    const float* bv   = (const float*)d_in[12];
    float* out = (float*)d_out;

    static int configured = 0;
    if (!configured) {
        cudaFuncSetAttribute(proj_mma_kernel,
            cudaFuncAttributeMaxDynamicSharedMemorySize, PJ_U32 * 4);
        cudaFuncSetAttribute(attn_bf16_kernel,
            cudaFuncAttributeMaxDynamicSharedMemorySize, AT_U32 * 4);
        cudaFuncSetAttribute(out_mma_kernel,
            cudaFuncAttributeMaxDynamicSharedMemorySize, OK_U32 * 4);
        configured = 1;
    }

    wprep_kernel<<<5, 256>>>(g_w, th_w, ph_w, W_w);
    xprep_kernel<<<dim3(32, 8), 256>>>(x);

    proj_mma_kernel<<<dim3(32, 3, 8), 256, PJ_U32 * 4>>>(g_b, th_b, ph_b);

    attn_bf16_kernel<<<dim3(32, 8), 256, AT_U32 * 4>>>();

    out_mma_kernel<<<dim3(32, 2, 8), 256, OK_U32 * 4>>>(
        x, W_b, bg, bbta, bm, bv, out);
}

// round 12
// speedup vs baseline: 2.3764x; 1.0347x over previous
#include <cuda_runtime.h>
#include <math.h>
#include <stdint.h>

#define BB   8
#define CC   256
#define ICn  128
#define NPIX 4096
#define NPm  1024

// ---------- bf16 helpers ----------
__device__ __forceinline__ uint32_t packbf(float e0, float e1) {
    uint32_t r; asm("cvt.rn.bf16x2.f32 %0, %1, %2;" : "=r"(r) : "f"(e1), "f"(e0)); return r;
}
__device__ __forceinline__ void splitpair(float v0, float v1, uint32_t &hp, uint32_t &lp) {
    hp = packbf(v0, v1);
    float h0 = __uint_as_float(hp << 16);
    float h1 = __uint_as_float(hp & 0xffff0000u);
    lp = packbf(v0 - h0, v1 - h1);
}

// mma.sync m16n8k16 bf16: C += A*B
__device__ __forceinline__ void mma16(float* c, const uint32_t* a, const uint32_t* b) {
    asm volatile("mma.sync.aligned.m16n8k16.row.col.f32.bf16.bf16.f32 "
        "{%0,%1,%2,%3}, {%4,%5,%6,%7}, {%8,%9}, {%0,%1,%2,%3};"
        : "+f"(c[0]), "+f"(c[1]), "+f"(c[2]), "+f"(c[3])
        : "r"(a[0]), "r"(a[1]), "r"(a[2]), "r"(a[3]), "r"(b[0]), "r"(b[1]));
}

// ---------- cp.async helpers ----------
__device__ __forceinline__ uint32_t smem_u32addr(const void* p) {
    uint32_t a;
    asm("{ .reg .u64 t; cvta.to.shared.u64 t, %1; cvt.u32.u64 %0, t; }" : "=r"(a) : "l"(p));
    return a;
}
__device__ __forceinline__ void cp_async16(uint32_t dst, const void* src) {
    asm volatile("cp.async.cg.shared.global [%0], [%1], 16;" :: "r"(dst), "l"(src));
}
#define CP_COMMIT() asm volatile("cp.async.commit_group;" ::: "memory")
#define CP_WAIT(n)  asm volatile("cp.async.wait_group %0;" :: "n"(n) : "memory")

// ---------- scratch: everything in frag format (hi/lo bf16x2) ----------
__device__ uint32_t d_xH [BB * 32 * 16384];      // x A-frags [b][pt][ch4][ww8 s4][128]
__device__ uint32_t d_xL [BB * 32 * 16384];
__device__ uint32_t d_wpH[3 * 16384 + 2 * 8192]; // proj W B-frags; out W at 49152
__device__ uint32_t d_wpL[3 * 16384 + 2 * 8192];
__device__ uint32_t d_thH[BB * 32 * 8192];       // theta A-frags [b][rt][ww][s][128]
__device__ uint32_t d_thL[BB * 32 * 8192];
__device__ uint32_t d_phH[BB * 16 * 4096];       // phi B-frags [b][ch][s 8][nt 8][64]
__device__ uint32_t d_phL[BB * 16 * 4096];
__device__ uint32_t d_gH [BB * 16 * 4096];       // g B-frags [b][ch][kt 4][nt 16][64]
__device__ uint32_t d_gL [BB * 16 * 4096];
__device__ uint32_t d_yh [BB * 32 * 8192];       // y A-frags (attn -> out)
__device__ uint32_t d_yl [BB * 32 * 8192];

#define OW_BASE 49152

// =====================================================================
// Kernel 0a: weight prep — convert all weights to B-frags once.
// =====================================================================
__global__ void __launch_bounds__(256) wprep_kernel(
    const float* __restrict__ g_w, const float* __restrict__ th_w,
    const float* __restrict__ ph_w, const float* __restrict__ W_w)
{
    int jt = blockIdx.x, tid = threadIdx.x;
    if (jt < 3) {
        const float* wsel = (jt == 0) ? th_w : (jt == 1) ? ph_w : g_w;
#pragma unroll
        for (int i = 0; i < 64; i++) {
            int e = tid + i * 256;
            int j = e >> 7, kp = e & 127, k0 = 2 * kp;
            float2 v = *(const float2*)&wsel[j * CC + k0];
            uint32_t h, l;
            splitpair(v.x, v.y, h, l);
            int ch = k0 >> 6, kl = k0 & 63;
            int s = kl >> 4, rg = (kl >> 3) & 1, ta = (kl >> 1) & 3;
            int nt = j >> 3, n8 = j & 7;
            int idx = jt * 16384 + ch * 4096 + (s * 16 + nt) * 64 + (n8 * 4 + ta) * 2 + rg;
            d_wpH[idx] = h;
            d_wpL[idx] = l;
        }
    } else {
        int oc0 = (jt - 3) * 128;
#pragma unroll
        for (int i = 0; i < 32; i++) {
            int e = tid + i * 256;
            int oc = e >> 6, kp = e & 63, k0 = 2 * kp;
            float2 v = *(const float2*)&W_w[(oc0 + oc) * ICn + k0];
            uint32_t h, l;
            splitpair(v.x, v.y, h, l);
            int kt = k0 >> 4, rg = (k0 >> 3) & 1, ta = (k0 >> 1) & 3;
            int nt = oc >> 3, n8 = oc & 7;
            int idx = OW_BASE + (jt - 3) * 8192 + (kt * 16 + nt) * 64 + (n8 * 4 + ta) * 2 + rg;
            d_wpH[idx] = h;
            d_wpL[idx] = l;
        }
    }
}

// =====================================================================
// Kernel 0b: x prep — convert each 128-pixel tile of x to A-frags once.
// =====================================================================
__global__ void __launch_bounds__(256) xprep_kernel(const float* __restrict__ x)
{
    __shared__ float sx[64 * 128];
    int pt = blockIdx.x, b = blockIdx.y, tid = threadIdx.x;
    size_t base = (size_t)(b * 32 + pt) * 16384;

    for (int ch = 0; ch < 4; ch++) {
#pragma unroll
        for (int i = 0; i < 8; i++) {
            int e = tid + i * 256;
            int kc = e >> 5, p4 = (e & 31) * 4;
            *(float4*)&sx[kc * 128 + p4] =
                *(const float4*)&x[((size_t)b * CC + ch * 64 + kc) * NPIX + pt * 128 + p4];
        }
        __syncthreads();
#pragma unroll
        for (int i = 0; i < 16; i++) {
            int e = tid + i * 256;
            int blk = e >> 7, off = e & 127;
            int ww = blk >> 2, s = blk & 3;
            int gg = off >> 4, ta = (off >> 2) & 3, rg = (off >> 1) & 1, hi8 = off & 1;
            int p = ww * 16 + hi8 * 8 + gg;
            int kl = s * 16 + rg * 8 + ta * 2;
            uint32_t h, l;
            splitpair(sx[kl * 128 + p], sx[(kl + 1) * 128 + p], h, l);
            d_xH[base + ch * 4096 + e] = h;
            d_xL[base + ch * 4096 + e] = l;
        }
        __syncthreads();
    }
}

// =====================================================================
// Kernel 1: projection mma + fused 2x2 maxpool, cp.async double-buffered.
// smem u32: buf0 [0,16384): XH[0) XL[4096) WH[8192) WL[12288)
//           buf1 [16384,32768); BIAS f32 [32768,32896)
// stage f32 [128][132] overlays [0,16896)
// =====================================================================
#define PJ_BUF 16384
#define PJ_BIAS 32768
#define PJ_U32 32896

__global__ void __launch_bounds__(256) proj_mma_kernel(
    const float* __restrict__ g_b, const float* __restrict__ th_b,
    const float* __restrict__ ph_b)
{
    extern __shared__ uint32_t su[];
    float* sf = (float*)su;
    uint32_t sb = smem_u32addr(su);

    int pt = blockIdx.x, jt = blockIdx.y, b = blockIdx.z;
    const float* bsel = (jt == 0) ? th_b : (jt == 1) ? ph_b : g_b;

    int tid = threadIdx.x;
    int w = tid >> 5, lane = tid & 31;
    int gr = lane >> 2, t4 = lane & 3;
    int wM = w >> 1, wN = w & 1;

    if (tid < 128) sf[PJ_BIAS + tid] = bsel[tid];

    size_t xbase = (size_t)(b * 32 + pt) * 16384;
    int wbase = jt * 16384;

    // ---- prefetch chunk 0 ----
    {
#pragma unroll
        for (int i = 0; i < 4; i++) {
            int e4 = (tid + i * 256) * 4;
            cp_async16(sb + (e4) * 4,          &d_xH[xbase + e4]);
            cp_async16(sb + (4096 + e4) * 4,   &d_xL[xbase + e4]);
            cp_async16(sb + (8192 + e4) * 4,   &d_wpH[wbase + e4]);
            cp_async16(sb + (12288 + e4) * 4,  &d_wpL[wbase + e4]);
        }
        CP_COMMIT();
    }

    float acc[2][8][4];
#pragma unroll
    for (int mt = 0; mt < 2; mt++)
#pragma unroll
        for (int nt = 0; nt < 8; nt++)
#pragma unroll
            for (int q = 0; q < 4; q++) acc[mt][nt][q] = 0.f;

    for (int ch = 0; ch < 4; ch++) {
        int off = (ch & 1) * PJ_BUF;

        if (ch + 1 < 4) {
            int noff = ((ch + 1) & 1) * PJ_BUF;
            size_t xo = xbase + (ch + 1) * 4096;
            int wo = wbase + (ch + 1) * 4096;
#pragma unroll
            for (int i = 0; i < 4; i++) {
                int e4 = (tid + i * 256) * 4;
                cp_async16(sb + (noff + e4) * 4,          &d_xH[xo + e4]);
                cp_async16(sb + (noff + 4096 + e4) * 4,   &d_xL[xo + e4]);
                cp_async16(sb + (noff + 8192 + e4) * 4,   &d_wpH[wo + e4]);
                cp_async16(sb + (noff + 12288 + e4) * 4,  &d_wpL[wo + e4]);
            }
            CP_COMMIT();
            CP_WAIT(1);
        } else {
            CP_WAIT(0);
        }
        __syncthreads();

#pragma unroll
        for (int s = 0; s < 4; s++) {
            uint4 ahv[2], alv[2];
#pragma unroll
            for (int mt = 0; mt < 2; mt++) {
                int ww = wM * 2 + mt;
                ahv[mt] = *(const uint4*)&su[off + (ww * 4 + s) * 128 + lane * 4];
                alv[mt] = *(const uint4*)&su[off + 4096 + (ww * 4 + s) * 128 + lane * 4];
            }
#pragma unroll
            for (int nt = 0; nt < 8; nt++) {
                int ntg = wN * 8 + nt;
                uint2 bhv = *(const uint2*)&su[off + 8192 + (s * 16 + ntg) * 64 + lane * 2];
                uint2 blv = *(const uint2*)&su[off + 12288 + (s * 16 + ntg) * 64 + lane * 2];
#pragma unroll
                for (int mt = 0; mt < 2; mt++) {
                    mma16(acc[mt][nt], (const uint32_t*)&ahv[mt], (const uint32_t*)&bhv);
                    mma16(acc[mt][nt], (const uint32_t*)&alv[mt], (const uint32_t*)&bhv);
                    mma16(acc[mt][nt], (const uint32_t*)&ahv[mt], (const uint32_t*)&blv);
                }
            }
        }
        __syncthreads();
    }

    // ---- +bias, stage [pixel 128][out 128] pitch 132 ----
#pragma unroll
    for (int mt = 0; mt < 2; mt++)
#pragma unroll
    for (int nt = 0; nt < 8; nt++) {
        int col = wN * 64 + nt * 8 + 2 * t4;
        float b0 = sf[PJ_BIAS + col], b1 = sf[PJ_BIAS + col + 1];
        int ra = (wM * 2 + mt) * 16 + gr, rb = ra + 8;
        sf[ra * 132 + col]     = acc[mt][nt][0] + b0;
        sf[ra * 132 + col + 1] = acc[mt][nt][1] + b1;
        sf[rb * 132 + col]     = acc[mt][nt][2] + b0;
        sf[rb * 132 + col + 1] = acc[mt][nt][3] + b1;
    }
    __syncthreads();

    if (jt == 0) {
        size_t base = (size_t)(b * 32 + pt) * 8192;
#pragma unroll
        for (int i = 0; i < 32; i++) {
            int e = tid + i * 256;
            int blk = e >> 7, off = e & 127;
            int ww = blk >> 3, s = blk & 7;
            int gg = off >> 4, ta = (off >> 2) & 3, rg = (off >> 1) & 1, hi8 = off & 1;
            int p = ww * 16 + hi8 * 8 + gg;
            int ic = s * 16 + rg * 8 + ta * 2;
            uint32_t h, l;
            splitpair(sf[p * 132 + ic], sf[p * 132 + ic + 1], h, l);
            d_thH[base + e] = h;
            d_thL[base + e] = l;
        }
    } else if (jt == 1) {
        int ch = pt >> 1, nthi = (pt & 1) * 4;
        size_t base = (size_t)(b * 16 + ch) * 4096;
#pragma unroll
        for (int i = 0; i < 8; i++) {
            int e = tid + i * 256;
            int s = e >> 8, r = e & 255;
            int ntl = r >> 6, woff = r & 63;
            int n8 = woff >> 3, ta = (woff >> 1) & 3, rg = woff & 1;
            int mc = ntl * 8 + n8;
            int ic = s * 16 + rg * 8 + ta * 2;
            int r0 = 2 * mc, r1 = 2 * mc + 1, r2 = 64 + 2 * mc, r3 = 65 + 2 * mc;
            float v0 = fmaxf(fmaxf(sf[r0 * 132 + ic],     sf[r1 * 132 + ic]),
                             fmaxf(sf[r2 * 132 + ic],     sf[r3 * 132 + ic]));
            float v1 = fmaxf(fmaxf(sf[r0 * 132 + ic + 1], sf[r1 * 132 + ic + 1]),
                             fmaxf(sf[r2 * 132 + ic + 1], sf[r3 * 132 + ic + 1]));
            uint32_t h, l;
            splitpair(v0, v1, h, l);
            size_t idx = base + ((size_t)s * 8 + nthi + ntl) * 64 + woff;
            d_phH[idx] = h;
            d_phL[idx] = l;
        }
    } else {
        int ch = pt >> 1, kthi = (pt & 1) * 2;
        size_t base = (size_t)(b * 16 + ch) * 4096;
#pragma unroll
        for (int i = 0; i < 8; i++) {
            int e = tid + i * 256;
            int ktl = e >> 10, r = e & 1023;
            int nt = r >> 6, woff = r & 63;
            int n8 = woff >> 3, ta = (woff >> 1) & 3, rg = woff & 1;
            int m16 = rg * 8 + ta * 2;
            int mc = ktl * 16 + m16;
            int ic = nt * 8 + n8;
            int ra = 2 * mc, rb = 2 * mc + 1, rc = 64 + 2 * mc, rd = 65 + 2 * mc;
            float v0 = fmaxf(fmaxf(sf[ra * 132 + ic], sf[rb * 132 + ic]),
                             fmaxf(sf[rc * 132 + ic], sf[rd * 132 + ic]));
            ra += 2; rb += 2; rc += 2; rd += 2;
            float v1 = fmaxf(fmaxf(sf[ra * 132 + ic], sf[rb * 132 + ic]),
                             fmaxf(sf[rc * 132 + ic], sf[rd * 132 + ic]));
            uint32_t h, l;
            splitpair(v0, v1, h, l);
            size_t idx = base + ((size_t)(kthi + ktl) * 16 + nt) * 64 + woff;
            d_gH[idx] = h;
            d_gL[idx] = l;
        }
    }
}

// =====================================================================
// Kernel 2: bf16 attention, cp.async double-buffered, theta in regs,
// exp interleaved with Y-mma (per-kt) to hide MUFU latency.
// =====================================================================
#define AT_U32 32768

__global__ void __launch_bounds__(256, 1) attn_bf16_kernel()
{
    extern __shared__ uint32_t su[];
    uint32_t sb = smem_u32addr(su);
    int tid = threadIdx.x;
    int w = tid >> 5, lane = tid & 31;
    int rt = blockIdx.x, b = blockIdx.y;

    // ---- issue chunk 0 copy (cp.async) ----
    {
        size_t base = (size_t)(b * 16) * 4096;
#pragma unroll
        for (int i = 0; i < 4; i++) {
            int e4 = (tid + i * 256) * 4;
            cp_async16(sb + (e4) * 4,          &d_phH[base + e4]);
            cp_async16(sb + (4096 + e4) * 4,   &d_phL[base + e4]);
            cp_async16(sb + (8192 + e4) * 4,   &d_gH[base + e4]);
            cp_async16(sb + (12288 + e4) * 4,  &d_gL[base + e4]);
        }
        CP_COMMIT();
    }

    // ---- theta A-frags -> registers ----
    uint4 thh[8], thl[8];
    {
        size_t tb = (size_t)(b * 32 + rt) * 8192;
#pragma unroll
        for (int s = 0; s < 8; s++) {
            thh[s] = *(const uint4*)&d_thH[tb + (w * 8 + s) * 128 + lane * 4];
            thl[s] = *(const uint4*)&d_thL[tb + (w * 8 + s) * 128 + lane * 4];
        }
    }

    float yacc[16][4];
#pragma unroll
    for (int nt = 0; nt < 16; nt++)
#pragma unroll
        for (int q = 0; q < 4; q++) yacc[nt][q] = 0.f;
    float ls0 = 0.f, ls1 = 0.f;

    for (int ch = 0; ch < 16; ch++) {
        int off = (ch & 1) * 16384;

        if (ch + 1 < 16) {
            int noff = ((ch + 1) & 1) * 16384;
            size_t base = (size_t)(b * 16 + ch + 1) * 4096;
#pragma unroll
            for (int i = 0; i < 4; i++) {
                int e4 = (tid + i * 256) * 4;
                cp_async16(sb + (noff + e4) * 4,         &d_phH[base + e4]);
                cp_async16(sb + (noff + 4096 + e4) * 4,  &d_phL[base + e4]);
                cp_async16(sb + (noff + 8192 + e4) * 4,  &d_gH[base + e4]);
                cp_async16(sb + (noff + 12288 + e4) * 4, &d_gL[base + e4]);
            }
            CP_COMMIT();
            CP_WAIT(1);
        } else {
            CP_WAIT(0);
        }
        __syncthreads();

        // ---- S = theta . phi (3-term bf16 split), theta from regs ----
        float sacc[8][4];
#pragma unroll
        for (int nt = 0; nt < 8; nt++)
#pragma unroll
            for (int q = 0; q < 4; q++) sacc[nt][q] = 0.f;

#pragma unroll
        for (int s = 0; s < 8; s++) {
#pragma unroll
            for (int nt = 0; nt < 8; nt++) {
                uint2 bhv = *(const uint2*)&su[off + (s * 8 + nt) * 64 + lane * 2];
                uint2 blv = *(const uint2*)&su[off + 4096 + (s * 8 + nt) * 64 + lane * 2];
                mma16(sacc[nt], (const uint32_t*)&thh[s], (const uint32_t*)&bhv);
                mma16(sacc[nt], (const uint32_t*)&thl[s], (const uint32_t*)&bhv);
                mma16(sacc[nt], (const uint32_t*)&thh[s], (const uint32_t*)&blv);
            }
        }

        // ---- interleaved: per kt, exp two nt groups then Y-mma for kt ----
#pragma unroll
        for (int kt = 0; kt < 4; kt++) {
            uint32_t ah[4], al[4];
#pragma unroll
            for (int j = 0; j < 2; j++) {
                int nt = 2 * kt + j;
                float p0 = __expf(sacc[nt][0] - 40.f);
                float p1 = __expf(sacc[nt][1] - 40.f);
                float p2 = __expf(sacc[nt][2] - 40.f);
                float p3 = __expf(sacc[nt][3] - 40.f);
                ls0 += p0 + p1;
                ls1 += p2 + p3;
                splitpair(p0, p1, ah[2 * j],     al[2 * j]);
                splitpair(p2, p3, ah[2 * j + 1], al[2 * j + 1]);
            }
#pragma unroll
            for (int nt = 0; nt < 16; nt++) {
                uint2 ghv = *(const uint2*)&su[off + 8192 + (kt * 16 + nt) * 64 + lane * 2];
                uint2 glv = *(const uint2*)&su[off + 12288 + (kt * 16 + nt) * 64 + lane * 2];
                mma16(yacc[nt], ah, (const uint32_t*)&ghv);
                mma16(yacc[nt], al, (const uint32_t*)&ghv);
                mma16(yacc[nt], ah, (const uint32_t*)&glv);
            }
        }
        __syncthreads();   // all warps done with this buffer before ch+2 overwrites it
    }

    // ---- epilogue: normalize, split hi/lo, store y as A-frags ----
    ls0 += __shfl_xor_sync(0xffffffffu, ls0, 1);
    ls0 += __shfl_xor_sync(0xffffffffu, ls0, 2);
    ls1 += __shfl_xor_sync(0xffffffffu, ls1, 1);
    ls1 += __shfl_xor_sync(0xffffffffu, ls1, 2);
    float inv0 = 1.f / ls0, inv1 = 1.f / ls1;

    size_t base = ((size_t)(b * 32 + rt) * 8 + w) * 1024;
#pragma unroll
    for (int kt = 0; kt < 8; kt++) {
        uint32_t h0, l0, h1, l1, h2, l2, h3, l3;
        splitpair(yacc[2 * kt][0] * inv0, yacc[2 * kt][1] * inv0, h0, l0);
        splitpair(yacc[2 * kt][2] * inv1, yacc[2 * kt][3] * inv1, h1, l1);
        splitpair(yacc[2 * kt + 1][0] * inv0, yacc[2 * kt + 1][1] * inv0, h2, l2);
        splitpair(yacc[2 * kt + 1][2] * inv1, yacc[2 * kt + 1][3] * inv1, h3, l3);
        *(uint4*)&d_yh[base + kt * 128 + lane * 4] = make_uint4(h0, h1, h2, h3);
        *(uint4*)&d_yl[base + kt * 128 + lane * 4] = make_uint4(l0, l1, l2, l3);
    }
}

// =====================================================================
// Kernel 3: output conv mma + BN + residual (unchanged)
// =====================================================================
#define OK_BH 0
#define OK_BL 8192
#define OK_BN 16640
#define OK_U32 16896

__global__ void __launch_bounds__(256) out_mma_kernel(
    const float* __restrict__ x,
    const float* __restrict__ Wb,    const float* __restrict__ gamma,
    const float* __restrict__ beta,  const float* __restrict__ bmean,
    const float* __restrict__ bvar,  float* __restrict__ out)
{
    extern __shared__ uint32_t su[];
    float* sf = (float*)su;

    int pt = blockIdx.x, jt = blockIdx.y, b = blockIdx.z;
    int oc0 = jt * 128;
    int tid = threadIdx.x;
    int w = tid >> 5, lane = tid & 31;
    int gr = lane >> 2, t4 = lane & 3;
    int wM = w >> 1, wN = w & 1;

    if (tid < 128) {
        int oc = oc0 + tid;
        float inv = gamma[oc] * rsqrtf(bvar[oc] + 1e-5f);
        sf[OK_BN + tid] = inv;
        sf[OK_BN + 128 + tid] = (Wb[oc] - bmean[oc]) * inv + beta[oc];
    }

    {
        int wo = OW_BASE + jt * 8192;
#pragma unroll
        for (int i = 0; i < 8; i++) {
            int e4 = (tid + i * 256) * 4;
            *(uint4*)&su[OK_BH + e4] = *(const uint4*)&d_wpH[wo + e4];
            *(uint4*)&su[OK_BL + e4] = *(const uint4*)&d_wpL[wo + e4];
        }
    }
    __syncthreads();

    float acc[2][8][4];
#pragma unroll
    for (int mt = 0; mt < 2; mt++)
#pragma unroll
        for (int nt = 0; nt < 8; nt++)
#pragma unroll
            for (int q = 0; q < 4; q++) acc[mt][nt][q] = 0.f;

    size_t abase = (size_t)(b * 32 + pt) * 8192;
#pragma unroll
    for (int kt = 0; kt < 8; kt++) {
        uint4 ahv[2], alv[2];
#pragma unroll
        for (int mt = 0; mt < 2; mt++) {
            int ww = wM * 2 + mt;
            ahv[mt] = *(const uint4*)&d_yh[abase + (ww * 8 + kt) * 128 + lane * 4];
            alv[mt] = *(const uint4*)&d_yl[abase + (ww * 8 + kt) * 128 + lane * 4];
        }
#pragma unroll
        for (int nt = 0; nt < 8; nt++) {
            int ntg = wN * 8 + nt;
            uint2 bhv = *(const uint2*)&su[OK_BH + (kt * 16 + ntg) * 64 + lane * 2];
            uint2 blv = *(const uint2*)&su[OK_BL + (kt * 16 + ntg) * 64 + lane * 2];
#pragma unroll
            for (int mt = 0; mt < 2; mt++) {
                mma16(acc[mt][nt], (const uint32_t*)&ahv[mt], (const uint32_t*)&bhv);
                mma16(acc[mt][nt], (const uint32_t*)&alv[mt], (const uint32_t*)&bhv);
                mma16(acc[mt][nt], (const uint32_t*)&ahv[mt], (const uint32_t*)&blv);
            }
        }
    }
    __syncthreads();

#pragma unroll
    for (int mt = 0; mt < 2; mt++)
#pragma unroll
    for (int nt = 0; nt < 8; nt++) {
        int col = wN * 64 + nt * 8 + 2 * t4;
        float i0 = sf[OK_BN + col],       i1 = sf[OK_BN + col + 1];
        float a0 = sf[OK_BN + 128 + col], a1 = sf[OK_BN + 128 + col + 1];
        int ra = (wM * 2 + mt) * 16 + gr, rb = ra + 8;
        sf[ra * 130 + col]     = acc[mt][nt][0] * i0 + a0;
        sf[ra * 130 + col + 1] = acc[mt][nt][1] * i1 + a1;
        sf[rb * 130 + col]     = acc[mt][nt][2] * i0 + a0;
        sf[rb * 130 + col + 1] = acc[mt][nt][3] * i1 + a1;
    }
    __syncthreads();

    const float* xr = x + ((size_t)b * CC + oc0) * NPIX + pt * 128;
    float* outp = out + ((size_t)b * CC + oc0) * NPIX + pt * 128;
#pragma unroll
    for (int i = 0; i < 16; i++) {
        int e = tid + i * 256;
        int oc = e >> 5, pq = (e & 31) * 4;
        float4 xv = *(const float4*)&xr[(size_t)oc * NPIX + pq];
        float4 v = make_float4(sf[(pq + 0) * 130 + oc] + xv.x,
                               sf[(pq + 1) * 130 + oc] + xv.y,
                               sf[(pq + 2) * 130 + oc] + xv.z,
                               sf[(pq + 3) * 130 + oc] + xv.w);
        *(float4*)&outp[(size_t)oc * NPIX + pq] = v;
    }
}

// =====================================================================
extern "C" void kernel_launch(void* const* d_in, const int* in_sizes, int n_in,
                              void* d_out, int out_size)
{
    (void)in_sizes; (void)n_in; (void)out_size;
    const float* x    = (const float*)d_in[0];
    const float* g_w  = (const float*)d_in[1];
    const float* g_b  = (const float*)d_in[2];
    const float* th_w = (const float*)d_in[3];
    const float* th_b = (const float*)d_in[4];
    const float* ph_w = (const float*)d_in[5];
    const float* ph_b = (const float*)d_in[6];
    const float* W_w  = (const float*)d_in[7];
    const float* W_b  = (const float*)d_in[8];
    const float* bg   = (const float*)d_in[9];
    const float* bbta = (const float*)d_in[10];
    const float* bm   = (const float*)d_in[11];
    const float* bv   = (const float*)d_in[12];
    float* out = (float*)d_out;

    static int configured = 0;
    if (!configured) {
        cudaFuncSetAttribute(proj_mma_kernel,
            cudaFuncAttributeMaxDynamicSharedMemorySize, PJ_U32 * 4);
        cudaFuncSetAttribute(attn_bf16_kernel,
            cudaFuncAttributeMaxDynamicSharedMemorySize, AT_U32 * 4);
        cudaFuncSetAttribute(out_mma_kernel,
            cudaFuncAttributeMaxDynamicSharedMemorySize, OK_U32 * 4);
        configured = 1;
    }

    wprep_kernel<<<5, 256>>>(g_w, th_w, ph_w, W_w);
    xprep_kernel<<<dim3(32, 8), 256>>>(x);

    proj_mma_kernel<<<dim3(32, 3, 8), 256, PJ_U32 * 4>>>(g_b, th_b, ph_b);

    attn_bf16_kernel<<<dim3(32, 8), 256, AT_U32 * 4>>>();

    out_mma_kernel<<<dim3(32, 2, 8), 256, OK_U32 * 4>>>(
        x, W_b, bg, bbta, bm, bv, out);
}

// round 13
// speedup vs baseline: 2.4438x; 1.0283x over previous
#include <cuda_runtime.h>
#include <math.h>
#include <stdint.h>

#define BB   8
#define CC   256
#define ICn  128
#define NPIX 4096
#define NPm  1024

// ---------- bf16 helpers ----------
__device__ __forceinline__ uint32_t packbf(float e0, float e1) {
    uint32_t r; asm("cvt.rn.bf16x2.f32 %0, %1, %2;" : "=r"(r) : "f"(e1), "f"(e0)); return r;
}
__device__ __forceinline__ void splitpair(float v0, float v1, uint32_t &hp, uint32_t &lp) {
    hp = packbf(v0, v1);
    float h0 = __uint_as_float(hp << 16);
    float h1 = __uint_as_float(hp & 0xffff0000u);
    lp = packbf(v0 - h0, v1 - h1);
}

// mma.sync m16n8k16 bf16: C += A*B
__device__ __forceinline__ void mma16(float* c, const uint32_t* a, const uint32_t* b) {
    asm volatile("mma.sync.aligned.m16n8k16.row.col.f32.bf16.bf16.f32 "
        "{%0,%1,%2,%3}, {%4,%5,%6,%7}, {%8,%9}, {%0,%1,%2,%3};"
        : "+f"(c[0]), "+f"(c[1]), "+f"(c[2]), "+f"(c[3])
        : "r"(a[0]), "r"(a[1]), "r"(a[2]), "r"(a[3]), "r"(b[0]), "r"(b[1]));
}

// ---------- cp.async helpers ----------
__device__ __forceinline__ uint32_t smem_u32addr(const void* p) {
    uint32_t a;
    asm("{ .reg .u64 t; cvta.to.shared.u64 t, %1; cvt.u32.u64 %0, t; }" : "=r"(a) : "l"(p));
    return a;
}
__device__ __forceinline__ void cp_async16(uint32_t dst, const void* src) {
    asm volatile("cp.async.cg.shared.global [%0], [%1], 16;" :: "r"(dst), "l"(src));
}
#define CP_COMMIT() asm volatile("cp.async.commit_group;" ::: "memory")
#define CP_WAIT(n)  asm volatile("cp.async.wait_group %0;" :: "n"(n) : "memory")

// ---------- scratch: everything in frag format (hi/lo bf16x2) ----------
__device__ uint32_t d_xH [BB * 32 * 16384];      // x A-frags [b][pt][ch4][ww8 s4][128]
__device__ uint32_t d_xL [BB * 32 * 16384];
__device__ uint32_t d_wpH[3 * 16384 + 2 * 8192]; // proj W B-frags; out W at 49152
__device__ uint32_t d_wpL[3 * 16384 + 2 * 8192];
__device__ uint32_t d_thH[BB * 32 * 8192];       // theta A-frags [b][rt][ww][s][128]
__device__ uint32_t d_thL[BB * 32 * 8192];
__device__ uint32_t d_phH[BB * 16 * 4096];       // phi B-frags [b][ch][s 8][nt 8][64]
__device__ uint32_t d_phL[BB * 16 * 4096];
__device__ uint32_t d_gH [BB * 16 * 4096];       // g B-frags [b][ch][kt 4][nt 16][64]
__device__ uint32_t d_gL [BB * 16 * 4096];

#define OW_BASE 49152

// =====================================================================
// Kernel 0a: weight prep — convert all weights to B-frags once.
// =====================================================================
__global__ void __launch_bounds__(256) wprep_kernel(
    const float* __restrict__ g_w, const float* __restrict__ th_w,
    const float* __restrict__ ph_w, const float* __restrict__ W_w)
{
    int jt = blockIdx.x, tid = threadIdx.x;
    if (jt < 3) {
        const float* wsel = (jt == 0) ? th_w : (jt == 1) ? ph_w : g_w;
#pragma unroll
        for (int i = 0; i < 64; i++) {
            int e = tid + i * 256;
            int j = e >> 7, kp = e & 127, k0 = 2 * kp;
            float2 v = *(const float2*)&wsel[j * CC + k0];
            uint32_t h, l;
            splitpair(v.x, v.y, h, l);
            int ch = k0 >> 6, kl = k0 & 63;
            int s = kl >> 4, rg = (kl >> 3) & 1, ta = (kl >> 1) & 3;
            int nt = j >> 3, n8 = j & 7;
            int idx = jt * 16384 + ch * 4096 + (s * 16 + nt) * 64 + (n8 * 4 + ta) * 2 + rg;
            d_wpH[idx] = h;
            d_wpL[idx] = l;
        }
    } else {
        int oc0 = (jt - 3) * 128;
#pragma unroll
        for (int i = 0; i < 32; i++) {
            int e = tid + i * 256;
            int oc = e >> 6, kp = e & 63, k0 = 2 * kp;
            float2 v = *(const float2*)&W_w[(oc0 + oc) * ICn + k0];
            uint32_t h, l;
            splitpair(v.x, v.y, h, l);
            int kt = k0 >> 4, rg = (k0 >> 3) & 1, ta = (k0 >> 1) & 3;
            int nt = oc >> 3, n8 = oc & 7;
            int idx = OW_BASE + (jt - 3) * 8192 + (kt * 16 + nt) * 64 + (n8 * 4 + ta) * 2 + rg;
            d_wpH[idx] = h;
            d_wpL[idx] = l;
        }
    }
}

// =====================================================================
// Kernel 0b: x prep — convert each 128-pixel tile of x to A-frags once.
// =====================================================================
__global__ void __launch_bounds__(256) xprep_kernel(const float* __restrict__ x)
{
    __shared__ float sx[64 * 128];
    int pt = blockIdx.x, b = blockIdx.y, tid = threadIdx.x;
    size_t base = (size_t)(b * 32 + pt) * 16384;

    for (int ch = 0; ch < 4; ch++) {
#pragma unroll
        for (int i = 0; i < 8; i++) {
            int e = tid + i * 256;
            int kc = e >> 5, p4 = (e & 31) * 4;
            *(float4*)&sx[kc * 128 + p4] =
                *(const float4*)&x[((size_t)b * CC + ch * 64 + kc) * NPIX + pt * 128 + p4];
        }
        __syncthreads();
#pragma unroll
        for (int i = 0; i < 16; i++) {
            int e = tid + i * 256;
            int blk = e >> 7, off = e & 127;
            int ww = blk >> 2, s = blk & 3;
            int gg = off >> 4, ta = (off >> 2) & 3, rg = (off >> 1) & 1, hi8 = off & 1;
            int p = ww * 16 + hi8 * 8 + gg;
            int kl = s * 16 + rg * 8 + ta * 2;
            uint32_t h, l;
            splitpair(sx[kl * 128 + p], sx[(kl + 1) * 128 + p], h, l);
            d_xH[base + ch * 4096 + e] = h;
            d_xL[base + ch * 4096 + e] = l;
        }
        __syncthreads();
    }
}

// =====================================================================
// Kernel 1: projection mma + fused 2x2 maxpool, cp.async double-buffered.
// (unchanged from round 12 passing version)
// =====================================================================
#define PJ_BUF 16384
#define PJ_BIAS 32768
#define PJ_U32 32896

__global__ void __launch_bounds__(256) proj_mma_kernel(
    const float* __restrict__ g_b, const float* __restrict__ th_b,
    const float* __restrict__ ph_b)
{
    extern __shared__ uint32_t su[];
    float* sf = (float*)su;
    uint32_t sb = smem_u32addr(su);

    int pt = blockIdx.x, jt = blockIdx.y, b = blockIdx.z;
    const float* bsel = (jt == 0) ? th_b : (jt == 1) ? ph_b : g_b;

    int tid = threadIdx.x;
    int w = tid >> 5, lane = tid & 31;
    int gr = lane >> 2, t4 = lane & 3;
    int wM = w >> 1, wN = w & 1;

    if (tid < 128) sf[PJ_BIAS + tid] = bsel[tid];

    size_t xbase = (size_t)(b * 32 + pt) * 16384;
    int wbase = jt * 16384;

    {
#pragma unroll
        for (int i = 0; i < 4; i++) {
            int e4 = (tid + i * 256) * 4;
            cp_async16(sb + (e4) * 4,          &d_xH[xbase + e4]);
            cp_async16(sb + (4096 + e4) * 4,   &d_xL[xbase + e4]);
            cp_async16(sb + (8192 + e4) * 4,   &d_wpH[wbase + e4]);
            cp_async16(sb + (12288 + e4) * 4,  &d_wpL[wbase + e4]);
        }
        CP_COMMIT();
    }

    float acc[2][8][4];
#pragma unroll
    for (int mt = 0; mt < 2; mt++)
#pragma unroll
        for (int nt = 0; nt < 8; nt++)
#pragma unroll
            for (int q = 0; q < 4; q++) acc[mt][nt][q] = 0.f;

    for (int ch = 0; ch < 4; ch++) {
        int off = (ch & 1) * PJ_BUF;

        if (ch + 1 < 4) {
            int noff = ((ch + 1) & 1) * PJ_BUF;
            size_t xo = xbase + (ch + 1) * 4096;
            int wo = wbase + (ch + 1) * 4096;
#pragma unroll
            for (int i = 0; i < 4; i++) {
                int e4 = (tid + i * 256) * 4;
                cp_async16(sb + (noff + e4) * 4,          &d_xH[xo + e4]);
                cp_async16(sb + (noff + 4096 + e4) * 4,   &d_xL[xo + e4]);
                cp_async16(sb + (noff + 8192 + e4) * 4,   &d_wpH[wo + e4]);
                cp_async16(sb + (noff + 12288 + e4) * 4,  &d_wpL[wo + e4]);
            }
            CP_COMMIT();
            CP_WAIT(1);
        } else {
            CP_WAIT(0);
        }
        __syncthreads();

#pragma unroll
        for (int s = 0; s < 4; s++) {
            uint4 ahv[2], alv[2];
#pragma unroll
            for (int mt = 0; mt < 2; mt++) {
                int ww = wM * 2 + mt;
                ahv[mt] = *(const uint4*)&su[off + (ww * 4 + s) * 128 + lane * 4];
                alv[mt] = *(const uint4*)&su[off + 4096 + (ww * 4 + s) * 128 + lane * 4];
            }
#pragma unroll
            for (int nt = 0; nt < 8; nt++) {
                int ntg = wN * 8 + nt;
                uint2 bhv = *(const uint2*)&su[off + 8192 + (s * 16 + ntg) * 64 + lane * 2];
                uint2 blv = *(const uint2*)&su[off + 12288 + (s * 16 + ntg) * 64 + lane * 2];
#pragma unroll
                for (int mt = 0; mt < 2; mt++) {
                    mma16(acc[mt][nt], (const uint32_t*)&ahv[mt], (const uint32_t*)&bhv);
                    mma16(acc[mt][nt], (const uint32_t*)&alv[mt], (const uint32_t*)&bhv);
                    mma16(acc[mt][nt], (const uint32_t*)&ahv[mt], (const uint32_t*)&blv);
                }
            }
        }
        __syncthreads();
    }

#pragma unroll
    for (int mt = 0; mt < 2; mt++)
#pragma unroll
    for (int nt = 0; nt < 8; nt++) {
        int col = wN * 64 + nt * 8 + 2 * t4;
        float b0 = sf[PJ_BIAS + col], b1 = sf[PJ_BIAS + col + 1];
        int ra = (wM * 2 + mt) * 16 + gr, rb = ra + 8;
        sf[ra * 132 + col]     = acc[mt][nt][0] + b0;
        sf[ra * 132 + col + 1] = acc[mt][nt][1] + b1;
        sf[rb * 132 + col]     = acc[mt][nt][2] + b0;
        sf[rb * 132 + col + 1] = acc[mt][nt][3] + b1;
    }
    __syncthreads();

    if (jt == 0) {
        size_t base = (size_t)(b * 32 + pt) * 8192;
#pragma unroll
        for (int i = 0; i < 32; i++) {
            int e = tid + i * 256;
            int blk = e >> 7, off = e & 127;
            int ww = blk >> 3, s = blk & 7;
            int gg = off >> 4, ta = (off >> 2) & 3, rg = (off >> 1) & 1, hi8 = off & 1;
            int p = ww * 16 + hi8 * 8 + gg;
            int ic = s * 16 + rg * 8 + ta * 2;
            uint32_t h, l;
            splitpair(sf[p * 132 + ic], sf[p * 132 + ic + 1], h, l);
            d_thH[base + e] = h;
            d_thL[base + e] = l;
        }
    } else if (jt == 1) {
        int ch = pt >> 1, nthi = (pt & 1) * 4;
        size_t base = (size_t)(b * 16 + ch) * 4096;
#pragma unroll
        for (int i = 0; i < 8; i++) {
            int e = tid + i * 256;
            int s = e >> 8, r = e & 255;
            int ntl = r >> 6, woff = r & 63;
            int n8 = woff >> 3, ta = (woff >> 1) & 3, rg = woff & 1;
            int mc = ntl * 8 + n8;
            int ic = s * 16 + rg * 8 + ta * 2;
            int r0 = 2 * mc, r1 = 2 * mc + 1, r2 = 64 + 2 * mc, r3 = 65 + 2 * mc;
            float v0 = fmaxf(fmaxf(sf[r0 * 132 + ic],     sf[r1 * 132 + ic]),
                             fmaxf(sf[r2 * 132 + ic],     sf[r3 * 132 + ic]));
            float v1 = fmaxf(fmaxf(sf[r0 * 132 + ic + 1], sf[r1 * 132 + ic + 1]),
                             fmaxf(sf[r2 * 132 + ic + 1], sf[r3 * 132 + ic + 1]));
            uint32_t h, l;
            splitpair(v0, v1, h, l);
            size_t idx = base + ((size_t)s * 8 + nthi + ntl) * 64 + woff;
            d_phH[idx] = h;
            d_phL[idx] = l;
        }
    } else {
        int ch = pt >> 1, kthi = (pt & 1) * 2;
        size_t base = (size_t)(b * 16 + ch) * 4096;
#pragma unroll
        for (int i = 0; i < 8; i++) {
            int e = tid + i * 256;
            int ktl = e >> 10, r = e & 1023;
            int nt = r >> 6, woff = r & 63;
            int n8 = woff >> 3, ta = (woff >> 1) & 3, rg = woff & 1;
            int m16 = rg * 8 + ta * 2;
            int mc = ktl * 16 + m16;
            int ic = nt * 8 + n8;
            int ra = 2 * mc, rb = 2 * mc + 1, rc = 64 + 2 * mc, rd = 65 + 2 * mc;
            float v0 = fmaxf(fmaxf(sf[ra * 132 + ic], sf[rb * 132 + ic]),
                             fmaxf(sf[rc * 132 + ic], sf[rd * 132 + ic]));
            ra += 2; rb += 2; rc += 2; rd += 2;
            float v1 = fmaxf(fmaxf(sf[ra * 132 + ic], sf[rb * 132 + ic]),
                             fmaxf(sf[rc * 132 + ic], sf[rd * 132 + ic]));
            uint32_t h, l;
            splitpair(v0, v1, h, l);
            size_t idx = base + ((size_t)(kthi + ktl) * 16 + nt) * 64 + woff;
            d_gH[idx] = h;
            d_gL[idx] = l;
        }
    }
}

// =====================================================================
// Kernel 2: FUSED attention + output conv + BN + residual.
// Mainloop unchanged (cp.async double-buffer, theta in regs).
// Epilogue: yacc -> in-register y A-frags; two jt passes compute
// out = BN(y @ W) + x directly (W frags from gmem via smem).
// smem u32: mainloop buf0/buf1 [0,32768); epilogue reuses:
//   W: HI[0,8192) LO[8192,16384); BN f32 inv[16640..16768) addc[16768..16896)
//   stage f32 [128][130] in [0,16640)
// =====================================================================
#define AT_U32 32768
#define FB_INV 16640
#define FB_ADD 16768

__global__ void __launch_bounds__(256, 1) attn_fused_kernel(
    const float* __restrict__ x,
    const float* __restrict__ Wb,    const float* __restrict__ gamma,
    const float* __restrict__ beta,  const float* __restrict__ bmean,
    const float* __restrict__ bvar,  float* __restrict__ out)
{
    extern __shared__ uint32_t su[];
    float* sf = (float*)su;
    uint32_t sb = smem_u32addr(su);
    int tid = threadIdx.x;
    int w = tid >> 5, lane = tid & 31;
    int gr = lane >> 2, t4 = lane & 3;
    int rt = blockIdx.x, b = blockIdx.y;

    // ---- issue chunk 0 copy (cp.async) ----
    {
        size_t base = (size_t)(b * 16) * 4096;
#pragma unroll
        for (int i = 0; i < 4; i++) {
            int e4 = (tid + i * 256) * 4;
            cp_async16(sb + (e4) * 4,          &d_phH[base + e4]);
            cp_async16(sb + (4096 + e4) * 4,   &d_phL[base + e4]);
            cp_async16(sb + (8192 + e4) * 4,   &d_gH[base + e4]);
            cp_async16(sb + (12288 + e4) * 4,  &d_gL[base + e4]);
        }
        CP_COMMIT();
    }

    // ---- theta A-frags -> registers ----
    uint4 thh[8], thl[8];
    {
        size_t tb = (size_t)(b * 32 + rt) * 8192;
#pragma unroll
        for (int s = 0; s < 8; s++) {
            thh[s] = *(const uint4*)&d_thH[tb + (w * 8 + s) * 128 + lane * 4];
            thl[s] = *(const uint4*)&d_thL[tb + (w * 8 + s) * 128 + lane * 4];
        }
    }

    float yacc[16][4];
#pragma unroll
    for (int nt = 0; nt < 16; nt++)
#pragma unroll
        for (int q = 0; q < 4; q++) yacc[nt][q] = 0.f;
    float ls0 = 0.f, ls1 = 0.f;

    for (int ch = 0; ch < 16; ch++) {
        int off = (ch & 1) * 16384;

        if (ch + 1 < 16) {
            int noff = ((ch + 1) & 1) * 16384;
            size_t base = (size_t)(b * 16 + ch + 1) * 4096;
#pragma unroll
            for (int i = 0; i < 4; i++) {
                int e4 = (tid + i * 256) * 4;
                cp_async16(sb + (noff + e4) * 4,         &d_phH[base + e4]);
                cp_async16(sb + (noff + 4096 + e4) * 4,  &d_phL[base + e4]);
                cp_async16(sb + (noff + 8192 + e4) * 4,  &d_gH[base + e4]);
                cp_async16(sb + (noff + 12288 + e4) * 4, &d_gL[base + e4]);
            }
            CP_COMMIT();
            CP_WAIT(1);
        } else {
            CP_WAIT(0);
        }
        __syncthreads();

        // ---- S = theta . phi (3-term bf16 split) ----
        float sacc[8][4];
#pragma unroll
        for (int nt = 0; nt < 8; nt++)
#pragma unroll
            for (int q = 0; q < 4; q++) sacc[nt][q] = 0.f;

#pragma unroll
        for (int s = 0; s < 8; s++) {
#pragma unroll
            for (int nt = 0; nt < 8; nt++) {
                uint2 bhv = *(const uint2*)&su[off + (s * 8 + nt) * 64 + lane * 2];
                uint2 blv = *(const uint2*)&su[off + 4096 + (s * 8 + nt) * 64 + lane * 2];
                mma16(sacc[nt], (const uint32_t*)&thh[s], (const uint32_t*)&bhv);
                mma16(sacc[nt], (const uint32_t*)&thl[s], (const uint32_t*)&bhv);
                mma16(sacc[nt], (const uint32_t*)&thh[s], (const uint32_t*)&blv);
            }
        }

        // ---- per kt: exp two nt groups then Y-mma ----
#pragma unroll
        for (int kt = 0; kt < 4; kt++) {
            uint32_t ah[4], al[4];
#pragma unroll
            for (int j = 0; j < 2; j++) {
                int nt = 2 * kt + j;
                float p0 = __expf(sacc[nt][0] - 40.f);
                float p1 = __expf(sacc[nt][1] - 40.f);
                float p2 = __expf(sacc[nt][2] - 40.f);
                float p3 = __expf(sacc[nt][3] - 40.f);
                ls0 += p0 + p1;
                ls1 += p2 + p3;
                splitpair(p0, p1, ah[2 * j],     al[2 * j]);
                splitpair(p2, p3, ah[2 * j + 1], al[2 * j + 1]);
            }
#pragma unroll
            for (int nt = 0; nt < 16; nt++) {
                uint2 ghv = *(const uint2*)&su[off + 8192 + (kt * 16 + nt) * 64 + lane * 2];
                uint2 glv = *(const uint2*)&su[off + 12288 + (kt * 16 + nt) * 64 + lane * 2];
                mma16(yacc[nt], ah, (const uint32_t*)&ghv);
                mma16(yacc[nt], al, (const uint32_t*)&ghv);
                mma16(yacc[nt], ah, (const uint32_t*)&glv);
            }
        }
        __syncthreads();
    }

    // ---- normalize + convert yacc -> y A-frags (registers) ----
    ls0 += __shfl_xor_sync(0xffffffffu, ls0, 1);
    ls0 += __shfl_xor_sync(0xffffffffu, ls0, 2);
    ls1 += __shfl_xor_sync(0xffffffffu, ls1, 1);
    ls1 += __shfl_xor_sync(0xffffffffu, ls1, 2);
    float inv0 = 1.f / ls0, inv1 = 1.f / ls1;

    uint32_t yh[8][4], yl[8][4];
#pragma unroll
    for (int kt = 0; kt < 8; kt++) {
        splitpair(yacc[2 * kt][0] * inv0, yacc[2 * kt][1] * inv0, yh[kt][0], yl[kt][0]);
        splitpair(yacc[2 * kt][2] * inv1, yacc[2 * kt][3] * inv1, yh[kt][1], yl[kt][1]);
        splitpair(yacc[2 * kt + 1][0] * inv0, yacc[2 * kt + 1][1] * inv0, yh[kt][2], yl[kt][2]);
        splitpair(yacc[2 * kt + 1][2] * inv1, yacc[2 * kt + 1][3] * inv1, yh[kt][3], yl[kt][3]);
    }

    // ---- fused output conv: two halves of 128 oc each ----
    for (int jt = 0; jt < 2; jt++) {
        int oc0 = jt * 128;
        // W frags -> smem, BN consts
        {
            int wo = OW_BASE + jt * 8192;
#pragma unroll
            for (int i = 0; i < 8; i++) {
                int e4 = (tid + i * 256) * 4;
                *(uint4*)&su[e4]        = *(const uint4*)&d_wpH[wo + e4];
                *(uint4*)&su[8192 + e4] = *(const uint4*)&d_wpL[wo + e4];
            }
            if (tid < 128) {
                int oc = oc0 + tid;
                float bninv = gamma[oc] * rsqrtf(bvar[oc] + 1e-5f);
                sf[FB_INV + tid] = bninv;
                sf[FB_ADD + tid] = (Wb[oc] - bmean[oc]) * bninv + beta[oc];
            }
        }
        __syncthreads();

        float oacc[16][4];
#pragma unroll
        for (int nt = 0; nt < 16; nt++)
#pragma unroll
            for (int q = 0; q < 4; q++) oacc[nt][q] = 0.f;

#pragma unroll
        for (int kt = 0; kt < 8; kt++) {
#pragma unroll
            for (int nt = 0; nt < 16; nt++) {
                uint2 bhv = *(const uint2*)&su[(kt * 16 + nt) * 64 + lane * 2];
                uint2 blv = *(const uint2*)&su[8192 + (kt * 16 + nt) * 64 + lane * 2];
                mma16(oacc[nt], yh[kt], (const uint32_t*)&bhv);
                mma16(oacc[nt], yl[kt], (const uint32_t*)&bhv);
                mma16(oacc[nt], yh[kt], (const uint32_t*)&blv);
            }
        }
        __syncthreads();   // W reads done before staging overwrites

        // ---- BN, stage [pixel 128][oc 128] pitch 130 (scalar) ----
#pragma unroll
        for (int nt = 0; nt < 16; nt++) {
            int col = nt * 8 + 2 * t4;
            float i0 = sf[FB_INV + col], i1 = sf[FB_INV + col + 1];
            float a0 = sf[FB_ADD + col], a1 = sf[FB_ADD + col + 1];
            int ra = w * 16 + gr, rb = ra + 8;
            sf[ra * 130 + col]     = oacc[nt][0] * i0 + a0;
            sf[ra * 130 + col + 1] = oacc[nt][1] * i1 + a1;
            sf[rb * 130 + col]     = oacc[nt][2] * i0 + a0;
            sf[rb * 130 + col + 1] = oacc[nt][3] * i1 + a1;
        }
        __syncthreads();

        // ---- transpose write + residual ----
        const float* xr = x + ((size_t)b * CC + oc0) * NPIX + rt * 128;
        float* outp = out + ((size_t)b * CC + oc0) * NPIX + rt * 128;
#pragma unroll
        for (int i = 0; i < 16; i++) {
            int e = tid + i * 256;
            int oc = e >> 5, pq = (e & 31) * 4;
            float4 xv = *(const float4*)&xr[(size_t)oc * NPIX + pq];
            float4 v = make_float4(sf[(pq + 0) * 130 + oc] + xv.x,
                                   sf[(pq + 1) * 130 + oc] + xv.y,
                                   sf[(pq + 2) * 130 + oc] + xv.z,
                                   sf[(pq + 3) * 130 + oc] + xv.w);
            *(float4*)&outp[(size_t)oc * NPIX + pq] = v;
        }
        __syncthreads();   // staging free before next jt's W copy
    }
}

// =====================================================================
extern "C" void kernel_launch(void* const* d_in, const int* in_sizes, int n_in,
                              void* d_out, int out_size)
{
    (void)in_sizes; (void)n_in; (void)out_size;
    const float* x    = (const float*)d_in[0];
    const float* g_w  = (const float*)d_in[1];
    const float* g_b  = (const float*)d_in[2];
    const float* th_w = (const float*)d_in[3];
    const float* th_b = (const float*)d_in[4];
    const float* ph_w = (const float*)d_in[5];
    const float* ph_b = (const float*)d_in[6];
    const float* W_w  = (const float*)d_in[7];
    const float* W_b  = (const float*)d_in[8];
    const float* bg   = (const float*)d_in[9];
    const float* bbta = (const float*)d_in[10];
    const float* bm   = (const float*)d_in[11];
    const float* bv   = (const float*)d_in[12];
    float* out = (float*)d_out;

    static int configured = 0;
    if (!configured) {
        cudaFuncSetAttribute(proj_mma_kernel,
            cudaFuncAttributeMaxDynamicSharedMemorySize, PJ_U32 * 4);
        cudaFuncSetAttribute(attn_fused_kernel,
            cudaFuncAttributeMaxDynamicSharedMemorySize, AT_U32 * 4);
        configured = 1;
    }

    wprep_kernel<<<5, 256>>>(g_w, th_w, ph_w, W_w);
    xprep_kernel<<<dim3(32, 8), 256>>>(x);

    proj_mma_kernel<<<dim3(32, 3, 8), 256, PJ_U32 * 4>>>(g_b, th_b, ph_b);

    attn_fused_kernel<<<dim3(32, 8), 256, AT_U32 * 4>>>(
        x, W_b, bg, bbta, bm, bv, out);
}

// round 15
// speedup vs baseline: 2.7569x; 1.1281x over previous
#include <cuda_runtime.h>
#include <math.h>
#include <stdint.h>

#define BB   8
#define CC   256
#define ICn  128
#define NPIX 4096
#define NPm  1024

// ---------- bf16 helpers ----------
__device__ __forceinline__ uint32_t packbf(float e0, float e1) {
    uint32_t r; asm("cvt.rn.bf16x2.f32 %0, %1, %2;" : "=r"(r) : "f"(e1), "f"(e0)); return r;
}
__device__ __forceinline__ void splitpair(float v0, float v1, uint32_t &hp, uint32_t &lp) {
    hp = packbf(v0, v1);
    float h0 = __uint_as_float(hp << 16);
    float h1 = __uint_as_float(hp & 0xffff0000u);
    lp = packbf(v0 - h0, v1 - h1);
}

// mma.sync m16n8k16 bf16: C += A*B
__device__ __forceinline__ void mma16(float* c, const uint32_t* a, const uint32_t* b) {
    asm volatile("mma.sync.aligned.m16n8k16.row.col.f32.bf16.bf16.f32 "
        "{%0,%1,%2,%3}, {%4,%5,%6,%7}, {%8,%9}, {%0,%1,%2,%3};"
        : "+f"(c[0]), "+f"(c[1]), "+f"(c[2]), "+f"(c[3])
        : "r"(a[0]), "r"(a[1]), "r"(a[2]), "r"(a[3]), "r"(b[0]), "r"(b[1]));
}

// ---------- cp.async helpers ----------
__device__ __forceinline__ uint32_t smem_u32addr(const void* p) {
    uint32_t a;
    asm("{ .reg .u64 t; cvta.to.shared.u64 t, %1; cvt.u32.u64 %0, t; }" : "=r"(a) : "l"(p));
    return a;
}
__device__ __forceinline__ void cp_async16(uint32_t dst, const void* src) {
    asm volatile("cp.async.cg.shared.global [%0], [%1], 16;" :: "r"(dst), "l"(src));
}
#define CP_COMMIT() asm volatile("cp.async.commit_group;" ::: "memory")
#define CP_WAIT(n)  asm volatile("cp.async.wait_group %0;" :: "n"(n) : "memory")

// ---------- scratch: everything in frag format (hi/lo bf16x2) ----------
__device__ uint32_t d_xH [BB * 32 * 16384];      // x A-frags [b][pt][ch4][ww8 s4][128]
__device__ uint32_t d_xL [BB * 32 * 16384];
__device__ uint32_t d_wpH[3 * 16384 + 2 * 8192]; // proj W B-frags; out W at 49152
__device__ uint32_t d_wpL[3 * 16384 + 2 * 8192];
__device__ uint32_t d_thH[BB * 32 * 8192];       // theta A-frags [b][rt][ww][s][128]
__device__ uint32_t d_thL[BB * 32 * 8192];
__device__ uint32_t d_phH[BB * 16 * 4096];       // phi B-frags [b][ch][s 8][nt 8][64]
__device__ uint32_t d_phL[BB * 16 * 4096];
__device__ uint32_t d_gH [BB * 16 * 4096];       // g B-frags [b][ch][kt 4][nt 16][64]
__device__ uint32_t d_gL [BB * 16 * 4096];

#define OW_BASE 49152

// =====================================================================
// Kernel 0: merged prep. grid (32, 9):
//   y < 8            : xprep for tile (pt=x, b=y)
//   y == 8 && x < 5  : wprep jt=x (0..2 proj W, 3..4 out W halves)
// =====================================================================
__global__ void __launch_bounds__(256) prep_kernel(
    const float* __restrict__ x,
    const float* __restrict__ g_w, const float* __restrict__ th_w,
    const float* __restrict__ ph_w, const float* __restrict__ W_w)
{
    __shared__ float sx[64 * 128];
    int tid = threadIdx.x;

    if (blockIdx.y == 8) {
        int jt = blockIdx.x;
        if (jt >= 5) return;
        if (jt < 3) {
            const float* wsel = (jt == 0) ? th_w : (jt == 1) ? ph_w : g_w;
#pragma unroll
            for (int i = 0; i < 64; i++) {
                int e = tid + i * 256;
                int j = e >> 7, kp = e & 127, k0 = 2 * kp;
                float2 v = *(const float2*)&wsel[j * CC + k0];
                uint32_t h, l;
                splitpair(v.x, v.y, h, l);
                int ch = k0 >> 6, kl = k0 & 63;
                int s = kl >> 4, rg = (kl >> 3) & 1, ta = (kl >> 1) & 3;
                int nt = j >> 3, n8 = j & 7;
                int idx = jt * 16384 + ch * 4096 + (s * 16 + nt) * 64 + (n8 * 4 + ta) * 2 + rg;
                d_wpH[idx] = h;
                d_wpL[idx] = l;
            }
        } else {
            int oc0 = (jt - 3) * 128;
#pragma unroll
            for (int i = 0; i < 32; i++) {
                int e = tid + i * 256;
                int oc = e >> 6, kp = e & 63, k0 = 2 * kp;
                float2 v = *(const float2*)&W_w[(oc0 + oc) * ICn + k0];
                uint32_t h, l;
                splitpair(v.x, v.y, h, l);
                int kt = k0 >> 4, rg = (k0 >> 3) & 1, ta = (k0 >> 1) & 3;
                int nt = oc >> 3, n8 = oc & 7;
                int idx = OW_BASE + (jt - 3) * 8192 + (kt * 16 + nt) * 64 + (n8 * 4 + ta) * 2 + rg;
                d_wpH[idx] = h;
                d_wpL[idx] = l;
            }
        }
        return;
    }

    int pt = blockIdx.x, b = blockIdx.y;
    size_t base = (size_t)(b * 32 + pt) * 16384;

    for (int ch = 0; ch < 4; ch++) {
#pragma unroll
        for (int i = 0; i < 8; i++) {
            int e = tid + i * 256;
            int kc = e >> 5, p4 = (e & 31) * 4;
            *(float4*)&sx[kc * 128 + p4] =
                *(const float4*)&x[((size_t)b * CC + ch * 64 + kc) * NPIX + pt * 128 + p4];
        }
        __syncthreads();
#pragma unroll
        for (int i = 0; i < 16; i++) {
            int e = tid + i * 256;
            int blk = e >> 7, off = e & 127;
            int ww = blk >> 2, s = blk & 3;
            int gg = off >> 4, ta = (off >> 2) & 3, rg = (off >> 1) & 1, hi8 = off & 1;
            int p = ww * 16 + hi8 * 8 + gg;
            int kl = s * 16 + rg * 8 + ta * 2;
            uint32_t h, l;
            splitpair(sx[kl * 128 + p], sx[(kl + 1) * 128 + p], h, l);
            d_xH[base + ch * 4096 + e] = h;
            d_xL[base + ch * 4096 + e] = l;
        }
        __syncthreads();
    }
}

// =====================================================================
// Kernel 1: projection mma + fused 2x2 maxpool, cp.async double-buffered.
// (round-13 passing version; g epilogue stores hi AND lo)
// =====================================================================
#define PJ_BUF 16384
#define PJ_BIAS 32768
#define PJ_U32 32896

__global__ void __launch_bounds__(256) proj_mma_kernel(
    const float* __restrict__ g_b, const float* __restrict__ th_b,
    const float* __restrict__ ph_b)
{
    extern __shared__ uint32_t su[];
    float* sf = (float*)su;
    uint32_t sb = smem_u32addr(su);

    int pt = blockIdx.x, jt = blockIdx.y, b = blockIdx.z;
    const float* bsel = (jt == 0) ? th_b : (jt == 1) ? ph_b : g_b;

    int tid = threadIdx.x;
    int w = tid >> 5, lane = tid & 31;
    int gr = lane >> 2, t4 = lane & 3;
    int wM = w >> 1, wN = w & 1;

    if (tid < 128) sf[PJ_BIAS + tid] = bsel[tid];

    size_t xbase = (size_t)(b * 32 + pt) * 16384;
    int wbase = jt * 16384;

    {
#pragma unroll
        for (int i = 0; i < 4; i++) {
            int e4 = (tid + i * 256) * 4;
            cp_async16(sb + (e4) * 4,          &d_xH[xbase + e4]);
            cp_async16(sb + (4096 + e4) * 4,   &d_xL[xbase + e4]);
            cp_async16(sb + (8192 + e4) * 4,   &d_wpH[wbase + e4]);
            cp_async16(sb + (12288 + e4) * 4,  &d_wpL[wbase + e4]);
        }
        CP_COMMIT();
    }

    float acc[2][8][4];
#pragma unroll
    for (int mt = 0; mt < 2; mt++)
#pragma unroll
        for (int nt = 0; nt < 8; nt++)
#pragma unroll
            for (int q = 0; q < 4; q++) acc[mt][nt][q] = 0.f;

    for (int ch = 0; ch < 4; ch++) {
        int off = (ch & 1) * PJ_BUF;

        if (ch + 1 < 4) {
            int noff = ((ch + 1) & 1) * PJ_BUF;
            size_t xo = xbase + (ch + 1) * 4096;
            int wo = wbase + (ch + 1) * 4096;
#pragma unroll
            for (int i = 0; i < 4; i++) {
                int e4 = (tid + i * 256) * 4;
                cp_async16(sb + (noff + e4) * 4,          &d_xH[xo + e4]);
                cp_async16(sb + (noff + 4096 + e4) * 4,   &d_xL[xo + e4]);
                cp_async16(sb + (noff + 8192 + e4) * 4,   &d_wpH[wo + e4]);
                cp_async16(sb + (noff + 12288 + e4) * 4,  &d_wpL[wo + e4]);
            }
            CP_COMMIT();
            CP_WAIT(1);
        } else {
            CP_WAIT(0);
        }
        __syncthreads();

#pragma unroll
        for (int s = 0; s < 4; s++) {
            uint4 ahv[2], alv[2];
#pragma unroll
            for (int mt = 0; mt < 2; mt++) {
                int ww = wM * 2 + mt;
                ahv[mt] = *(const uint4*)&su[off + (ww * 4 + s) * 128 + lane * 4];
                alv[mt] = *(const uint4*)&su[off + 4096 + (ww * 4 + s) * 128 + lane * 4];
            }
#pragma unroll
            for (int nt = 0; nt < 8; nt++) {
                int ntg = wN * 8 + nt;
                uint2 bhv = *(const uint2*)&su[off + 8192 + (s * 16 + ntg) * 64 + lane * 2];
                uint2 blv = *(const uint2*)&su[off + 12288 + (s * 16 + ntg) * 64 + lane * 2];
#pragma unroll
                for (int mt = 0; mt < 2; mt++) {
                    mma16(acc[mt][nt], (const uint32_t*)&ahv[mt], (const uint32_t*)&bhv);
                    mma16(acc[mt][nt], (const uint32_t*)&alv[mt], (const uint32_t*)&bhv);
                    mma16(acc[mt][nt], (const uint32_t*)&ahv[mt], (const uint32_t*)&blv);
                }
            }
        }
        __syncthreads();
    }

#pragma unroll
    for (int mt = 0; mt < 2; mt++)
#pragma unroll
    for (int nt = 0; nt < 8; nt++) {
        int col = wN * 64 + nt * 8 + 2 * t4;
        float b0 = sf[PJ_BIAS + col], b1 = sf[PJ_BIAS + col + 1];
        int ra = (wM * 2 + mt) * 16 + gr, rb = ra + 8;
        sf[ra * 132 + col]     = acc[mt][nt][0] + b0;
        sf[ra * 132 + col + 1] = acc[mt][nt][1] + b1;
        sf[rb * 132 + col]     = acc[mt][nt][2] + b0;
        sf[rb * 132 + col + 1] = acc[mt][nt][3] + b1;
    }
    __syncthreads();

    if (jt == 0) {
        size_t base = (size_t)(b * 32 + pt) * 8192;
#pragma unroll
        for (int i = 0; i < 32; i++) {
            int e = tid + i * 256;
            int blk = e >> 7, off = e & 127;
            int ww = blk >> 3, s = blk & 7;
            int gg = off >> 4, ta = (off >> 2) & 3, rg = (off >> 1) & 1, hi8 = off & 1;
            int p = ww * 16 + hi8 * 8 + gg;
            int ic = s * 16 + rg * 8 + ta * 2;
            uint32_t h, l;
            splitpair(sf[p * 132 + ic], sf[p * 132 + ic + 1], h, l);
            d_thH[base + e] = h;
            d_thL[base + e] = l;
        }
    } else if (jt == 1) {
        int ch = pt >> 1, nthi = (pt & 1) * 4;
        size_t base = (size_t)(b * 16 + ch) * 4096;
#pragma unroll
        for (int i = 0; i < 8; i++) {
            int e = tid + i * 256;
            int s = e >> 8, r = e & 255;
            int ntl = r >> 6, woff = r & 63;
            int n8 = woff >> 3, ta = (woff >> 1) & 3, rg = woff & 1;
            int mc = ntl * 8 + n8;
            int ic = s * 16 + rg * 8 + ta * 2;
            int r0 = 2 * mc, r1 = 2 * mc + 1, r2 = 64 + 2 * mc, r3 = 65 + 2 * mc;
            float v0 = fmaxf(fmaxf(sf[r0 * 132 + ic],     sf[r1 * 132 + ic]),
                             fmaxf(sf[r2 * 132 + ic],     sf[r3 * 132 + ic]));
            float v1 = fmaxf(fmaxf(sf[r0 * 132 + ic + 1], sf[r1 * 132 + ic + 1]),
                             fmaxf(sf[r2 * 132 + ic + 1], sf[r3 * 132 + ic + 1]));
            uint32_t h, l;
            splitpair(v0, v1, h, l);
            size_t idx = base + ((size_t)s * 8 + nthi + ntl) * 64 + woff;
            d_phH[idx] = h;
            d_phL[idx] = l;
        }
    } else {
        int ch = pt >> 1, kthi = (pt & 1) * 2;
        size_t base = (size_t)(b * 16 + ch) * 4096;
#pragma unroll
        for (int i = 0; i < 8; i++) {
            int e = tid + i * 256;
            int ktl = e >> 10, r = e & 1023;
            int nt = r >> 6, woff = r & 63;
            int n8 = woff >> 3, ta = (woff >> 1) & 3, rg = woff & 1;
            int m16 = rg * 8 + ta * 2;
            int mc = ktl * 16 + m16;
            int ic = nt * 8 + n8;
            int ra = 2 * mc, rb = 2 * mc + 1, rc = 64 + 2 * mc, rd = 65 + 2 * mc;
            float v0 = fmaxf(fmaxf(sf[ra * 132 + ic], sf[rb * 132 + ic]),
                             fmaxf(sf[rc * 132 + ic], sf[rd * 132 + ic]));
            ra += 2; rb += 2; rc += 2; rd += 2;
            float v1 = fmaxf(fmaxf(sf[ra * 132 + ic], sf[rb * 132 + ic]),
                             fmaxf(sf[rc * 132 + ic], sf[rd * 132 + ic]));
            uint32_t h, l;
            splitpair(v0, v1, h, l);
            size_t idx = base + ((size_t)(kthi + ktl) * 16 + nt) * 64 + woff;
            d_gH[idx] = h;
            d_gL[idx] = l;
        }
    }
}

// =====================================================================
// Kernel 2: FUSED attention + output conv + BN + residual.
// 3-term Y restored. Epilogue W pipelined via cp.async:
//   ch15 -> jt0 W (hi+lo) into free buf0; after loop -> jt1 W at J1W.
// smem u32 (33280):
//   mainloop buf0 [0,16384): PBH 0, PBL 4096, GBH 8192, GBL 12288
//   buf1 [16384,32768)
//   epilogue: jt0 W HI[0,8192) LO[8192,16384); jt1 W HI[J1W) LO[J1W+8192)
//   BN inv[16640,16768) addc[16768,16896); stage f32 [0,16640)
// =====================================================================
#define AT_U32 33280
#define AB_SZ  16384
#define FB_INV 16640
#define FB_ADD 16768
#define J1W    16896

__global__ void __launch_bounds__(256, 1) attn_fused_kernel(
    const float* __restrict__ x,
    const float* __restrict__ Wb,    const float* __restrict__ gamma,
    const float* __restrict__ beta,  const float* __restrict__ bmean,
    const float* __restrict__ bvar,  float* __restrict__ out)
{
    extern __shared__ uint32_t su[];
    float* sf = (float*)su;
    uint32_t sb = smem_u32addr(su);
    int tid = threadIdx.x;
    int w = tid >> 5, lane = tid & 31;
    int gr = lane >> 2, t4 = lane & 3;
    int rt = blockIdx.x, b = blockIdx.y;

    // ---- issue chunk 0 copy ----
    {
        size_t base = (size_t)(b * 16) * 4096;
#pragma unroll
        for (int i = 0; i < 4; i++) {
            int e4 = (tid + i * 256) * 4;
            cp_async16(sb + (e4) * 4,          &d_phH[base + e4]);
            cp_async16(sb + (4096 + e4) * 4,   &d_phL[base + e4]);
            cp_async16(sb + (8192 + e4) * 4,   &d_gH[base + e4]);
            cp_async16(sb + (12288 + e4) * 4,  &d_gL[base + e4]);
        }
        CP_COMMIT();
    }

    // ---- theta A-frags -> registers ----
    uint4 thh[8], thl[8];
    {
        size_t tb = (size_t)(b * 32 + rt) * 8192;
#pragma unroll
        for (int s = 0; s < 8; s++) {
            thh[s] = *(const uint4*)&d_thH[tb + (w * 8 + s) * 128 + lane * 4];
            thl[s] = *(const uint4*)&d_thL[tb + (w * 8 + s) * 128 + lane * 4];
        }
    }

    float yacc[16][4];
#pragma unroll
    for (int nt = 0; nt < 16; nt++)
#pragma unroll
        for (int q = 0; q < 4; q++) yacc[nt][q] = 0.f;
    float ls0 = 0.f, ls1 = 0.f;

    for (int ch = 0; ch < 16; ch++) {
        int off = (ch & 1) * AB_SZ;

        if (ch + 1 < 16) {
            int noff = ((ch + 1) & 1) * AB_SZ;
            size_t base = (size_t)(b * 16 + ch + 1) * 4096;
#pragma unroll
            for (int i = 0; i < 4; i++) {
                int e4 = (tid + i * 256) * 4;
                cp_async16(sb + (noff + e4) * 4,         &d_phH[base + e4]);
                cp_async16(sb + (noff + 4096 + e4) * 4,  &d_phL[base + e4]);
                cp_async16(sb + (noff + 8192 + e4) * 4,  &d_gH[base + e4]);
                cp_async16(sb + (noff + 12288 + e4) * 4, &d_gL[base + e4]);
            }
            CP_COMMIT();
            CP_WAIT(1);
        } else {
            // ch == 15 (buf1 active): prefetch jt0 W (hi+lo) into buf0
#pragma unroll
            for (int i = 0; i < 8; i++) {
                int e4 = (tid + i * 256) * 4;
                cp_async16(sb + e4 * 4,            &d_wpH[OW_BASE + e4]);
                cp_async16(sb + (8192 + e4) * 4,   &d_wpL[OW_BASE + e4]);
            }
            CP_COMMIT();
            CP_WAIT(1);     // chunk 15 data done; W group in flight
        }
        __syncthreads();

        // ---- S = theta . phi (3-term bf16 split) ----
        float sacc[8][4];
#pragma unroll
        for (int nt = 0; nt < 8; nt++)
#pragma unroll
            for (int q = 0; q < 4; q++) sacc[nt][q] = 0.f;

#pragma unroll
        for (int s = 0; s < 8; s++) {
#pragma unroll
            for (int nt = 0; nt < 8; nt++) {
                uint2 bhv = *(const uint2*)&su[off + (s * 8 + nt) * 64 + lane * 2];
                uint2 blv = *(const uint2*)&su[off + 4096 + (s * 8 + nt) * 64 + lane * 2];
                mma16(sacc[nt], (const uint32_t*)&thh[s], (const uint32_t*)&bhv);
                mma16(sacc[nt], (const uint32_t*)&thl[s], (const uint32_t*)&bhv);
                mma16(sacc[nt], (const uint32_t*)&thh[s], (const uint32_t*)&blv);
            }
        }

        // ---- per kt: exp then Y += Ph*Gh + Pl*Gh + Ph*Gl ----
#pragma unroll
        for (int kt = 0; kt < 4; kt++) {
            uint32_t ah[4], al[4];
#pragma unroll
            for (int j = 0; j < 2; j++) {
                int nt = 2 * kt + j;
                float p0 = __expf(sacc[nt][0] - 40.f);
                float p1 = __expf(sacc[nt][1] - 40.f);
                float p2 = __expf(sacc[nt][2] - 40.f);
                float p3 = __expf(sacc[nt][3] - 40.f);
                ls0 += p0 + p1;
                ls1 += p2 + p3;
                splitpair(p0, p1, ah[2 * j],     al[2 * j]);
                splitpair(p2, p3, ah[2 * j + 1], al[2 * j + 1]);
            }
#pragma unroll
            for (int nt = 0; nt < 16; nt++) {
                uint2 ghv = *(const uint2*)&su[off + 8192 + (kt * 16 + nt) * 64 + lane * 2];
                uint2 glv = *(const uint2*)&su[off + 12288 + (kt * 16 + nt) * 64 + lane * 2];
                mma16(yacc[nt], ah, (const uint32_t*)&ghv);
                mma16(yacc[nt], al, (const uint32_t*)&ghv);
                mma16(yacc[nt], ah, (const uint32_t*)&glv);
            }
        }
        __syncthreads();
    }

    // ---- normalize + convert yacc -> y A-frags (registers) ----
    ls0 += __shfl_xor_sync(0xffffffffu, ls0, 1);
    ls0 += __shfl_xor_sync(0xffffffffu, ls0, 2);
    ls1 += __shfl_xor_sync(0xffffffffu, ls1, 1);
    ls1 += __shfl_xor_sync(0xffffffffu, ls1, 2);
    float inv0 = 1.f / ls0, inv1 = 1.f / ls1;

    uint32_t yh[8][4], yl[8][4];
#pragma unroll
    for (int kt = 0; kt < 8; kt++) {
        splitpair(yacc[2 * kt][0] * inv0, yacc[2 * kt][1] * inv0, yh[kt][0], yl[kt][0]);
        splitpair(yacc[2 * kt][2] * inv1, yacc[2 * kt][3] * inv1, yh[kt][1], yl[kt][1]);
        splitpair(yacc[2 * kt + 1][0] * inv0, yacc[2 * kt + 1][1] * inv0, yh[kt][2], yl[kt][2]);
        splitpair(yacc[2 * kt + 1][2] * inv1, yacc[2 * kt + 1][3] * inv1, yh[kt][3], yl[kt][3]);
    }

    // ---- stream jt1 W under jt0 compute; BN consts for jt0 ----
    {
#pragma unroll
        for (int i = 0; i < 8; i++) {
            int e4 = (tid + i * 256) * 4;
            cp_async16(sb + (J1W + e4) * 4,        &d_wpH[OW_BASE + 8192 + e4]);
            cp_async16(sb + (J1W + 8192 + e4) * 4, &d_wpL[OW_BASE + 8192 + e4]);
        }
        CP_COMMIT();    // group B (jt1 W)
    }
    if (tid < 128) {
        float bninv = gamma[tid] * rsqrtf(bvar[tid] + 1e-5f);
        sf[FB_INV + tid] = bninv;
        sf[FB_ADD + tid] = (Wb[tid] - bmean[tid]) * bninv + beta[tid];
    }
    CP_WAIT(1);         // jt0 W done; jt1 W may be in flight
    __syncthreads();

    // ---- fused output conv: two halves of 128 oc each ----
    for (int jt = 0; jt < 2; jt++) {
        int oc0 = jt * 128;
        int wbh = (jt == 0) ? 0 : J1W;
        int wbl = (jt == 0) ? 8192 : (J1W + 8192);

        float oacc[16][4];
#pragma unroll
        for (int nt = 0; nt < 16; nt++)
#pragma unroll
            for (int q = 0; q < 4; q++) oacc[nt][q] = 0.f;

#pragma unroll
        for (int kt = 0; kt < 8; kt++) {
#pragma unroll
            for (int nt = 0; nt < 16; nt++) {
                uint2 bhv = *(const uint2*)&su[wbh + (kt * 16 + nt) * 64 + lane * 2];
                uint2 blv = *(const uint2*)&su[wbl + (kt * 16 + nt) * 64 + lane * 2];
                mma16(oacc[nt], yh[kt], (const uint32_t*)&bhv);
                mma16(oacc[nt], yl[kt], (const uint32_t*)&bhv);
                mma16(oacc[nt], yh[kt], (const uint32_t*)&blv);
            }
        }
        __syncthreads();   // W region (jt0) dead before stage overwrites

        // ---- BN, stage [pixel 128][oc 128] pitch 130 (scalar) ----
#pragma unroll
        for (int nt = 0; nt < 16; nt++) {
            int col = nt * 8 + 2 * t4;
            float i0 = sf[FB_INV + col], i1 = sf[FB_INV + col + 1];
            float a0 = sf[FB_ADD + col], a1 = sf[FB_ADD + col + 1];
            int ra = w * 16 + gr, rb = ra + 8;
            sf[ra * 130 + col]     = oacc[nt][0] * i0 + a0;
            sf[ra * 130 + col + 1] = oacc[nt][1] * i1 + a1;
            sf[rb * 130 + col]     = oacc[nt][2] * i0 + a0;
            sf[rb * 130 + col + 1] = oacc[nt][3] * i1 + a1;
        }
        __syncthreads();

        // ---- transpose write + residual ----
        const float* xr = x + ((size_t)b * CC + oc0) * NPIX + rt * 128;
        float* outp = out + ((size_t)b * CC + oc0) * NPIX + rt * 128;
#pragma unroll
        for (int i = 0; i < 16; i++) {
            int e = tid + i * 256;
            int oc = e >> 5, pq = (e & 31) * 4;
            float4 xv = *(const float4*)&xr[(size_t)oc * NPIX + pq];
            float4 v = make_float4(sf[(pq + 0) * 130 + oc] + xv.x,
                                   sf[(pq + 1) * 130 + oc] + xv.y,
                                   sf[(pq + 2) * 130 + oc] + xv.z,
                                   sf[(pq + 3) * 130 + oc] + xv.w);
            *(float4*)&outp[(size_t)oc * NPIX + pq] = v;
        }

        if (jt == 0) {
            CP_WAIT(0);     // jt1 W landed
            __syncthreads();
            if (tid < 128) {
                int oc = 128 + tid;
                float bninv = gamma[oc] * rsqrtf(bvar[oc] + 1e-5f);
                sf[FB_INV + tid] = bninv;
                sf[FB_ADD + tid] = (Wb[oc] - bmean[oc]) * bninv + beta[oc];
            }
            __syncthreads();
        }
    }
}

// =====================================================================
extern "C" void kernel_launch(void* const* d_in, const int* in_sizes, int n_in,
                              void* d_out, int out_size)
{
    (void)in_sizes; (void)n_in; (void)out_size;
    const float* x    = (const float*)d_in[0];
    const float* g_w  = (const float*)d_in[1];
    const float* g_b  = (const float*)d_in[2];
    const float* th_w = (const float*)d_in[3];
    const float* th_b = (const float*)d_in[4];
    const float* ph_w = (const float*)d_in[5];
    const float* ph_b = (const float*)d_in[6];
    const float* W_w  = (const float*)d_in[7];
    const float* W_b  = (const float*)d_in[8];
    const float* bg   = (const float*)d_in[9];
    const float* bbta = (const float*)d_in[10];
    const float* bm   = (const float*)d_in[11];
    const float* bv   = (const float*)d_in[12];
    float* out = (float*)d_out;

    static int configured = 0;
    if (!configured) {
        cudaFuncSetAttribute(proj_mma_kernel,
            cudaFuncAttributeMaxDynamicSharedMemorySize, PJ_U32 * 4);
        cudaFuncSetAttribute(attn_fused_kernel,
            cudaFuncAttributeMaxDynamicSharedMemorySize, AT_U32 * 4);
        configured = 1;
    }

    prep_kernel<<<dim3(32, 9), 256>>>(x, g_w, th_w, ph_w, W_w);

    proj_mma_kernel<<<dim3(32, 3, 8), 256, PJ_U32 * 4>>>(g_b, th_b, ph_b);

    attn_fused_kernel<<<dim3(32, 8), 256, AT_U32 * 4>>>(
        x, W_b, bg, bbta, bm, bv, out);
}

// round 16
// speedup vs baseline: 2.7917x; 1.0126x over previous
#include <cuda_runtime.h>
#include <math.h>
#include <stdint.h>

#define BB   8
#define CC   256
#define ICn  128
#define NPIX 4096
#define NPm  1024

// ---------- bf16 helpers ----------
__device__ __forceinline__ uint32_t packbf(float e0, float e1) {
    uint32_t r; asm("cvt.rn.bf16x2.f32 %0, %1, %2;" : "=r"(r) : "f"(e1), "f"(e0)); return r;
}
__device__ __forceinline__ void splitpair(float v0, float v1, uint32_t &hp, uint32_t &lp) {
    hp = packbf(v0, v1);
    float h0 = __uint_as_float(hp << 16);
    float h1 = __uint_as_float(hp & 0xffff0000u);
    lp = packbf(v0 - h0, v1 - h1);
}

// mma.sync m16n8k16 bf16: C += A*B
__device__ __forceinline__ void mma16(float* c, const uint32_t* a, const uint32_t* b) {
    asm volatile("mma.sync.aligned.m16n8k16.row.col.f32.bf16.bf16.f32 "
        "{%0,%1,%2,%3}, {%4,%5,%6,%7}, {%8,%9}, {%0,%1,%2,%3};"
        : "+f"(c[0]), "+f"(c[1]), "+f"(c[2]), "+f"(c[3])
        : "r"(a[0]), "r"(a[1]), "r"(a[2]), "r"(a[3]), "r"(b[0]), "r"(b[1]));
}

// ---------- cp.async helpers ----------
__device__ __forceinline__ uint32_t smem_u32addr(const void* p) {
    uint32_t a;
    asm("{ .reg .u64 t; cvta.to.shared.u64 t, %1; cvt.u32.u64 %0, t; }" : "=r"(a) : "l"(p));
    return a;
}
__device__ __forceinline__ void cp_async16(uint32_t dst, const void* src) {
    asm volatile("cp.async.cg.shared.global [%0], [%1], 16;" :: "r"(dst), "l"(src));
}
#define CP_COMMIT() asm volatile("cp.async.commit_group;" ::: "memory")
#define CP_WAIT(n)  asm volatile("cp.async.wait_group %0;" :: "n"(n) : "memory")

// ---------- scratch: everything in frag format (hi/lo bf16x2) ----------
__device__ uint32_t d_xH [BB * 32 * 16384];      // x A-frags [b][pt][ch4][ww8 s4][128]
__device__ uint32_t d_xL [BB * 32 * 16384];
__device__ uint32_t d_wpH[3 * 16384 + 2 * 8192]; // proj W B-frags; out W at 49152
__device__ uint32_t d_wpL[3 * 16384 + 2 * 8192];
__device__ uint32_t d_thH[BB * 32 * 8192];       // theta A-frags [b][rt][ww][s][128]
__device__ uint32_t d_thL[BB * 32 * 8192];
__device__ uint32_t d_phH[BB * 16 * 4096];       // phi B-frags [b][ch][s 8][nt 8][64]
__device__ uint32_t d_phL[BB * 16 * 4096];
__device__ uint32_t d_gH [BB * 16 * 4096];       // g B-frags [b][ch][kt 4][nt 16][64]
__device__ uint32_t d_gL [BB * 16 * 4096];

#define OW_BASE 49152

// =====================================================================
// Kernel 0: merged prep (unchanged, round-15 passing)
// =====================================================================
__global__ void __launch_bounds__(256) prep_kernel(
    const float* __restrict__ x,
    const float* __restrict__ g_w, const float* __restrict__ th_w,
    const float* __restrict__ ph_w, const float* __restrict__ W_w)
{
    __shared__ float sx[64 * 128];
    int tid = threadIdx.x;

    if (blockIdx.y == 8) {
        int jt = blockIdx.x;
        if (jt >= 5) return;
        if (jt < 3) {
            const float* wsel = (jt == 0) ? th_w : (jt == 1) ? ph_w : g_w;
#pragma unroll
            for (int i = 0; i < 64; i++) {
                int e = tid + i * 256;
                int j = e >> 7, kp = e & 127, k0 = 2 * kp;
                float2 v = *(const float2*)&wsel[j * CC + k0];
                uint32_t h, l;
                splitpair(v.x, v.y, h, l);
                int ch = k0 >> 6, kl = k0 & 63;
                int s = kl >> 4, rg = (kl >> 3) & 1, ta = (kl >> 1) & 3;
                int nt = j >> 3, n8 = j & 7;
                int idx = jt * 16384 + ch * 4096 + (s * 16 + nt) * 64 + (n8 * 4 + ta) * 2 + rg;
                d_wpH[idx] = h;
                d_wpL[idx] = l;
            }
        } else {
            int oc0 = (jt - 3) * 128;
#pragma unroll
            for (int i = 0; i < 32; i++) {
                int e = tid + i * 256;
                int oc = e >> 6, kp = e & 63, k0 = 2 * kp;
                float2 v = *(const float2*)&W_w[(oc0 + oc) * ICn + k0];
                uint32_t h, l;
                splitpair(v.x, v.y, h, l);
                int kt = k0 >> 4, rg = (k0 >> 3) & 1, ta = (k0 >> 1) & 3;
                int nt = oc >> 3, n8 = oc & 7;
                int idx = OW_BASE + (jt - 3) * 8192 + (kt * 16 + nt) * 64 + (n8 * 4 + ta) * 2 + rg;
                d_wpH[idx] = h;
                d_wpL[idx] = l;
            }
        }
        return;
    }

    int pt = blockIdx.x, b = blockIdx.y;
    size_t base = (size_t)(b * 32 + pt) * 16384;

    for (int ch = 0; ch < 4; ch++) {
#pragma unroll
        for (int i = 0; i < 8; i++) {
            int e = tid + i * 256;
            int kc = e >> 5, p4 = (e & 31) * 4;
            *(float4*)&sx[kc * 128 + p4] =
                *(const float4*)&x[((size_t)b * CC + ch * 64 + kc) * NPIX + pt * 128 + p4];
        }
        __syncthreads();
#pragma unroll
        for (int i = 0; i < 16; i++) {
            int e = tid + i * 256;
            int blk = e >> 7, off = e & 127;
            int ww = blk >> 2, s = blk & 3;
            int gg = off >> 4, ta = (off >> 2) & 3, rg = (off >> 1) & 1, hi8 = off & 1;
            int p = ww * 16 + hi8 * 8 + gg;
            int kl = s * 16 + rg * 8 + ta * 2;
            uint32_t h, l;
            splitpair(sx[kl * 128 + p], sx[(kl + 1) * 128 + p], h, l);
            d_xH[base + ch * 4096 + e] = h;
            d_xL[base + ch * 4096 + e] = l;
        }
        __syncthreads();
    }
}

// =====================================================================
// Kernel 1: projection mma + fused 2x2 maxpool (unchanged, round-15)
// =====================================================================
#define PJ_BUF 16384
#define PJ_BIAS 32768
#define PJ_U32 32896

__global__ void __launch_bounds__(256) proj_mma_kernel(
    const float* __restrict__ g_b, const float* __restrict__ th_b,
    const float* __restrict__ ph_b)
{
    extern __shared__ uint32_t su[];
    float* sf = (float*)su;
    uint32_t sb = smem_u32addr(su);

    int pt = blockIdx.x, jt = blockIdx.y, b = blockIdx.z;
    const float* bsel = (jt == 0) ? th_b : (jt == 1) ? ph_b : g_b;

    int tid = threadIdx.x;
    int w = tid >> 5, lane = tid & 31;
    int gr = lane >> 2, t4 = lane & 3;
    int wM = w >> 1, wN = w & 1;

    if (tid < 128) sf[PJ_BIAS + tid] = bsel[tid];

    size_t xbase = (size_t)(b * 32 + pt) * 16384;
    int wbase = jt * 16384;

    {
#pragma unroll
        for (int i = 0; i < 4; i++) {
            int e4 = (tid + i * 256) * 4;
            cp_async16(sb + (e4) * 4,          &d_xH[xbase + e4]);
            cp_async16(sb + (4096 + e4) * 4,   &d_xL[xbase + e4]);
            cp_async16(sb + (8192 + e4) * 4,   &d_wpH[wbase + e4]);
            cp_async16(sb + (12288 + e4) * 4,  &d_wpL[wbase + e4]);
        }
        CP_COMMIT();
    }

    float acc[2][8][4];
#pragma unroll
    for (int mt = 0; mt < 2; mt++)
#pragma unroll
        for (int nt = 0; nt < 8; nt++)
#pragma unroll
            for (int q = 0; q < 4; q++) acc[mt][nt][q] = 0.f;

    for (int ch = 0; ch < 4; ch++) {
        int off = (ch & 1) * PJ_BUF;

        if (ch + 1 < 4) {
            int noff = ((ch + 1) & 1) * PJ_BUF;
            size_t xo = xbase + (ch + 1) * 4096;
            int wo = wbase + (ch + 1) * 4096;
#pragma unroll
            for (int i = 0; i < 4; i++) {
                int e4 = (tid + i * 256) * 4;
                cp_async16(sb + (noff + e4) * 4,          &d_xH[xo + e4]);
                cp_async16(sb + (noff + 4096 + e4) * 4,   &d_xL[xo + e4]);
                cp_async16(sb + (noff + 8192 + e4) * 4,   &d_wpH[wo + e4]);
                cp_async16(sb + (noff + 12288 + e4) * 4,  &d_wpL[wo + e4]);
            }
            CP_COMMIT();
            CP_WAIT(1);
        } else {
            CP_WAIT(0);
        }
        __syncthreads();

#pragma unroll
        for (int s = 0; s < 4; s++) {
            uint4 ahv[2], alv[2];
#pragma unroll
            for (int mt = 0; mt < 2; mt++) {
                int ww = wM * 2 + mt;
                ahv[mt] = *(const uint4*)&su[off + (ww * 4 + s) * 128 + lane * 4];
                alv[mt] = *(const uint4*)&su[off + 4096 + (ww * 4 + s) * 128 + lane * 4];
            }
#pragma unroll
            for (int nt = 0; nt < 8; nt++) {
                int ntg = wN * 8 + nt;
                uint2 bhv = *(const uint2*)&su[off + 8192 + (s * 16 + ntg) * 64 + lane * 2];
                uint2 blv = *(const uint2*)&su[off + 12288 + (s * 16 + ntg) * 64 + lane * 2];
#pragma unroll
                for (int mt = 0; mt < 2; mt++) {
                    mma16(acc[mt][nt], (const uint32_t*)&ahv[mt], (const uint32_t*)&bhv);
                    mma16(acc[mt][nt], (const uint32_t*)&alv[mt], (const uint32_t*)&bhv);
                    mma16(acc[mt][nt], (const uint32_t*)&ahv[mt], (const uint32_t*)&blv);
                }
            }
        }
        __syncthreads();
    }

#pragma unroll
    for (int mt = 0; mt < 2; mt++)
#pragma unroll
    for (int nt = 0; nt < 8; nt++) {
        int col = wN * 64 + nt * 8 + 2 * t4;
        float b0 = sf[PJ_BIAS + col], b1 = sf[PJ_BIAS + col + 1];
        int ra = (wM * 2 + mt) * 16 + gr, rb = ra + 8;
        sf[ra * 132 + col]     = acc[mt][nt][0] + b0;
        sf[ra * 132 + col + 1] = acc[mt][nt][1] + b1;
        sf[rb * 132 + col]     = acc[mt][nt][2] + b0;
        sf[rb * 132 + col + 1] = acc[mt][nt][3] + b1;
    }
    __syncthreads();

    if (jt == 0) {
        size_t base = (size_t)(b * 32 + pt) * 8192;
#pragma unroll
        for (int i = 0; i < 32; i++) {
            int e = tid + i * 256;
            int blk = e >> 7, off = e & 127;
            int ww = blk >> 3, s = blk & 7;
            int gg = off >> 4, ta = (off >> 2) & 3, rg = (off >> 1) & 1, hi8 = off & 1;
            int p = ww * 16 + hi8 * 8 + gg;
            int ic = s * 16 + rg * 8 + ta * 2;
            uint32_t h, l;
            splitpair(sf[p * 132 + ic], sf[p * 132 + ic + 1], h, l);
            d_thH[base + e] = h;
            d_thL[base + e] = l;
        }
    } else if (jt == 1) {
        int ch = pt >> 1, nthi = (pt & 1) * 4;
        size_t base = (size_t)(b * 16 + ch) * 4096;
#pragma unroll
        for (int i = 0; i < 8; i++) {
            int e = tid + i * 256;
            int s = e >> 8, r = e & 255;
            int ntl = r >> 6, woff = r & 63;
            int n8 = woff >> 3, ta = (woff >> 1) & 3, rg = woff & 1;
            int mc = ntl * 8 + n8;
            int ic = s * 16 + rg * 8 + ta * 2;
            int r0 = 2 * mc, r1 = 2 * mc + 1, r2 = 64 + 2 * mc, r3 = 65 + 2 * mc;
            float v0 = fmaxf(fmaxf(sf[r0 * 132 + ic],     sf[r1 * 132 + ic]),
                             fmaxf(sf[r2 * 132 + ic],     sf[r3 * 132 + ic]));
            float v1 = fmaxf(fmaxf(sf[r0 * 132 + ic + 1], sf[r1 * 132 + ic + 1]),
                             fmaxf(sf[r2 * 132 + ic + 1], sf[r3 * 132 + ic + 1]));
            uint32_t h, l;
            splitpair(v0, v1, h, l);
            size_t idx = base + ((size_t)s * 8 + nthi + ntl) * 64 + woff;
            d_phH[idx] = h;
            d_phL[idx] = l;
        }
    } else {
        int ch = pt >> 1, kthi = (pt & 1) * 2;
        size_t base = (size_t)(b * 16 + ch) * 4096;
#pragma unroll
        for (int i = 0; i < 8; i++) {
            int e = tid + i * 256;
            int ktl = e >> 10, r = e & 1023;
            int nt = r >> 6, woff = r & 63;
            int n8 = woff >> 3, ta = (woff >> 1) & 3, rg = woff & 1;
            int m16 = rg * 8 + ta * 2;
            int mc = ktl * 16 + m16;
            int ic = nt * 8 + n8;
            int ra = 2 * mc, rb = 2 * mc + 1, rc = 64 + 2 * mc, rd = 65 + 2 * mc;
            float v0 = fmaxf(fmaxf(sf[ra * 132 + ic], sf[rb * 132 + ic]),
                             fmaxf(sf[rc * 132 + ic], sf[rd * 132 + ic]));
            ra += 2; rb += 2; rc += 2; rd += 2;
            float v1 = fmaxf(fmaxf(sf[ra * 132 + ic], sf[rb * 132 + ic]),
                             fmaxf(sf[rc * 132 + ic], sf[rd * 132 + ic]));
            uint32_t h, l;
            splitpair(v0, v1, h, l);
            size_t idx = base + ((size_t)(kthi + ktl) * 16 + nt) * 64 + woff;
            d_gH[idx] = h;
            d_gL[idx] = l;
        }
    }
}

// =====================================================================
// Kernel 2: single-wave fused attention + output conv. 256 rows/CTA,
// 8 warps x 32 rows (mt=0,1), grid (16,8) = 128 CTAs.
// Theta in smem; phi double-buffered; g single-buffered (early issue).
// smem u32 (57344 = 224KB):
//   TH_H[0,16384) TH_L[16384,32768)
//   PB0[32768,40960) PB1[40960,49152)  (each: phi hi 4096 + lo 4096)
//   GB [49152,57344)                    (g hi 4096 + lo 4096)
// epilogue overlays: stage f32 [0,33280) pitch 130 x 256 rows
//   BN inv[33280,33408) addc[33408,33536); W hi[40960,49152) lo[49152,57344)
// =====================================================================
#define TH_H 0
#define TH_L 16384
#define PB0  32768
#define PB1  40960
#define GB   49152
#define AT2_U32 57344
#define FB2_INV 33280
#define FB2_ADD 33408
#define WRG  40960

__global__ void __launch_bounds__(256, 1) attn_fused_kernel(
    const float* __restrict__ x,
    const float* __restrict__ Wb,    const float* __restrict__ gamma,
    const float* __restrict__ beta,  const float* __restrict__ bmean,
    const float* __restrict__ bvar,  float* __restrict__ out)
{
    extern __shared__ uint32_t su[];
    float* sf = (float*)su;
    uint32_t sb = smem_u32addr(su);
    int tid = threadIdx.x;
    int w = tid >> 5, lane = tid & 31;
    int gr = lane >> 2, t4 = lane & 3;
    int rt = blockIdx.x, b = blockIdx.y;

    // ---- prologue: theta (2 tiles) + phi0 -> group A; g0 -> group B ----
    {
        size_t tb = (size_t)(b * 32 + rt * 2) * 8192;
#pragma unroll
        for (int i = 0; i < 16; i++) {
            int e4 = (tid + i * 256) * 4;
            cp_async16(sb + (TH_H + e4) * 4, &d_thH[tb + e4]);
            cp_async16(sb + (TH_L + e4) * 4, &d_thL[tb + e4]);
        }
        size_t base = (size_t)(b * 16) * 4096;
#pragma unroll
        for (int i = 0; i < 4; i++) {
            int e4 = (tid + i * 256) * 4;
            cp_async16(sb + (PB0 + e4) * 4,        &d_phH[base + e4]);
            cp_async16(sb + (PB0 + 4096 + e4) * 4, &d_phL[base + e4]);
        }
        CP_COMMIT();
#pragma unroll
        for (int i = 0; i < 4; i++) {
            int e4 = (tid + i * 256) * 4;
            cp_async16(sb + (GB + e4) * 4,        &d_gH[base + e4]);
            cp_async16(sb + (GB + 4096 + e4) * 4, &d_gL[base + e4]);
        }
        CP_COMMIT();
    }

    float yacc[2][16][4];
#pragma unroll
    for (int mt = 0; mt < 2; mt++)
#pragma unroll
        for (int nt = 0; nt < 16; nt++)
#pragma unroll
            for (int q = 0; q < 4; q++) yacc[mt][nt][q] = 0.f;
    float ls00 = 0.f, ls01 = 0.f, ls10 = 0.f, ls11 = 0.f;

    for (int ch = 0; ch < 16; ch++) {
        int pb = (ch & 1) ? PB1 : PB0;
        CP_WAIT(1);            // phi(ch) [+theta at ch 0] landed; g(ch) may be in flight
        __syncthreads();

        // ---- S-pass: 32 rows (mt 0,1), theta from smem, B reused x2 ----
        float sacc[2][8][4];
#pragma unroll
        for (int mt = 0; mt < 2; mt++)
#pragma unroll
            for (int nt = 0; nt < 8; nt++)
#pragma unroll
                for (int q = 0; q < 4; q++) sacc[mt][nt][q] = 0.f;

#pragma unroll
        for (int s = 0; s < 8; s++) {
            uint4 ah0 = *(const uint4*)&su[TH_H + ((w * 2 + 0) * 8 + s) * 128 + lane * 4];
            uint4 al0 = *(const uint4*)&su[TH_L + ((w * 2 + 0) * 8 + s) * 128 + lane * 4];
            uint4 ah1 = *(const uint4*)&su[TH_H + ((w * 2 + 1) * 8 + s) * 128 + lane * 4];
            uint4 al1 = *(const uint4*)&su[TH_L + ((w * 2 + 1) * 8 + s) * 128 + lane * 4];
#pragma unroll
            for (int nt = 0; nt < 8; nt++) {
                uint2 bhv = *(const uint2*)&su[pb + (s * 8 + nt) * 64 + lane * 2];
                uint2 blv = *(const uint2*)&su[pb + 4096 + (s * 8 + nt) * 64 + lane * 2];
                mma16(sacc[0][nt], (const uint32_t*)&ah0, (const uint32_t*)&bhv);
                mma16(sacc[0][nt], (const uint32_t*)&al0, (const uint32_t*)&bhv);
                mma16(sacc[0][nt], (const uint32_t*)&ah0, (const uint32_t*)&blv);
                mma16(sacc[1][nt], (const uint32_t*)&ah1, (const uint32_t*)&bhv);
                mma16(sacc[1][nt], (const uint32_t*)&al1, (const uint32_t*)&bhv);
                mma16(sacc[1][nt], (const uint32_t*)&ah1, (const uint32_t*)&blv);
            }
        }

        CP_WAIT(0);            // g(ch) landed
        __syncthreads();       // g visible; all warps past S (phi buffers free)

        if (ch + 1 < 16) {     // issue phi(ch+1) into the other buffer
            int npb = ((ch + 1) & 1) ? PB1 : PB0;
            size_t base = (size_t)(b * 16 + ch + 1) * 4096;
#pragma unroll
            for (int i = 0; i < 4; i++) {
                int e4 = (tid + i * 256) * 4;
                cp_async16(sb + (npb + e4) * 4,        &d_phH[base + e4]);
                cp_async16(sb + (npb + 4096 + e4) * 4, &d_phL[base + e4]);
            }
            CP_COMMIT();
        } else {               // ch 15: prefetch epilogue W jt0 hi into [WRG) (= PB1, free)
#pragma unroll
            for (int i = 0; i < 8; i++) {
                int e4 = (tid + i * 256) * 4;
                cp_async16(sb + (WRG + e4) * 4, &d_wpH[OW_BASE + e4]);
            }
            CP_COMMIT();
        }

        // ---- per kt: exp (both mt) then Y-mma with B reused x2 ----
#pragma unroll
        for (int kt = 0; kt < 4; kt++) {
            uint32_t ah[2][4], al[2][4];
#pragma unroll
            for (int mt = 0; mt < 2; mt++) {
#pragma unroll
                for (int j = 0; j < 2; j++) {
                    int nt = 2 * kt + j;
                    float p0 = __expf(sacc[mt][nt][0] - 40.f);
                    float p1 = __expf(sacc[mt][nt][1] - 40.f);
                    float p2 = __expf(sacc[mt][nt][2] - 40.f);
                    float p3 = __expf(sacc[mt][nt][3] - 40.f);
                    if (mt == 0) { ls00 += p0 + p1; ls01 += p2 + p3; }
                    else         { ls10 += p0 + p1; ls11 += p2 + p3; }
                    splitpair(p0, p1, ah[mt][2 * j],     al[mt][2 * j]);
                    splitpair(p2, p3, ah[mt][2 * j + 1], al[mt][2 * j + 1]);
                }
            }
#pragma unroll
            for (int nt = 0; nt < 16; nt++) {
                uint2 ghv = *(const uint2*)&su[GB + (kt * 16 + nt) * 64 + lane * 2];
                uint2 glv = *(const uint2*)&su[GB + 4096 + (kt * 16 + nt) * 64 + lane * 2];
                mma16(yacc[0][nt], ah[0], (const uint32_t*)&ghv);
                mma16(yacc[0][nt], al[0], (const uint32_t*)&ghv);
                mma16(yacc[0][nt], ah[0], (const uint32_t*)&glv);
                mma16(yacc[1][nt], ah[1], (const uint32_t*)&ghv);
                mma16(yacc[1][nt], al[1], (const uint32_t*)&ghv);
                mma16(yacc[1][nt], ah[1], (const uint32_t*)&glv);
            }
        }
        __syncthreads();       // all warps done reading GB

        if (ch + 1 < 16) {     // issue g(ch+1) into GB
            size_t base = (size_t)(b * 16 + ch + 1) * 4096;
#pragma unroll
            for (int i = 0; i < 4; i++) {
                int e4 = (tid + i * 256) * 4;
                cp_async16(sb + (GB + e4) * 4,        &d_gH[base + e4]);
                cp_async16(sb + (GB + 4096 + e4) * 4, &d_gL[base + e4]);
            }
            CP_COMMIT();
        } else {               // ch 15: W jt0 lo into [GB) (now free)
#pragma unroll
            for (int i = 0; i < 8; i++) {
                int e4 = (tid + i * 256) * 4;
                cp_async16(sb + (GB + e4) * 4, &d_wpL[OW_BASE + e4]);
            }
            CP_COMMIT();
        }
    }

    // ---- normalize; convert yacc -> y A-frags (yacc released) ----
    ls00 += __shfl_xor_sync(0xffffffffu, ls00, 1);
    ls00 += __shfl_xor_sync(0xffffffffu, ls00, 2);
    ls01 += __shfl_xor_sync(0xffffffffu, ls01, 1);
    ls01 += __shfl_xor_sync(0xffffffffu, ls01, 2);
    ls10 += __shfl_xor_sync(0xffffffffu, ls10, 1);
    ls10 += __shfl_xor_sync(0xffffffffu, ls10, 2);
    ls11 += __shfl_xor_sync(0xffffffffu, ls11, 1);
    ls11 += __shfl_xor_sync(0xffffffffu, ls11, 2);
    float inv00 = 1.f / ls00, inv01 = 1.f / ls01;
    float inv10 = 1.f / ls10, inv11 = 1.f / ls11;

    uint32_t yh[2][8][4], yl[2][8][4];
#pragma unroll
    for (int mt = 0; mt < 2; mt++) {
        float i0 = (mt == 0) ? inv00 : inv10;
        float i1 = (mt == 0) ? inv01 : inv11;
#pragma unroll
        for (int kt = 0; kt < 8; kt++) {
            splitpair(yacc[mt][2 * kt][0] * i0, yacc[mt][2 * kt][1] * i0, yh[mt][kt][0], yl[mt][kt][0]);
            splitpair(yacc[mt][2 * kt][2] * i1, yacc[mt][2 * kt][3] * i1, yh[mt][kt][1], yl[mt][kt][1]);
            splitpair(yacc[mt][2 * kt + 1][0] * i0, yacc[mt][2 * kt + 1][1] * i0, yh[mt][kt][2], yl[mt][kt][2]);
            splitpair(yacc[mt][2 * kt + 1][2] * i1, yacc[mt][2 * kt + 1][3] * i1, yh[mt][kt][3], yl[mt][kt][3]);
        }
    }

    // ---- W jt0 landed; BN consts jt0 ----
    CP_WAIT(0);
    __syncthreads();
    if (tid < 128) {
        float bninv = gamma[tid] * rsqrtf(bvar[tid] + 1e-5f);
        sf[FB2_INV + tid] = bninv;
        sf[FB2_ADD + tid] = (Wb[tid] - bmean[tid]) * bninv + beta[tid];
    }
    __syncthreads();

    // ---- fused output conv: two halves of 128 oc ----
    for (int jt = 0; jt < 2; jt++) {
        int oc0 = jt * 128;

#pragma unroll
        for (int mt = 0; mt < 2; mt++) {
            float oacc[16][4];
#pragma unroll
            for (int nt = 0; nt < 16; nt++)
#pragma unroll
                for (int q = 0; q < 4; q++) oacc[nt][q] = 0.f;

#pragma unroll
            for (int kt = 0; kt < 8; kt++) {
#pragma unroll
                for (int nt = 0; nt < 16; nt++) {
                    uint2 bhv = *(const uint2*)&su[WRG + (kt * 16 + nt) * 64 + lane * 2];
                    uint2 blv = *(const uint2*)&su[GB + (kt * 16 + nt) * 64 + lane * 2];
                    mma16(oacc[nt], yh[mt][kt], (const uint32_t*)&bhv);
                    mma16(oacc[nt], yl[mt][kt], (const uint32_t*)&bhv);
                    mma16(oacc[nt], yh[mt][kt], (const uint32_t*)&blv);
                }
            }

            // BN + stage rows w*32 + mt*16 + {gr, gr+8}
#pragma unroll
            for (int nt = 0; nt < 16; nt++) {
                int col = nt * 8 + 2 * t4;
                float i0 = sf[FB2_INV + col], i1 = sf[FB2_INV + col + 1];
                float a0 = sf[FB2_ADD + col], a1 = sf[FB2_ADD + col + 1];
                int ra = w * 32 + mt * 16 + gr, rb = ra + 8;
                sf[ra * 130 + col]     = oacc[nt][0] * i0 + a0;
                sf[ra * 130 + col + 1] = oacc[nt][1] * i1 + a1;
                sf[rb * 130 + col]     = oacc[nt][2] * i0 + a0;
                sf[rb * 130 + col + 1] = oacc[nt][3] * i1 + a1;
            }
        }
        __syncthreads();       // stage complete; W reads done

        if (jt == 0) {         // stream jt1 W under the write-out
#pragma unroll
            for (int i = 0; i < 8; i++) {
                int e4 = (tid + i * 256) * 4;
                cp_async16(sb + (WRG + e4) * 4, &d_wpH[OW_BASE + 8192 + e4]);
                cp_async16(sb + (GB + e4) * 4,  &d_wpL[OW_BASE + 8192 + e4]);
            }
            CP_COMMIT();
        }

        // ---- transpose write + residual: 256 pixels x 128 oc ----
        const float* xr = x + ((size_t)b * CC + oc0) * NPIX + rt * 256;
        float* outp = out + ((size_t)b * CC + oc0) * NPIX + rt * 256;
#pragma unroll
        for (int i = 0; i < 32; i++) {
            int e = tid + i * 256;
            int oc = e >> 6, pq = (e & 63) * 4;
            float4 xv = *(const float4*)&xr[(size_t)oc * NPIX + pq];
            float4 v = make_float4(sf[(pq + 0) * 130 + oc] + xv.x,
                                   sf[(pq + 1) * 130 + oc] + xv.y,
                                   sf[(pq + 2) * 130 + oc] + xv.z,
                                   sf[(pq + 3) * 130 + oc] + xv.w);
            *(float4*)&outp[(size_t)oc * NPIX + pq] = v;
        }

        if (jt == 0) {
            CP_WAIT(0);        // jt1 W landed
            __syncthreads();   // write-out reads of stage done; W visible
            if (tid < 128) {
                int oc = 128 + tid;
                float bninv = gamma[oc] * rsqrtf(bvar[oc] + 1e-5f);
                sf[FB2_INV + tid] = bninv;
                sf[FB2_ADD + tid] = (Wb[oc] - bmean[oc]) * bninv + beta[oc];
            }
            __syncthreads();
        }
    }
}

// =====================================================================
extern "C" void kernel_launch(void* const* d_in, const int* in_sizes, int n_in,
                              void* d_out, int out_size)
{
    (void)in_sizes; (void)n_in; (void)out_size;
    const float* x    = (const float*)d_in[0];
    const float* g_w  = (const float*)d_in[1];
    const float* g_b  = (const float*)d_in[2];
    const float* th_w = (const float*)d_in[3];
    const float* th_b = (const float*)d_in[4];
    const float* ph_w = (const float*)d_in[5];
    const float* ph_b = (const float*)d_in[6];
    const float* W_w  = (const float*)d_in[7];
    const float* W_b  = (const float*)d_in[8];
    const float* bg   = (const float*)d_in[9];
    const float* bbta = (const float*)d_in[10];
    const float* bm   = (const float*)d_in[11];
    const float* bv   = (const float*)d_in[12];
    float* out = (float*)d_out;

    static int configured = 0;
    if (!configured) {
        cudaFuncSetAttribute(proj_mma_kernel,
            cudaFuncAttributeMaxDynamicSharedMemorySize, PJ_U32 * 4);
        cudaFuncSetAttribute(attn_fused_kernel,
            cudaFuncAttributeMaxDynamicSharedMemorySize, AT2_U32 * 4);
        configured = 1;
    }

    prep_kernel<<<dim3(32, 9), 256>>>(x, g_w, th_w, ph_w, W_w);

    proj_mma_kernel<<<dim3(32, 3, 8), 256, PJ_U32 * 4>>>(g_b, th_b, ph_b);

    attn_fused_kernel<<<dim3(16, 8), 256, AT2_U32 * 4>>>(
        x, W_b, bg, bbta, bm, bv, out);
}